// round 1
// baseline (speedup 1.0000x reference)
#include <cuda_runtime.h>
#include <math.h>

#define B_  4
#define N_  576
#define T_  3
#define C_  768
#define H_  12
#define P_  9
#define DH_ 64
#define HP_ 24
#define SCALE_ 0.125f   // 64^-0.5

// ---------------- scratch (device globals; no allocations allowed) ----------
__device__ float g_k[B_ * N_ * T_ * C_];        // x @ Wk   (B,N,T,C)
__device__ float g_v[B_ * N_ * T_ * C_];        // x @ Wv
__device__ float g_q[B_ * N_ * C_];             // query @ Wq
__device__ float g_off[B_ * N_ * H_ * P_ * 2];  // query @ Woff + boff
__device__ float g_attn[B_ * N_ * C_];          // attention output (b,n,h*64+d)

// ---------------- simple tiled SGEMM: C = A@B (+bias) -----------------------
// A: M x K, row r at A + r*lda (K contiguous). B: K x N row-major. M%64==0,
// K%16==0, N%4==0 assumed (holds for 768/216). N bounds-checked.
__global__ __launch_bounds__(256) void sgemm_kernel(
    const float* __restrict__ A, int lda,
    const float* __restrict__ Bm,
    const float* __restrict__ bias,
    float* __restrict__ C,
    int M, int N, int K)
{
    __shared__ float As[16][64];
    __shared__ float Bs[16][68];

    int tid = threadIdx.x;
    int tx = tid & 15, ty = tid >> 4;
    int row0 = blockIdx.y * 64, col0 = blockIdx.x * 64;

    float acc[4][4];
#pragma unroll
    for (int i = 0; i < 4; i++)
#pragma unroll
        for (int j = 0; j < 4; j++) acc[i][j] = 0.f;

    int am = tid >> 2;               // 0..63
    int ak = (tid & 3) * 4;          // 0,4,8,12
    int bk = tid >> 4;               // 0..15
    int bn = (tid & 15) * 4;         // 0..60

    for (int k0 = 0; k0 < K; k0 += 16) {
        // A tile (64 x 16) -> As[k][m]
        {
            const float* src = A + (long)(row0 + am) * lda + k0 + ak;
            float4 v = *(const float4*)src;
            As[ak + 0][am] = v.x;
            As[ak + 1][am] = v.y;
            As[ak + 2][am] = v.z;
            As[ak + 3][am] = v.w;
        }
        // B tile (16 x 64) -> Bs[k][n]
        {
            int gn = col0 + bn;
            float4 v = make_float4(0.f, 0.f, 0.f, 0.f);
            if (gn < N) v = *(const float4*)(Bm + (long)(k0 + bk) * N + gn);
            Bs[bk][bn + 0] = v.x;
            Bs[bk][bn + 1] = v.y;
            Bs[bk][bn + 2] = v.z;
            Bs[bk][bn + 3] = v.w;
        }
        __syncthreads();
#pragma unroll
        for (int kk = 0; kk < 16; kk++) {
            float a[4], b[4];
#pragma unroll
            for (int i = 0; i < 4; i++) a[i] = As[kk][ty * 4 + i];
#pragma unroll
            for (int j = 0; j < 4; j++) b[j] = Bs[kk][tx * 4 + j];
#pragma unroll
            for (int i = 0; i < 4; i++)
#pragma unroll
                for (int j = 0; j < 4; j++) acc[i][j] += a[i] * b[j];
        }
        __syncthreads();
    }

#pragma unroll
    for (int i = 0; i < 4; i++) {
        int gr = row0 + ty * 4 + i;
#pragma unroll
        for (int j = 0; j < 4; j++) {
            int gc = col0 + tx * 4 + j;
            if (gc < N) {
                float v = acc[i][j];
                if (bias) v += bias[gc];
                C[(long)gr * N + gc] = v;
            }
        }
    }
}

// Dual-output SGEMM: C0 = A@B0, C1 = A@B1 (shares A tile load). N%64==0.
__global__ __launch_bounds__(256) void sgemm2_kernel(
    const float* __restrict__ A, int lda,
    const float* __restrict__ B0, const float* __restrict__ B1,
    float* __restrict__ C0, float* __restrict__ C1,
    int M, int N, int K)
{
    __shared__ float As[16][64];
    __shared__ float Bs0[16][68];
    __shared__ float Bs1[16][68];

    int tid = threadIdx.x;
    int tx = tid & 15, ty = tid >> 4;
    int row0 = blockIdx.y * 64, col0 = blockIdx.x * 64;

    float acc0[4][4], acc1[4][4];
#pragma unroll
    for (int i = 0; i < 4; i++)
#pragma unroll
        for (int j = 0; j < 4; j++) { acc0[i][j] = 0.f; acc1[i][j] = 0.f; }

    int am = tid >> 2;
    int ak = (tid & 3) * 4;
    int bk = tid >> 4;
    int bn = (tid & 15) * 4;

    for (int k0 = 0; k0 < K; k0 += 16) {
        {
            const float* src = A + (long)(row0 + am) * lda + k0 + ak;
            float4 v = *(const float4*)src;
            As[ak + 0][am] = v.x;
            As[ak + 1][am] = v.y;
            As[ak + 2][am] = v.z;
            As[ak + 3][am] = v.w;
        }
        {
            int gn = col0 + bn;
            float4 v0 = *(const float4*)(B0 + (long)(k0 + bk) * N + gn);
            float4 v1 = *(const float4*)(B1 + (long)(k0 + bk) * N + gn);
            Bs0[bk][bn + 0] = v0.x; Bs0[bk][bn + 1] = v0.y;
            Bs0[bk][bn + 2] = v0.z; Bs0[bk][bn + 3] = v0.w;
            Bs1[bk][bn + 0] = v1.x; Bs1[bk][bn + 1] = v1.y;
            Bs1[bk][bn + 2] = v1.z; Bs1[bk][bn + 3] = v1.w;
        }
        __syncthreads();
#pragma unroll
        for (int kk = 0; kk < 16; kk++) {
            float a[4], b0[4], b1[4];
#pragma unroll
            for (int i = 0; i < 4; i++) a[i] = As[kk][ty * 4 + i];
#pragma unroll
            for (int j = 0; j < 4; j++) {
                b0[j] = Bs0[kk][tx * 4 + j];
                b1[j] = Bs1[kk][tx * 4 + j];
            }
#pragma unroll
            for (int i = 0; i < 4; i++)
#pragma unroll
                for (int j = 0; j < 4; j++) {
                    acc0[i][j] += a[i] * b0[j];
                    acc1[i][j] += a[i] * b1[j];
                }
        }
        __syncthreads();
    }

#pragma unroll
    for (int i = 0; i < 4; i++) {
        int gr = row0 + ty * 4 + i;
#pragma unroll
        for (int j = 0; j < 4; j++) {
            int gc = col0 + tx * 4 + j;
            C0[(long)gr * N + gc] = acc0[i][j];
            C1[(long)gr * N + gc] = acc1[i][j];
        }
    }
}

// ---------------- deformable attention core ---------------------------------
// grid = B*N blocks, 384 threads = 12 warps, warp h handles head h.
// Each lane owns d = lane and d = lane+32.
__global__ __launch_bounds__(384) void attn_kernel(
    const float* __restrict__ mask,
    const float* __restrict__ suppress_p)
{
    int bn = blockIdx.x;              // b*N + n
    int b  = bn / N_;
    int n  = bn % N_;
    int h    = threadIdx.x >> 5;
    int lane = threadIdx.x & 31;

    float suppress = *suppress_p;
    float mk  = mask[bn];
    float sw  = 1.f - suppress * mk;          // softmax temperature factor
    float moff = suppress * mk * 0.1f;        // offset suppression

    int gh = n / HP_, gw = n % HP_;
    float refx = gw * (2.f / 23.f) - 1.f;
    float refy = gh * (2.f / 23.f) - 1.f;

    const float* qrow = g_q + (long)bn * C_ + h * DH_;
    float q0 = qrow[lane];
    float q1 = qrow[lane + 32];

    const float* offrow = g_off + (long)bn * (H_ * P_ * 2) + h * (P_ * 2);

    float o0 = 0.f, o1 = 0.f;

#pragma unroll
    for (int t = 0; t < T_; t++) {
        float logit[P_], sv0[P_], sv1[P_];
#pragma unroll
        for (int p = 0; p < P_; p++) {
            float ox = offrow[p * 2 + 0] - moff;
            float oy = offrow[p * 2 + 1] - moff;
            float xs = (refx + ox + 1.f) * 0.5f * 23.f;
            float ys = (refy + oy + 1.f) * 0.5f * 23.f;
            float x0f = floorf(xs), y0f = floorf(ys);
            int   x0 = (int)x0f,  y0 = (int)y0f;
            float wx1 = xs - x0f, wy1 = ys - y0f;
            float wx0 = 1.f - wx1, wy0 = 1.f - wy1;

            float k0 = 0.f, k1 = 0.f, va = 0.f, vb = 0.f;
#pragma unroll
            for (int c = 0; c < 4; c++) {
                int dx = c & 1, dy = c >> 1;
                int ix = x0 + dx, iy = y0 + dy;
                if (ix >= 0 && ix < HP_ && iy >= 0 && iy < HP_) {
                    float w = (dx ? wx1 : wx0) * (dy ? wy1 : wy0);
                    int pix = iy * HP_ + ix;
                    long base = ((long)(b * N_ + pix) * T_ + t) * C_ + h * DH_;
                    k0 += w * g_k[base + lane];
                    k1 += w * g_k[base + lane + 32];
                    va += w * g_v[base + lane];
                    vb += w * g_v[base + lane + 32];
                }
            }
            // warp all-reduce of q . sk
            float dot = q0 * k0 + q1 * k1;
#pragma unroll
            for (int s = 16; s > 0; s >>= 1)
                dot += __shfl_xor_sync(0xffffffffu, dot, s);
            logit[p] = dot * SCALE_ * sw;
            sv0[p] = va;
            sv1[p] = vb;
        }
        // softmax over P (identical in every lane)
        float m = logit[0];
#pragma unroll
        for (int p = 1; p < P_; p++) m = fmaxf(m, logit[p]);
        float s = 0.f;
        float e[P_];
#pragma unroll
        for (int p = 0; p < P_; p++) { e[p] = __expf(logit[p] - m); s += e[p]; }
        float inv = 1.f / s;
#pragma unroll
        for (int p = 0; p < P_; p++) {
            float a = e[p] * inv;
            o0 += a * sv0[p];
            o1 += a * sv1[p];
        }
    }

    float invT = 1.f / (float)T_;
    float* orow = g_attn + (long)bn * C_ + h * DH_;
    orow[lane]      = o0 * invT;
    orow[lane + 32] = o1 * invT;
}

// ---------------- launch ----------------------------------------------------
extern "C" void kernel_launch(void* const* d_in, const int* in_sizes, int n_in,
                              void* d_out, int out_size)
{
    const float* x       = (const float*)d_in[0];  // (B,N,T,C)
    const float* mask    = (const float*)d_in[1];  // (B,N)
    const float* Wq      = (const float*)d_in[2];  // (C,C)
    const float* Wk      = (const float*)d_in[3];
    const float* Wv      = (const float*)d_in[4];
    const float* Woff    = (const float*)d_in[5];  // (C, 216)
    const float* boff    = (const float*)d_in[6];  // (216,)
    const float* Wproj   = (const float*)d_in[7];  // (C,C)
    const float* bproj   = (const float*)d_in[8];  // (C,)
    const float* suppr   = (const float*)d_in[9];  // scalar
    float* out = (float*)d_out;                    // (B,N,C)

    float *kbuf, *vbuf, *qbuf, *offbuf, *attnbuf;
    cudaGetSymbolAddress((void**)&kbuf,    g_k);
    cudaGetSymbolAddress((void**)&vbuf,    g_v);
    cudaGetSymbolAddress((void**)&qbuf,    g_q);
    cudaGetSymbolAddress((void**)&offbuf,  g_off);
    cudaGetSymbolAddress((void**)&attnbuf, g_attn);

    const int M_kv = B_ * N_ * T_;   // 6912
    const int M_q  = B_ * N_;        // 2304
    const int NOFF = H_ * P_ * 2;    // 216

    // 1) K and V projections (fused; reads x once)
    {
        dim3 grid(C_ / 64, M_kv / 64);
        sgemm2_kernel<<<grid, 256>>>(x, C_, Wk, Wv, kbuf, vbuf, M_kv, C_, C_);
    }
    // 2) Q projection from query = x[:,:,1,:]  (row stride T*C, offset C)
    {
        dim3 grid(C_ / 64, M_q / 64);
        sgemm_kernel<<<grid, 256>>>(x + C_, T_ * C_, Wq, nullptr, qbuf,
                                    M_q, C_, C_);
    }
    // 3) Offsets = query @ Woff + boff
    {
        dim3 grid((NOFF + 63) / 64, M_q / 64);
        sgemm_kernel<<<grid, 256>>>(x + C_, T_ * C_, Woff, boff, offbuf,
                                    M_q, NOFF, C_);
    }
    // 4) Deformable attention (sampling + softmax + weighted sum)
    attn_kernel<<<B_ * N_, 384>>>(mask, suppr);

    // 5) Output projection
    {
        dim3 grid(C_ / 64, M_q / 64);
        sgemm_kernel<<<grid, 256>>>(attnbuf, C_, Wproj, bproj, out,
                                    M_q, C_, C_);
    }
}

// round 2
// speedup vs baseline: 1.1316x; 1.1316x over previous
#include <cuda_runtime.h>
#include <math.h>

#define B_  4
#define N_  576
#define T_  3
#define C_  768
#define H_  12
#define P_  9
#define DH_ 64
#define HP_ 24
#define SCALE_ 0.125f   // 64^-0.5
#define BN_ (B_ * N_)
#define CKV_ (2 * C_)   // 1536

// ---------------- scratch (device globals; no allocations allowed) ----------
__device__ float g_kv[B_ * N_ * T_ * CKV_];         // [token][k(768)|v(768)]
__device__ float g_q[B_ * N_ * C_];                 // query @ Wq
__device__ float g_off[B_ * N_ * H_ * P_ * 2];      // query @ Woff + boff
__device__ float g_attn[T_ * B_ * N_ * C_];         // per-t attention output
__device__ float g_Wkv[C_ * CKV_];                  // [Wk | Wv]

// ---------------- pack [Wk|Wv] -----------------------------------------------
__global__ void pack_wkv_kernel(const float* __restrict__ Wk,
                                const float* __restrict__ Wv)
{
    int idx = blockIdx.x * blockDim.x + threadIdx.x;   // over C_*C_
    if (idx >= C_ * C_) return;
    int k = idx / C_, j = idx % C_;
    g_Wkv[(long)k * CKV_ + j]      = Wk[idx];
    g_Wkv[(long)k * CKV_ + C_ + j] = Wv[idx];
}

// ---------------- packed f32x2 SGEMM: C = A@B (+bias) ------------------------
// Tile 64(M) x 128(N), 256 threads, microtile 4x8 (4 col-pairs).
// A duplicated in shared ({a,a} pairs), B in natural pairs.
// Requires M%64==0, N%128==0, K%16==0.
#define PITCH 132

__device__ __forceinline__ void fma2(unsigned long long& d,
                                     unsigned long long a,
                                     unsigned long long b)
{
    asm("fma.rn.f32x2 %0, %1, %2, %0;" : "+l"(d) : "l"(a), "l"(b));
}

__global__ __launch_bounds__(256, 2) void gemm_f32x2(
    const float* __restrict__ A, int lda,
    const float* __restrict__ Bm,
    const float* __restrict__ bias,
    float* __restrict__ C,
    int M, int N, int K)
{
    __shared__ float As[16 * PITCH];   // dup pairs: pair m at word 2m
    __shared__ float Bs[16 * PITCH];

    int tid = threadIdx.x;
    int tx = tid & 15, ty = tid >> 4;
    int row0 = blockIdx.y * 64, col0 = blockIdx.x * 128;

    unsigned long long acc[4][4];
#pragma unroll
    for (int i = 0; i < 4; i++)
#pragma unroll
        for (int j = 0; j < 4; j++) acc[i][j] = 0ULL;

    int am = tid >> 2;            // 0..63
    int ak = (tid & 3) * 4;       // 0,4,8,12
    int bk = tid >> 4;            // 0..15
    int bn = (tid & 15) * 8;      // 0..120

    for (int k0 = 0; k0 < K; k0 += 16) {
        // A tile 64x16 -> duplicated pairs As[k][2m]=As[k][2m+1]=a
        {
            float4 v = *(const float4*)(A + (long)(row0 + am) * lda + k0 + ak);
            float* p0 = As + (ak + 0) * PITCH + 2 * am;
            float* p1 = As + (ak + 1) * PITCH + 2 * am;
            float* p2 = As + (ak + 2) * PITCH + 2 * am;
            float* p3 = As + (ak + 3) * PITCH + 2 * am;
            p0[0] = v.x; p0[1] = v.x;
            p1[0] = v.y; p1[1] = v.y;
            p2[0] = v.z; p2[1] = v.z;
            p3[0] = v.w; p3[1] = v.w;
        }
        // B tile 16x128
        {
            const float* src = Bm + (long)(k0 + bk) * N + col0 + bn;
            float4 v0 = *(const float4*)(src);
            float4 v1 = *(const float4*)(src + 4);
            float* dst = Bs + bk * PITCH + bn;
            dst[0] = v0.x; dst[1] = v0.y; dst[2] = v0.z; dst[3] = v0.w;
            dst[4] = v1.x; dst[5] = v1.y; dst[6] = v1.z; dst[7] = v1.w;
        }
        __syncthreads();
#pragma unroll
        for (int kk = 0; kk < 16; kk++) {
            const float* asr = As + kk * PITCH;
            const float* bsr = Bs + kk * PITCH;
            unsigned long long a2[4], b2[4];
#pragma unroll
            for (int i = 0; i < 4; i++)
                a2[i] = *(const unsigned long long*)(asr + (ty * 4 + i) * 2);
#pragma unroll
            for (int j = 0; j < 4; j++)
                b2[j] = *(const unsigned long long*)(bsr + (tx + j * 16) * 2);
#pragma unroll
            for (int i = 0; i < 4; i++)
#pragma unroll
                for (int j = 0; j < 4; j++)
                    fma2(acc[i][j], a2[i], b2[j]);
        }
        __syncthreads();
    }

#pragma unroll
    for (int i = 0; i < 4; i++) {
        int gr = row0 + ty * 4 + i;
#pragma unroll
        for (int j = 0; j < 4; j++) {
            int gc = col0 + (tx + j * 16) * 2;
            float2 f = *(float2*)&acc[i][j];
            if (bias) { f.x += bias[gc]; f.y += bias[gc + 1]; }
            *(float2*)(C + (long)gr * N + gc) = f;
        }
    }
}

// Variant: A tile = (A0 + A1 + A2) * (1/3)  (sums per-t attention outputs)
__global__ __launch_bounds__(256, 2) void gemm_f32x2_sum3(
    const float* __restrict__ A0, const float* __restrict__ A1,
    const float* __restrict__ A2, int lda,
    const float* __restrict__ Bm,
    const float* __restrict__ bias,
    float* __restrict__ C,
    int M, int N, int K)
{
    __shared__ float As[16 * PITCH];
    __shared__ float Bs[16 * PITCH];

    int tid = threadIdx.x;
    int tx = tid & 15, ty = tid >> 4;
    int row0 = blockIdx.y * 64, col0 = blockIdx.x * 128;

    unsigned long long acc[4][4];
#pragma unroll
    for (int i = 0; i < 4; i++)
#pragma unroll
        for (int j = 0; j < 4; j++) acc[i][j] = 0ULL;

    int am = tid >> 2;
    int ak = (tid & 3) * 4;
    int bk = tid >> 4;
    int bn = (tid & 15) * 8;
    const float third = 1.0f / 3.0f;

    for (int k0 = 0; k0 < K; k0 += 16) {
        {
            long off = (long)(row0 + am) * lda + k0 + ak;
            float4 v0 = *(const float4*)(A0 + off);
            float4 v1 = *(const float4*)(A1 + off);
            float4 v2 = *(const float4*)(A2 + off);
            float vx = (v0.x + v1.x + v2.x) * third;
            float vy = (v0.y + v1.y + v2.y) * third;
            float vz = (v0.z + v1.z + v2.z) * third;
            float vw = (v0.w + v1.w + v2.w) * third;
            float* p0 = As + (ak + 0) * PITCH + 2 * am;
            float* p1 = As + (ak + 1) * PITCH + 2 * am;
            float* p2 = As + (ak + 2) * PITCH + 2 * am;
            float* p3 = As + (ak + 3) * PITCH + 2 * am;
            p0[0] = vx; p0[1] = vx;
            p1[0] = vy; p1[1] = vy;
            p2[0] = vz; p2[1] = vz;
            p3[0] = vw; p3[1] = vw;
        }
        {
            const float* src = Bm + (long)(k0 + bk) * N + col0 + bn;
            float4 v0 = *(const float4*)(src);
            float4 v1 = *(const float4*)(src + 4);
            float* dst = Bs + bk * PITCH + bn;
            dst[0] = v0.x; dst[1] = v0.y; dst[2] = v0.z; dst[3] = v0.w;
            dst[4] = v1.x; dst[5] = v1.y; dst[6] = v1.z; dst[7] = v1.w;
        }
        __syncthreads();
#pragma unroll
        for (int kk = 0; kk < 16; kk++) {
            const float* asr = As + kk * PITCH;
            const float* bsr = Bs + kk * PITCH;
            unsigned long long a2[4], b2[4];
#pragma unroll
            for (int i = 0; i < 4; i++)
                a2[i] = *(const unsigned long long*)(asr + (ty * 4 + i) * 2);
#pragma unroll
            for (int j = 0; j < 4; j++)
                b2[j] = *(const unsigned long long*)(bsr + (tx + j * 16) * 2);
#pragma unroll
            for (int i = 0; i < 4; i++)
#pragma unroll
                for (int j = 0; j < 4; j++)
                    fma2(acc[i][j], a2[i], b2[j]);
        }
        __syncthreads();
    }

#pragma unroll
    for (int i = 0; i < 4; i++) {
        int gr = row0 + ty * 4 + i;
#pragma unroll
        for (int j = 0; j < 4; j++) {
            int gc = col0 + (tx + j * 16) * 2;
            float2 f = *(float2*)&acc[i][j];
            if (bias) { f.x += bias[gc]; f.y += bias[gc + 1]; }
            *(float2*)(C + (long)gr * N + gc) = f;
        }
    }
}

// ---------------- small bounds-checked SGEMM (offset projection, N=216) -----
__global__ __launch_bounds__(256) void sgemm_kernel(
    const float* __restrict__ A, int lda,
    const float* __restrict__ Bm,
    const float* __restrict__ bias,
    float* __restrict__ C,
    int M, int N, int K)
{
    __shared__ float As[16][64];
    __shared__ float Bs[16][68];

    int tid = threadIdx.x;
    int tx = tid & 15, ty = tid >> 4;
    int row0 = blockIdx.y * 64, col0 = blockIdx.x * 64;

    float acc[4][4];
#pragma unroll
    for (int i = 0; i < 4; i++)
#pragma unroll
        for (int j = 0; j < 4; j++) acc[i][j] = 0.f;

    int am = tid >> 2;
    int ak = (tid & 3) * 4;
    int bk = tid >> 4;
    int bn = (tid & 15) * 4;

    for (int k0 = 0; k0 < K; k0 += 16) {
        {
            const float* src = A + (long)(row0 + am) * lda + k0 + ak;
            float4 v = *(const float4*)src;
            As[ak + 0][am] = v.x;
            As[ak + 1][am] = v.y;
            As[ak + 2][am] = v.z;
            As[ak + 3][am] = v.w;
        }
        {
            int gn = col0 + bn;
            float4 v = make_float4(0.f, 0.f, 0.f, 0.f);
            if (gn < N) v = *(const float4*)(Bm + (long)(k0 + bk) * N + gn);
            Bs[bk][bn + 0] = v.x;
            Bs[bk][bn + 1] = v.y;
            Bs[bk][bn + 2] = v.z;
            Bs[bk][bn + 3] = v.w;
        }
        __syncthreads();
#pragma unroll
        for (int kk = 0; kk < 16; kk++) {
            float a[4], b[4];
#pragma unroll
            for (int i = 0; i < 4; i++) a[i] = As[kk][ty * 4 + i];
#pragma unroll
            for (int j = 0; j < 4; j++) b[j] = Bs[kk][tx * 4 + j];
#pragma unroll
            for (int i = 0; i < 4; i++)
#pragma unroll
                for (int j = 0; j < 4; j++) acc[i][j] += a[i] * b[j];
        }
        __syncthreads();
    }

#pragma unroll
    for (int i = 0; i < 4; i++) {
        int gr = row0 + ty * 4 + i;
#pragma unroll
        for (int j = 0; j < 4; j++) {
            int gc = col0 + tx * 4 + j;
            if (gc < N) {
                float v = acc[i][j];
                if (bias) v += bias[gc];
                C[(long)gr * N + gc] = v;
            }
        }
    }
}

// ---------------- deformable attention core ---------------------------------
// grid = (B*N, T), 384 threads = 12 warps, warp h handles head h.
// Each lane owns d = lane and d = lane+32. Writes per-t partial output.
__global__ __launch_bounds__(384, 2) void attn_kernel(
    const float* __restrict__ mask,
    const float* __restrict__ suppress_p)
{
    int bn = blockIdx.x;              // b*N + n
    int t  = blockIdx.y;
    int b  = bn / N_;
    int n  = bn % N_;
    int h    = threadIdx.x >> 5;
    int lane = threadIdx.x & 31;

    float suppress = *suppress_p;
    float mk  = mask[bn];
    float sw  = 1.f - suppress * mk;          // softmax temperature factor
    float moff = suppress * mk * 0.1f;        // offset suppression

    int gh = n / HP_, gw = n % HP_;
    float refx = gw * (2.f / 23.f) - 1.f;
    float refy = gh * (2.f / 23.f) - 1.f;

    const float* qrow = g_q + (long)bn * C_ + h * DH_;
    float q0 = qrow[lane];
    float q1 = qrow[lane + 32];

    const float* offrow = g_off + (long)bn * (H_ * P_ * 2) + h * (P_ * 2);

    float logit[P_], sv0[P_], sv1[P_];
#pragma unroll
    for (int p = 0; p < P_; p++) {
        float ox = offrow[p * 2 + 0] - moff;
        float oy = offrow[p * 2 + 1] - moff;
        float xs = (refx + ox + 1.f) * 0.5f * 23.f;
        float ys = (refy + oy + 1.f) * 0.5f * 23.f;
        float x0f = floorf(xs), y0f = floorf(ys);
        int   x0 = (int)x0f,  y0 = (int)y0f;
        float wx1 = xs - x0f, wy1 = ys - y0f;
        float wx0 = 1.f - wx1, wy0 = 1.f - wy1;

        float k0 = 0.f, k1 = 0.f, va = 0.f, vb = 0.f;
#pragma unroll
        for (int c = 0; c < 4; c++) {
            int dx = c & 1, dy = c >> 1;
            int ix = x0 + dx, iy = y0 + dy;
            if (ix >= 0 && ix < HP_ && iy >= 0 && iy < HP_) {
                float w = (dx ? wx1 : wx0) * (dy ? wy1 : wy0);
                int pix = iy * HP_ + ix;
                long base = ((long)((b * N_ + pix) * T_ + t)) * CKV_ + h * DH_;
                k0 = fmaf(w, g_kv[base + lane],            k0);
                k1 = fmaf(w, g_kv[base + lane + 32],       k1);
                va = fmaf(w, g_kv[base + C_ + lane],       va);
                vb = fmaf(w, g_kv[base + C_ + lane + 32],  vb);
            }
        }
        // warp all-reduce of q . sk
        float dot = q0 * k0 + q1 * k1;
#pragma unroll
        for (int s = 16; s > 0; s >>= 1)
            dot += __shfl_xor_sync(0xffffffffu, dot, s);
        logit[p] = dot * SCALE_ * sw;
        sv0[p] = va;
        sv1[p] = vb;
    }
    // softmax over P (identical in every lane)
    float m = logit[0];
#pragma unroll
    for (int p = 1; p < P_; p++) m = fmaxf(m, logit[p]);
    float s = 0.f;
    float e[P_];
#pragma unroll
    for (int p = 0; p < P_; p++) { e[p] = __expf(logit[p] - m); s += e[p]; }
    float inv = 1.f / s;

    float o0 = 0.f, o1 = 0.f;
#pragma unroll
    for (int p = 0; p < P_; p++) {
        float a = e[p] * inv;
        o0 = fmaf(a, sv0[p], o0);
        o1 = fmaf(a, sv1[p], o1);
    }

    float* orow = g_attn + ((long)t * BN_ + bn) * C_ + h * DH_;
    orow[lane]      = o0;   // /T folded into projection A-load
    orow[lane + 32] = o1;
}

// ---------------- launch ----------------------------------------------------
extern "C" void kernel_launch(void* const* d_in, const int* in_sizes, int n_in,
                              void* d_out, int out_size)
{
    const float* x       = (const float*)d_in[0];  // (B,N,T,C)
    const float* mask    = (const float*)d_in[1];  // (B,N)
    const float* Wq      = (const float*)d_in[2];  // (C,C)
    const float* Wk      = (const float*)d_in[3];
    const float* Wv      = (const float*)d_in[4];
    const float* Woff    = (const float*)d_in[5];  // (C, 216)
    const float* boff    = (const float*)d_in[6];  // (216,)
    const float* Wproj   = (const float*)d_in[7];  // (C,C)
    const float* bproj   = (const float*)d_in[8];  // (C,)
    const float* suppr   = (const float*)d_in[9];  // scalar
    float* out = (float*)d_out;                    // (B,N,C)

    float *kvbuf, *qbuf, *offbuf, *attnbuf;
    cudaGetSymbolAddress((void**)&kvbuf,   g_kv);
    cudaGetSymbolAddress((void**)&qbuf,    g_q);
    cudaGetSymbolAddress((void**)&offbuf,  g_off);
    cudaGetSymbolAddress((void**)&attnbuf, g_attn);
    float* wkvbuf;
    cudaGetSymbolAddress((void**)&wkvbuf,  g_Wkv);

    const int M_kv = B_ * N_ * T_;   // 6912
    const int M_q  = B_ * N_;        // 2304
    const int NOFF = H_ * P_ * 2;    // 216

    // 0) pack [Wk|Wv]
    pack_wkv_kernel<<<(C_ * C_ + 255) / 256, 256>>>(Wk, Wv);

    // 1) KV projection: x(6912x768) @ Wkv(768x1536)
    {
        dim3 grid(CKV_ / 128, M_kv / 64);
        gemm_f32x2<<<grid, 256>>>(x, C_, wkvbuf, nullptr, kvbuf,
                                  M_kv, CKV_, C_);
    }
    // 2) Q projection from query = x[:,:,1,:]  (row stride T*C, offset C)
    {
        dim3 grid(C_ / 128, M_q / 64);
        gemm_f32x2<<<grid, 256>>>(x + C_, T_ * C_, Wq, nullptr, qbuf,
                                  M_q, C_, C_);
    }
    // 3) Offsets = query @ Woff + boff (small, bounds-checked kernel)
    {
        dim3 grid((NOFF + 63) / 64, M_q / 64);
        sgemm_kernel<<<grid, 256>>>(x + C_, T_ * C_, Woff, boff, offbuf,
                                    M_q, NOFF, C_);
    }
    // 4) Deformable attention (sampling + softmax + weighted sum), per-t
    {
        dim3 grid(B_ * N_, T_);
        attn_kernel<<<grid, 384>>>(mask, suppr);
    }
    // 5) Output projection with on-the-fly sum over t and /T
    {
        dim3 grid(C_ / 128, M_q / 64);
        gemm_f32x2_sum3<<<grid, 256>>>(attnbuf,
                                       attnbuf + (long)BN_ * C_,
                                       attnbuf + 2L * BN_ * C_,
                                       C_, Wproj, bproj, out,
                                       M_q, C_, C_);
    }
}

// round 4
// speedup vs baseline: 2.8169x; 2.4892x over previous
#include <cuda_runtime.h>
#include <cuda_bf16.h>
#include <cstdint>
#include <math.h>

#define B_  4
#define N_  576
#define T_  3
#define C_  768
#define H_  12
#define P_  9
#define DH_ 64
#define HP_ 24
#define SCALE_ 0.125f
#define BN_ (B_ * N_)
#define CKV_ (2 * C_)       // 1536
#define MKV_ (BN_ * T_)     // 6912
#define NOFF_ (H_ * P_ * 2) // 216
#define NOFFP_ 256          // padded

// ---------------- scratch (device globals) -----------------------------------
__device__ __nv_bfloat16 g_xhi[MKV_ * C_];
__device__ __nv_bfloat16 g_xlo[MKV_ * C_];
__device__ __nv_bfloat16 g_wkvT_hi[CKV_ * C_];   // [n][k], n<768: Wk, else Wv
__device__ __nv_bfloat16 g_wkvT_lo[CKV_ * C_];
__device__ __nv_bfloat16 g_wqT_hi[C_ * C_];
__device__ __nv_bfloat16 g_wqT_lo[C_ * C_];
__device__ __nv_bfloat16 g_wprojT_hi[C_ * C_];
__device__ __nv_bfloat16 g_wprojT_lo[C_ * C_];
__device__ __nv_bfloat16 g_woffT_hi[NOFFP_ * C_];
__device__ __nv_bfloat16 g_woffT_lo[NOFFP_ * C_];
__device__ __nv_bfloat16 g_ahi[BN_ * C_];
__device__ __nv_bfloat16 g_alo[BN_ * C_];

__device__ float g_kv[MKV_ * CKV_];
__device__ float g_q[BN_ * C_];
__device__ float g_off[BN_ * NOFF_];
__device__ float g_attn[T_ * BN_ * C_];

// ---------------- PTX helpers ---------------------------------------------------
__device__ __forceinline__ uint32_t smem_to_u32(const void* p) {
    uint32_t a;
    asm("{ .reg .u64 t; cvta.to.shared.u64 t, %1; cvt.u32.u64 %0, t; }"
        : "=r"(a) : "l"(p));
    return a;
}
__device__ __forceinline__ void cp16(uint32_t dst, const void* src) {
    asm volatile("cp.async.cg.shared.global [%0], [%1], 16;"
                 :: "r"(dst), "l"(src));
}
#define CP_COMMIT() asm volatile("cp.async.commit_group;" ::: "memory")
#define CP_WAIT0()  asm volatile("cp.async.wait_group 0;" ::: "memory")
#define CP_WAIT1()  asm volatile("cp.async.wait_group 1;" ::: "memory")

__device__ __forceinline__ void ldm4(uint32_t* r, uint32_t addr) {
    asm volatile("ldmatrix.sync.aligned.m8n8.x4.shared.b16 {%0,%1,%2,%3}, [%4];"
                 : "=r"(r[0]), "=r"(r[1]), "=r"(r[2]), "=r"(r[3]) : "r"(addr));
}
__device__ __forceinline__ void mma_bf16(float* c, const uint32_t* a,
                                         uint32_t b0, uint32_t b1) {
    asm volatile(
        "mma.sync.aligned.m16n8k16.row.col.f32.bf16.bf16.f32 "
        "{%0,%1,%2,%3}, {%4,%5,%6,%7}, {%8,%9}, {%0,%1,%2,%3};"
        : "+f"(c[0]), "+f"(c[1]), "+f"(c[2]), "+f"(c[3])
        : "r"(a[0]), "r"(a[1]), "r"(a[2]), "r"(a[3]), "r"(b0), "r"(b1));
}

// ---------------- split / transpose prep kernels --------------------------------
__device__ __forceinline__ void split_bf(float v, __nv_bfloat16& hi, __nv_bfloat16& lo) {
    hi = __float2bfloat16(v);
    lo = __float2bfloat16(v - __bfloat162float(hi));
}

__global__ void split_x_kernel(const float* __restrict__ x) {
    int idx = blockIdx.x * blockDim.x + threadIdx.x;
    if (idx >= MKV_ * C_ / 4) return;
    float4 v = ((const float4*)x)[idx];
    __nv_bfloat16 h0, l0, h1, l1, h2, l2, h3, l3;
    split_bf(v.x, h0, l0); split_bf(v.y, h1, l1);
    split_bf(v.z, h2, l2); split_bf(v.w, h3, l3);
    ((__nv_bfloat162*)g_xhi)[idx * 2]     = __nv_bfloat162(h0, h1);
    ((__nv_bfloat162*)g_xhi)[idx * 2 + 1] = __nv_bfloat162(h2, h3);
    ((__nv_bfloat162*)g_xlo)[idx * 2]     = __nv_bfloat162(l0, l1);
    ((__nv_bfloat162*)g_xlo)[idx * 2 + 1] = __nv_bfloat162(l2, l3);
}

// src: 768 x N row-major. dst[n][k] = src[k][n], bf16 split. Zero-fills n>=N.
__global__ void tpose_split_kernel(const float* __restrict__ src, int N,
                                   __nv_bfloat16* __restrict__ dhi,
                                   __nv_bfloat16* __restrict__ dlo, int dstRows) {
    __shared__ float tile[32][33];
    int n0 = blockIdx.x * 32, k0 = blockIdx.y * 32;
    int tx = threadIdx.x, ty = threadIdx.y;
#pragma unroll
    for (int j = 0; j < 4; j++) {
        int k = k0 + ty + j * 8, n = n0 + tx;
        tile[ty + j * 8][tx] = (n < N) ? src[(long)k * N + n] : 0.f;
    }
    __syncthreads();
#pragma unroll
    for (int j = 0; j < 4; j++) {
        int n = n0 + ty + j * 8, k = k0 + tx;
        if (n < dstRows) {
            __nv_bfloat16 hi, lo;
            split_bf(tile[tx][ty + j * 8], hi, lo);
            dhi[(long)n * C_ + k] = hi;
            dlo[(long)n * C_ + k] = lo;
        }
    }
}

__global__ void sum3_split_kernel() {
    int idx = blockIdx.x * blockDim.x + threadIdx.x;
    if (idx >= BN_ * C_ / 4) return;
    const float third = 1.0f / 3.0f;
    float4 a = ((const float4*)g_attn)[idx];
    float4 b = ((const float4*)(g_attn + (long)BN_ * C_))[idx];
    float4 c = ((const float4*)(g_attn + 2L * BN_ * C_))[idx];
    float s0 = (a.x + b.x + c.x) * third;
    float s1 = (a.y + b.y + c.y) * third;
    float s2 = (a.z + b.z + c.z) * third;
    float s3 = (a.w + b.w + c.w) * third;
    __nv_bfloat16 h0, l0, h1, l1, h2, l2, h3, l3;
    split_bf(s0, h0, l0); split_bf(s1, h1, l1);
    split_bf(s2, h2, l2); split_bf(s3, h3, l3);
    ((__nv_bfloat162*)g_ahi)[idx * 2]     = __nv_bfloat162(h0, h1);
    ((__nv_bfloat162*)g_ahi)[idx * 2 + 1] = __nv_bfloat162(h2, h3);
    ((__nv_bfloat162*)g_alo)[idx * 2]     = __nv_bfloat162(l0, l1);
    ((__nv_bfloat162*)g_alo)[idx * 2 + 1] = __nv_bfloat162(l2, l3);
}

// ---------------- mma.sync bf16x3 GEMM -------------------------------------------
// C[M,N] = (Ahi+Alo) @ (Bhi+Blo)^T  (3-term). Tile 128x128, K-chunk 64 (128B rows,
// SW128 XOR swizzle). cp.async double-buffered. 8 warps: 4(m) x 2(n), warp tile
// 32x64 via m16n8k16.
#define TILE_BYTES 16384              // 128 x 64 bf16
#define STAGE_BYTES (4 * TILE_BYTES)  // Ahi,Alo,Bhi,Blo
#define SMEM_TOTAL (2 * STAGE_BYTES)  // 131072

__global__ __launch_bounds__(256, 1)
void gemm_bf16x3(const __nv_bfloat16* __restrict__ Ahi,
                 const __nv_bfloat16* __restrict__ Alo, long lda,
                 const __nv_bfloat16* __restrict__ Bhi,
                 const __nv_bfloat16* __restrict__ Blo,
                 const float* __restrict__ bias,
                 float* __restrict__ C, int ldc, int Nstore, int K)
{
    extern __shared__ char smem[];
    uint32_t sb = smem_to_u32(smem);

    int tid = threadIdx.x;
    int wid = tid >> 5, lane = tid & 31;
    int warp_m = wid & 3;          // 4 m-warps * 32 rows
    int warp_n = wid >> 2;         // 2 n-warps * 64 cols
    int row0 = blockIdx.y * 128, col0 = blockIdx.x * 128;

    const int NKITER = K / 64;

    // loader index precompute (4 units per array per thread)
    int rr[4], cc[4], doff[4];
#pragma unroll
    for (int j = 0; j < 4; j++) {
        int u = tid + j * 256;
        int r = u >> 3, cu = u & 7;
        rr[j] = r; cc[j] = cu;
        doff[j] = ((r << 3) + (cu ^ (r & 7))) << 4;
    }

    const __nv_bfloat16* gp[4] = {Ahi, Alo, Bhi, Blo};
    long  st[4] = {lda, lda, (long)K, (long)K};
    int   rb[4] = {row0, row0, col0, col0};

    // issue stage 0
#pragma unroll
    for (int a = 0; a < 4; a++) {
        uint32_t sdst = sb + a * TILE_BYTES;
        const __nv_bfloat16* g = gp[a];
#pragma unroll
        for (int j = 0; j < 4; j++)
            cp16(sdst + doff[j], g + (long)(rb[a] + rr[j]) * st[a] + cc[j] * 8);
    }
    CP_COMMIT();

    float acc[2][8][4];
#pragma unroll
    for (int mf = 0; mf < 2; mf++)
#pragma unroll
        for (int nf = 0; nf < 8; nf++)
#pragma unroll
            for (int e = 0; e < 4; e++) acc[mf][nf][e] = 0.f;

    // A-frag ldmatrix address components (per lane)
    int a_r = warp_m * 32 + (lane & 7) + ((lane & 8) ? 8 : 0);
    int a_usel = (lane & 16) ? 1 : 0;
    // B-frag
    int b_rbase = warp_n * 64 + (lane & 7) + ((lane & 16) ? 8 : 0);
    int b_usel = (lane & 8) ? 1 : 0;

    for (int kc = 0; kc < NKITER; kc++) {
        if (kc + 1 < NKITER) {
            uint32_t sstage = sb + ((kc + 1) & 1) * STAGE_BYTES;
            int k0 = (kc + 1) * 64;
#pragma unroll
            for (int a = 0; a < 4; a++) {
                uint32_t sdst = sstage + a * TILE_BYTES;
                const __nv_bfloat16* g = gp[a];
#pragma unroll
                for (int j = 0; j < 4; j++)
                    cp16(sdst + doff[j],
                         g + (long)(rb[a] + rr[j]) * st[a] + k0 + cc[j] * 8);
            }
            CP_COMMIT();
            CP_WAIT1();
        } else {
            CP_WAIT0();
        }
        __syncthreads();

        uint32_t s = sb + (kc & 1) * STAGE_BYTES;
        uint32_t sAhi = s, sAlo = s + TILE_BYTES;
        uint32_t sBhi = s + 2 * TILE_BYTES, sBlo = s + 3 * TILE_BYTES;

#pragma unroll
        for (int ks = 0; ks < 4; ks++) {
            uint32_t ah[2][4], al[2][4];
#pragma unroll
            for (int mf = 0; mf < 2; mf++) {
                int r = a_r + mf * 16;
                int u = ks * 2 + a_usel;
                uint32_t off = (uint32_t)(((r << 3) + (u ^ (r & 7))) << 4);
                ldm4(ah[mf], sAhi + off);
                ldm4(al[mf], sAlo + off);
            }
            uint32_t bh[4][4], bl[4][4];
#pragma unroll
            for (int np = 0; np < 4; np++) {
                int r = b_rbase + np * 16;
                int u = ks * 2 + b_usel;
                uint32_t off = (uint32_t)(((r << 3) + (u ^ (r & 7))) << 4);
                ldm4(bh[np], sBhi + off);
                ldm4(bl[np], sBlo + off);
            }
#pragma unroll
            for (int mf = 0; mf < 2; mf++)
#pragma unroll
                for (int nf = 0; nf < 8; nf++) {
                    int np = nf >> 1;
                    int half = (nf & 1) * 2;
                    uint32_t bh0 = bh[np][half], bh1 = bh[np][half + 1];
                    uint32_t bl0 = bl[np][half], bl1 = bl[np][half + 1];
                    mma_bf16(acc[mf][nf], ah[mf], bh0, bh1);
                    mma_bf16(acc[mf][nf], ah[mf], bl0, bl1);
                    mma_bf16(acc[mf][nf], al[mf], bh0, bh1);
                }
        }
        __syncthreads();
    }

    // epilogue
#pragma unroll
    for (int mf = 0; mf < 2; mf++) {
        int m = row0 + warp_m * 32 + mf * 16 + (lane >> 2);
#pragma unroll
        for (int nf = 0; nf < 8; nf++) {
            int n = col0 + warp_n * 64 + nf * 8 + (lane & 3) * 2;
            if (n < Nstore) {
                float2 v0, v1;
                v0.x = acc[mf][nf][0]; v0.y = acc[mf][nf][1];
                v1.x = acc[mf][nf][2]; v1.y = acc[mf][nf][3];
                if (bias) {
                    float bx = bias[n], by = bias[n + 1];
                    v0.x += bx; v0.y += by;
                    v1.x += bx; v1.y += by;
                }
                *(float2*)(C + (long)m * ldc + n)       = v0;
                *(float2*)(C + (long)(m + 8) * ldc + n) = v1;
            }
        }
    }
}

// ---------------- deformable attention core --------------------------------------
__global__ __launch_bounds__(384, 2) void attn_kernel(
    const float* __restrict__ mask,
    const float* __restrict__ suppress_p)
{
    int bn = blockIdx.x;
    int t  = blockIdx.y;
    int b  = bn / N_;
    int n  = bn % N_;
    int h    = threadIdx.x >> 5;
    int lane = threadIdx.x & 31;

    float suppress = *suppress_p;
    float mk  = mask[bn];
    float sw  = 1.f - suppress * mk;
    float moff = suppress * mk * 0.1f;

    int gh = n / HP_, gw = n % HP_;
    float refx = gw * (2.f / 23.f) - 1.f;
    float refy = gh * (2.f / 23.f) - 1.f;

    const float* qrow = g_q + (long)bn * C_ + h * DH_;
    float q0 = qrow[lane];
    float q1 = qrow[lane + 32];

    const float* offrow = g_off + (long)bn * NOFF_ + h * (P_ * 2);

    float logit[P_], sv0[P_], sv1[P_];
#pragma unroll
    for (int p = 0; p < P_; p++) {
        float ox = offrow[p * 2 + 0] - moff;
        float oy = offrow[p * 2 + 1] - moff;
        float xs = (refx + ox + 1.f) * 0.5f * 23.f;
        float ys = (refy + oy + 1.f) * 0.5f * 23.f;
        float x0f = floorf(xs), y0f = floorf(ys);
        int   x0 = (int)x0f,  y0 = (int)y0f;
        float wx1 = xs - x0f, wy1 = ys - y0f;
        float wx0 = 1.f - wx1, wy0 = 1.f - wy1;

        float k0 = 0.f, k1 = 0.f, va = 0.f, vb = 0.f;
#pragma unroll
        for (int c = 0; c < 4; c++) {
            int dx = c & 1, dy = c >> 1;
            int ix = x0 + dx, iy = y0 + dy;
            if (ix >= 0 && ix < HP_ && iy >= 0 && iy < HP_) {
                float w = (dx ? wx1 : wx0) * (dy ? wy1 : wy0);
                int pix = iy * HP_ + ix;
                long base = ((long)((b * N_ + pix) * T_ + t)) * CKV_ + h * DH_;
                k0 = fmaf(w, g_kv[base + lane],           k0);
                k1 = fmaf(w, g_kv[base + lane + 32],      k1);
                va = fmaf(w, g_kv[base + C_ + lane],      va);
                vb = fmaf(w, g_kv[base + C_ + lane + 32], vb);
            }
        }
        float dot = q0 * k0 + q1 * k1;
#pragma unroll
        for (int s = 16; s > 0; s >>= 1)
            dot += __shfl_xor_sync(0xffffffffu, dot, s);
        logit[p] = dot * SCALE_ * sw;
        sv0[p] = va;
        sv1[p] = vb;
    }
    float m = logit[0];
#pragma unroll
    for (int p = 1; p < P_; p++) m = fmaxf(m, logit[p]);
    float s = 0.f;
    float e[P_];
#pragma unroll
    for (int p = 0; p < P_; p++) { e[p] = __expf(logit[p] - m); s += e[p]; }
    float inv = 1.f / s;

    float o0 = 0.f, o1 = 0.f;
#pragma unroll
    for (int p = 0; p < P_; p++) {
        float a = e[p] * inv;
        o0 = fmaf(a, sv0[p], o0);
        o1 = fmaf(a, sv1[p], o1);
    }

    float* orow = g_attn + ((long)t * BN_ + bn) * C_ + h * DH_;
    orow[lane]      = o0;
    orow[lane + 32] = o1;
}

// ---------------- launch ----------------------------------------------------------
extern "C" void kernel_launch(void* const* d_in, const int* in_sizes, int n_in,
                              void* d_out, int out_size)
{
    const float* x     = (const float*)d_in[0];
    const float* mask  = (const float*)d_in[1];
    const float* Wq    = (const float*)d_in[2];
    const float* Wk    = (const float*)d_in[3];
    const float* Wv    = (const float*)d_in[4];
    const float* Woff  = (const float*)d_in[5];
    const float* boff  = (const float*)d_in[6];
    const float* Wproj = (const float*)d_in[7];
    const float* bproj = (const float*)d_in[8];
    const float* suppr = (const float*)d_in[9];
    float* out = (float*)d_out;

    __nv_bfloat16 *xhi, *xlo, *wkvh, *wkvl, *wqh, *wql, *wph, *wpl, *wofh, *wofl, *ahi, *alo;
    float *kvbuf, *qbuf, *offbuf, *attnbuf;
    cudaGetSymbolAddress((void**)&xhi,  g_xhi);
    cudaGetSymbolAddress((void**)&xlo,  g_xlo);
    cudaGetSymbolAddress((void**)&wkvh, g_wkvT_hi);
    cudaGetSymbolAddress((void**)&wkvl, g_wkvT_lo);
    cudaGetSymbolAddress((void**)&wqh,  g_wqT_hi);
    cudaGetSymbolAddress((void**)&wql,  g_wqT_lo);
    cudaGetSymbolAddress((void**)&wph,  g_wprojT_hi);
    cudaGetSymbolAddress((void**)&wpl,  g_wprojT_lo);
    cudaGetSymbolAddress((void**)&wofh, g_woffT_hi);
    cudaGetSymbolAddress((void**)&wofl, g_woffT_lo);
    cudaGetSymbolAddress((void**)&ahi,  g_ahi);
    cudaGetSymbolAddress((void**)&alo,  g_alo);
    cudaGetSymbolAddress((void**)&kvbuf,   g_kv);
    cudaGetSymbolAddress((void**)&qbuf,    g_q);
    cudaGetSymbolAddress((void**)&offbuf,  g_off);
    cudaGetSymbolAddress((void**)&attnbuf, g_attn);

    cudaFuncSetAttribute(gemm_bf16x3,
                         cudaFuncAttributeMaxDynamicSharedMemorySize, SMEM_TOTAL);

    dim3 t32x8(32, 8);

    // prep: split x, transpose+split weights
    split_x_kernel<<<(MKV_ * C_ / 4 + 255) / 256, 256>>>(x);
    tpose_split_kernel<<<dim3(C_ / 32, C_ / 32), t32x8>>>(Wq, C_, wqh, wql, C_);
    tpose_split_kernel<<<dim3(C_ / 32, C_ / 32), t32x8>>>(Wk, C_, wkvh, wkvl, C_);
    tpose_split_kernel<<<dim3(C_ / 32, C_ / 32), t32x8>>>(
        Wv, C_, wkvh + (long)C_ * C_, wkvl + (long)C_ * C_, C_);
    tpose_split_kernel<<<dim3(C_ / 32, C_ / 32), t32x8>>>(Wproj, C_, wph, wpl, C_);
    tpose_split_kernel<<<dim3(NOFFP_ / 32, C_ / 32), t32x8>>>(Woff, NOFF_, wofh, wofl, NOFFP_);

    // 1) KV: x(6912x768) @ [Wk|Wv] -> g_kv (6912x1536)
    gemm_bf16x3<<<dim3(CKV_ / 128, MKV_ / 128), 256, SMEM_TOTAL>>>(
        xhi, xlo, C_, wkvh, wkvl, nullptr, kvbuf, CKV_, CKV_, C_);
    // 2) Q: query rows (stride T*C, offset C)
    gemm_bf16x3<<<dim3(C_ / 128, BN_ / 128), 256, SMEM_TOTAL>>>(
        xhi + C_, xlo + C_, (long)T_ * C_, wqh, wql, nullptr, qbuf, C_, C_, C_);
    // 3) offsets (+boff), N padded 256 -> store 216
    gemm_bf16x3<<<dim3(NOFFP_ / 128, BN_ / 128), 256, SMEM_TOTAL>>>(
        xhi + C_, xlo + C_, (long)T_ * C_, wofh, wofl, boff, offbuf, NOFF_, NOFF_, C_);
    // 4) attention
    {
        dim3 grid(BN_, T_);
        attn_kernel<<<grid, 384>>>(mask, suppr);
    }
    // 5) average over t, split, project (+bproj)
    sum3_split_kernel<<<(BN_ * C_ / 4 + 255) / 256, 256>>>();
    gemm_bf16x3<<<dim3(C_ / 128, BN_ / 128), 256, SMEM_TOTAL>>>(
        ahi, alo, C_, wph, wpl, bproj, out, C_, C_, C_);
}

// round 5
// speedup vs baseline: 2.9138x; 1.0344x over previous
#include <cuda_runtime.h>
#include <cuda_bf16.h>
#include <cstdint>
#include <math.h>

#define B_  4
#define N_  576
#define T_  3
#define C_  768
#define H_  12
#define P_  9
#define DH_ 64
#define HP_ 24
#define SCALE_ 0.125f
#define BN_ (B_ * N_)
#define CKV_ (2 * C_)       // 1536
#define MKV_ (BN_ * T_)     // 6912
#define NOFF_ (H_ * P_ * 2) // 216
#define NOFFP_ 256          // padded

// ---------------- scratch (device globals) -----------------------------------
__device__ __nv_bfloat16 g_xhi[MKV_ * C_];
__device__ __nv_bfloat16 g_xlo[MKV_ * C_];
__device__ __nv_bfloat16 g_wkvT_hi[CKV_ * C_];   // [n][k], n<768: Wk, else Wv
__device__ __nv_bfloat16 g_wkvT_lo[CKV_ * C_];
__device__ __nv_bfloat16 g_wqT_hi[C_ * C_];
__device__ __nv_bfloat16 g_wqT_lo[C_ * C_];
__device__ __nv_bfloat16 g_wprojT_hi[C_ * C_];
__device__ __nv_bfloat16 g_wprojT_lo[C_ * C_];
__device__ __nv_bfloat16 g_woffT_hi[NOFFP_ * C_];
__device__ __nv_bfloat16 g_woffT_lo[NOFFP_ * C_];
__device__ __nv_bfloat16 g_ahi[BN_ * C_];
__device__ __nv_bfloat16 g_alo[BN_ * C_];

__device__ float g_kv[MKV_ * CKV_];
__device__ float g_q[BN_ * C_];
__device__ float g_off[BN_ * NOFF_];
__device__ float g_attn[T_ * BN_ * C_];

// ---------------- PTX helpers ---------------------------------------------------
__device__ __forceinline__ uint32_t smem_to_u32(const void* p) {
    uint32_t a;
    asm("{ .reg .u64 t; cvta.to.shared.u64 t, %1; cvt.u32.u64 %0, t; }"
        : "=r"(a) : "l"(p));
    return a;
}
__device__ __forceinline__ void cp16(uint32_t dst, const void* src) {
    asm volatile("cp.async.cg.shared.global [%0], [%1], 16;"
                 :: "r"(dst), "l"(src));
}
#define CP_COMMIT() asm volatile("cp.async.commit_group;" ::: "memory")
#define CP_WAIT0()  asm volatile("cp.async.wait_group 0;" ::: "memory")
#define CP_WAIT1()  asm volatile("cp.async.wait_group 1;" ::: "memory")

__device__ __forceinline__ void ldm4(uint32_t* r, uint32_t addr) {
    asm volatile("ldmatrix.sync.aligned.m8n8.x4.shared.b16 {%0,%1,%2,%3}, [%4];"
                 : "=r"(r[0]), "=r"(r[1]), "=r"(r[2]), "=r"(r[3]) : "r"(addr));
}
__device__ __forceinline__ void mma_bf16(float* c, const uint32_t* a,
                                         uint32_t b0, uint32_t b1) {
    asm volatile(
        "mma.sync.aligned.m16n8k16.row.col.f32.bf16.bf16.f32 "
        "{%0,%1,%2,%3}, {%4,%5,%6,%7}, {%8,%9}, {%0,%1,%2,%3};"
        : "+f"(c[0]), "+f"(c[1]), "+f"(c[2]), "+f"(c[3])
        : "r"(a[0]), "r"(a[1]), "r"(a[2]), "r"(a[3]), "r"(b0), "r"(b1));
}

// ---------------- split / transpose prep kernels --------------------------------
__device__ __forceinline__ void split_bf(float v, __nv_bfloat16& hi, __nv_bfloat16& lo) {
    hi = __float2bfloat16(v);
    lo = __float2bfloat16(v - __bfloat162float(hi));
}

__global__ void split_x_kernel(const float* __restrict__ x) {
    int idx = blockIdx.x * blockDim.x + threadIdx.x;
    if (idx >= MKV_ * C_ / 4) return;
    float4 v = ((const float4*)x)[idx];
    __nv_bfloat16 h0, l0, h1, l1, h2, l2, h3, l3;
    split_bf(v.x, h0, l0); split_bf(v.y, h1, l1);
    split_bf(v.z, h2, l2); split_bf(v.w, h3, l3);
    ((__nv_bfloat162*)g_xhi)[idx * 2]     = __nv_bfloat162(h0, h1);
    ((__nv_bfloat162*)g_xhi)[idx * 2 + 1] = __nv_bfloat162(h2, h3);
    ((__nv_bfloat162*)g_xlo)[idx * 2]     = __nv_bfloat162(l0, l1);
    ((__nv_bfloat162*)g_xlo)[idx * 2 + 1] = __nv_bfloat162(l2, l3);
}

// Fused transpose+split of all 5 weight matrices; blockIdx.z selects matrix.
// dst[n][k] = src[k][n] (bf16 hi/lo). Zero-fills n in [N, dstRows).
__global__ void tpose_split_all_kernel(
    const float* __restrict__ Wq, const float* __restrict__ Wk,
    const float* __restrict__ Wv, const float* __restrict__ Wproj,
    const float* __restrict__ Woff)
{
    const float* src;
    __nv_bfloat16 *dhi, *dlo;
    int N, dstRows;
    switch (blockIdx.z) {
        case 0: src = Wq;    dhi = g_wqT_hi;    dlo = g_wqT_lo;    N = C_;   dstRows = C_;    break;
        case 1: src = Wk;    dhi = g_wkvT_hi;   dlo = g_wkvT_lo;   N = C_;   dstRows = C_;    break;
        case 2: src = Wv;    dhi = g_wkvT_hi + (long)C_ * C_;
                             dlo = g_wkvT_lo + (long)C_ * C_;      N = C_;   dstRows = C_;    break;
        case 3: src = Wproj; dhi = g_wprojT_hi; dlo = g_wprojT_lo; N = C_;   dstRows = C_;    break;
        default: src = Woff; dhi = g_woffT_hi;  dlo = g_woffT_lo;  N = NOFF_; dstRows = NOFFP_; break;
    }
    int n0 = blockIdx.x * 32, k0 = blockIdx.y * 32;
    if (n0 >= dstRows) return;

    __shared__ float tile[32][33];
    int tx = threadIdx.x, ty = threadIdx.y;
#pragma unroll
    for (int j = 0; j < 4; j++) {
        int k = k0 + ty + j * 8, n = n0 + tx;
        tile[ty + j * 8][tx] = (n < N) ? src[(long)k * N + n] : 0.f;
    }
    __syncthreads();
#pragma unroll
    for (int j = 0; j < 4; j++) {
        int n = n0 + ty + j * 8, k = k0 + tx;
        if (n < dstRows) {
            __nv_bfloat16 hi, lo;
            split_bf(tile[tx][ty + j * 8], hi, lo);
            dhi[(long)n * C_ + k] = hi;
            dlo[(long)n * C_ + k] = lo;
        }
    }
}

__global__ void sum3_split_kernel() {
    int idx = blockIdx.x * blockDim.x + threadIdx.x;
    if (idx >= BN_ * C_ / 4) return;
    const float third = 1.0f / 3.0f;
    float4 a = ((const float4*)g_attn)[idx];
    float4 b = ((const float4*)(g_attn + (long)BN_ * C_))[idx];
    float4 c = ((const float4*)(g_attn + 2L * BN_ * C_))[idx];
    float s0 = (a.x + b.x + c.x) * third;
    float s1 = (a.y + b.y + c.y) * third;
    float s2 = (a.z + b.z + c.z) * third;
    float s3 = (a.w + b.w + c.w) * third;
    __nv_bfloat16 h0, l0, h1, l1, h2, l2, h3, l3;
    split_bf(s0, h0, l0); split_bf(s1, h1, l1);
    split_bf(s2, h2, l2); split_bf(s3, h3, l3);
    ((__nv_bfloat162*)g_ahi)[idx * 2]     = __nv_bfloat162(h0, h1);
    ((__nv_bfloat162*)g_ahi)[idx * 2 + 1] = __nv_bfloat162(h2, h3);
    ((__nv_bfloat162*)g_alo)[idx * 2]     = __nv_bfloat162(l0, l1);
    ((__nv_bfloat162*)g_alo)[idx * 2 + 1] = __nv_bfloat162(l2, l3);
}

// ---------------- mma.sync bf16x3 GEMM -------------------------------------------
#define TILE_BYTES 16384              // 128 x 64 bf16
#define STAGE_BYTES (4 * TILE_BYTES)  // Ahi,Alo,Bhi,Blo
#define SMEM_TOTAL (2 * STAGE_BYTES)  // 131072

__global__ __launch_bounds__(256, 1)
void gemm_bf16x3(const __nv_bfloat16* __restrict__ Ahi,
                 const __nv_bfloat16* __restrict__ Alo, long lda,
                 const __nv_bfloat16* __restrict__ Bhi,
                 const __nv_bfloat16* __restrict__ Blo,
                 const float* __restrict__ bias,
                 float* __restrict__ C, int ldc, int Nstore, int K)
{
    extern __shared__ char smem[];
    uint32_t sb = smem_to_u32(smem);

    int tid = threadIdx.x;
    int wid = tid >> 5, lane = tid & 31;
    int warp_m = wid & 3;
    int warp_n = wid >> 2;
    int row0 = blockIdx.y * 128, col0 = blockIdx.x * 128;

    const int NKITER = K / 64;

    int rr[4], cc[4], doff[4];
#pragma unroll
    for (int j = 0; j < 4; j++) {
        int u = tid + j * 256;
        int r = u >> 3, cu = u & 7;
        rr[j] = r; cc[j] = cu;
        doff[j] = ((r << 3) + (cu ^ (r & 7))) << 4;
    }

    const __nv_bfloat16* gp[4] = {Ahi, Alo, Bhi, Blo};
    long  st[4] = {lda, lda, (long)K, (long)K};
    int   rb[4] = {row0, row0, col0, col0};

#pragma unroll
    for (int a = 0; a < 4; a++) {
        uint32_t sdst = sb + a * TILE_BYTES;
        const __nv_bfloat16* g = gp[a];
#pragma unroll
        for (int j = 0; j < 4; j++)
            cp16(sdst + doff[j], g + (long)(rb[a] + rr[j]) * st[a] + cc[j] * 8);
    }
    CP_COMMIT();

    float acc[2][8][4];
#pragma unroll
    for (int mf = 0; mf < 2; mf++)
#pragma unroll
        for (int nf = 0; nf < 8; nf++)
#pragma unroll
            for (int e = 0; e < 4; e++) acc[mf][nf][e] = 0.f;

    int a_r = warp_m * 32 + (lane & 7) + ((lane & 8) ? 8 : 0);
    int a_usel = (lane & 16) ? 1 : 0;
    int b_rbase = warp_n * 64 + (lane & 7) + ((lane & 16) ? 8 : 0);
    int b_usel = (lane & 8) ? 1 : 0;

    for (int kc = 0; kc < NKITER; kc++) {
        if (kc + 1 < NKITER) {
            uint32_t sstage = sb + ((kc + 1) & 1) * STAGE_BYTES;
            int k0 = (kc + 1) * 64;
#pragma unroll
            for (int a = 0; a < 4; a++) {
                uint32_t sdst = sstage + a * TILE_BYTES;
                const __nv_bfloat16* g = gp[a];
#pragma unroll
                for (int j = 0; j < 4; j++)
                    cp16(sdst + doff[j],
                         g + (long)(rb[a] + rr[j]) * st[a] + k0 + cc[j] * 8);
            }
            CP_COMMIT();
            CP_WAIT1();
        } else {
            CP_WAIT0();
        }
        __syncthreads();

        uint32_t s = sb + (kc & 1) * STAGE_BYTES;
        uint32_t sAhi = s, sAlo = s + TILE_BYTES;
        uint32_t sBhi = s + 2 * TILE_BYTES, sBlo = s + 3 * TILE_BYTES;

#pragma unroll
        for (int ks = 0; ks < 4; ks++) {
            uint32_t ah[2][4], al[2][4];
#pragma unroll
            for (int mf = 0; mf < 2; mf++) {
                int r = a_r + mf * 16;
                int u = ks * 2 + a_usel;
                uint32_t off = (uint32_t)(((r << 3) + (u ^ (r & 7))) << 4);
                ldm4(ah[mf], sAhi + off);
                ldm4(al[mf], sAlo + off);
            }
            uint32_t bh[4][4], bl[4][4];
#pragma unroll
            for (int np = 0; np < 4; np++) {
                int r = b_rbase + np * 16;
                int u = ks * 2 + b_usel;
                uint32_t off = (uint32_t)(((r << 3) + (u ^ (r & 7))) << 4);
                ldm4(bh[np], sBhi + off);
                ldm4(bl[np], sBlo + off);
            }
#pragma unroll
            for (int mf = 0; mf < 2; mf++)
#pragma unroll
                for (int nf = 0; nf < 8; nf++) {
                    int np = nf >> 1;
                    int half = (nf & 1) * 2;
                    uint32_t bh0 = bh[np][half], bh1 = bh[np][half + 1];
                    uint32_t bl0 = bl[np][half], bl1 = bl[np][half + 1];
                    mma_bf16(acc[mf][nf], ah[mf], bh0, bh1);
                    mma_bf16(acc[mf][nf], ah[mf], bl0, bl1);
                    mma_bf16(acc[mf][nf], al[mf], bh0, bh1);
                }
        }
        __syncthreads();
    }

#pragma unroll
    for (int mf = 0; mf < 2; mf++) {
        int m = row0 + warp_m * 32 + mf * 16 + (lane >> 2);
#pragma unroll
        for (int nf = 0; nf < 8; nf++) {
            int n = col0 + warp_n * 64 + nf * 8 + (lane & 3) * 2;
            if (n < Nstore) {
                float2 v0, v1;
                v0.x = acc[mf][nf][0]; v0.y = acc[mf][nf][1];
                v1.x = acc[mf][nf][2]; v1.y = acc[mf][nf][3];
                if (bias) {
                    float bx = bias[n], by = bias[n + 1];
                    v0.x += bx; v0.y += by;
                    v1.x += bx; v1.y += by;
                }
                *(float2*)(C + (long)m * ldc + n)       = v0;
                *(float2*)(C + (long)(m + 8) * ldc + n) = v1;
            }
        }
    }
}

// ---------------- deformable attention core --------------------------------------
// grid=(B*N, T), 384 threads = 12 warps (warp h = head h). Lane owns channel
// pair (2*lane, 2*lane+1) -> float2 loads, branch-free bilinear corners.
__global__ __launch_bounds__(384, 2) void attn_kernel(
    const float* __restrict__ mask,
    const float* __restrict__ suppress_p)
{
    int bn = blockIdx.x;
    int t  = blockIdx.y;
    int b  = bn / N_;
    int n  = bn % N_;
    int h    = threadIdx.x >> 5;
    int lane = threadIdx.x & 31;

    float suppress = *suppress_p;
    float mk  = mask[bn];
    float sw  = 1.f - suppress * mk;
    float moff = suppress * mk * 0.1f;

    float refx = (float)(n % HP_) * (2.f / 23.f) - 1.f;
    float refy = (float)(n / HP_) * (2.f / 23.f) - 1.f;

    const float2* q2 = (const float2*)(g_q + (long)bn * C_ + h * DH_);
    float2 q = q2[lane];

    const float* offrow = g_off + (long)bn * NOFF_ + h * (P_ * 2);

    float  logit[P_];
    float2 sv[P_];
#pragma unroll
    for (int p = 0; p < P_; p++) {
        float ox = offrow[p * 2 + 0] - moff;
        float oy = offrow[p * 2 + 1] - moff;
        float xs = (refx + ox + 1.f) * 11.5f;
        float ys = (refy + oy + 1.f) * 11.5f;
        float x0f = floorf(xs), y0f = floorf(ys);
        int   x0 = (int)x0f,  y0 = (int)y0f;
        float wx1 = xs - x0f, wy1 = ys - y0f;
        float wx0 = 1.f - wx1, wy0 = 1.f - wy1;

        float2 kk = make_float2(0.f, 0.f), vv = make_float2(0.f, 0.f);
#pragma unroll
        for (int c = 0; c < 4; c++) {
            int dx = c & 1, dy = c >> 1;
            int ix = x0 + dx, iy = y0 + dy;
            float valid = (ix >= 0 && ix < HP_ && iy >= 0 && iy < HP_) ? 1.f : 0.f;
            float w = (dx ? wx1 : wx0) * (dy ? wy1 : wy0) * valid;
            int ixc = min(max(ix, 0), HP_ - 1);
            int iyc = min(max(iy, 0), HP_ - 1);
            int pix = iyc * HP_ + ixc;
            long base = ((long)((b * N_ + pix) * T_ + t)) * CKV_ + h * DH_ + 2 * lane;
            float2 kl = *(const float2*)(g_kv + base);
            float2 vl = *(const float2*)(g_kv + base + C_);
            kk.x = fmaf(w, kl.x, kk.x); kk.y = fmaf(w, kl.y, kk.y);
            vv.x = fmaf(w, vl.x, vv.x); vv.y = fmaf(w, vl.y, vv.y);
        }
        float dot = q.x * kk.x + q.y * kk.y;
#pragma unroll
        for (int s = 16; s > 0; s >>= 1)
            dot += __shfl_xor_sync(0xffffffffu, dot, s);
        logit[p] = dot * SCALE_ * sw;
        sv[p] = vv;
    }
    float m = logit[0];
#pragma unroll
    for (int p = 1; p < P_; p++) m = fmaxf(m, logit[p]);
    float s = 0.f;
    float e[P_];
#pragma unroll
    for (int p = 0; p < P_; p++) { e[p] = __expf(logit[p] - m); s += e[p]; }
    float inv = 1.f / s;

    float2 o = make_float2(0.f, 0.f);
#pragma unroll
    for (int p = 0; p < P_; p++) {
        float a = e[p] * inv;
        o.x = fmaf(a, sv[p].x, o.x);
        o.y = fmaf(a, sv[p].y, o.y);
    }

    float2* orow = (float2*)(g_attn + ((long)t * BN_ + bn) * C_ + h * DH_);
    orow[lane] = o;
}

// ---------------- launch ----------------------------------------------------------
extern "C" void kernel_launch(void* const* d_in, const int* in_sizes, int n_in,
                              void* d_out, int out_size)
{
    const float* x     = (const float*)d_in[0];
    const float* mask  = (const float*)d_in[1];
    const float* Wq    = (const float*)d_in[2];
    const float* Wk    = (const float*)d_in[3];
    const float* Wv    = (const float*)d_in[4];
    const float* Woff  = (const float*)d_in[5];
    const float* boff  = (const float*)d_in[6];
    const float* Wproj = (const float*)d_in[7];
    const float* bproj = (const float*)d_in[8];
    const float* suppr = (const float*)d_in[9];
    float* out = (float*)d_out;

    __nv_bfloat16 *xhi, *xlo, *wkvh, *wkvl, *wqh, *wql, *wph, *wpl, *wofh, *wofl, *ahi, *alo;
    float *kvbuf, *qbuf, *offbuf, *attnbuf;
    cudaGetSymbolAddress((void**)&xhi,  g_xhi);
    cudaGetSymbolAddress((void**)&xlo,  g_xlo);
    cudaGetSymbolAddress((void**)&wkvh, g_wkvT_hi);
    cudaGetSymbolAddress((void**)&wkvl, g_wkvT_lo);
    cudaGetSymbolAddress((void**)&wqh,  g_wqT_hi);
    cudaGetSymbolAddress((void**)&wql,  g_wqT_lo);
    cudaGetSymbolAddress((void**)&wph,  g_wprojT_hi);
    cudaGetSymbolAddress((void**)&wpl,  g_wprojT_lo);
    cudaGetSymbolAddress((void**)&wofh, g_woffT_hi);
    cudaGetSymbolAddress((void**)&wofl, g_woffT_lo);
    cudaGetSymbolAddress((void**)&ahi,  g_ahi);
    cudaGetSymbolAddress((void**)&alo,  g_alo);
    cudaGetSymbolAddress((void**)&kvbuf,   g_kv);
    cudaGetSymbolAddress((void**)&qbuf,    g_q);
    cudaGetSymbolAddress((void**)&offbuf,  g_off);
    cudaGetSymbolAddress((void**)&attnbuf, g_attn);

    cudaFuncSetAttribute(gemm_bf16x3,
                         cudaFuncAttributeMaxDynamicSharedMemorySize, SMEM_TOTAL);

    // prep: split x, fused transpose+split of all weights
    split_x_kernel<<<(MKV_ * C_ / 4 + 255) / 256, 256>>>(x);
    tpose_split_all_kernel<<<dim3(C_ / 32, C_ / 32, 5), dim3(32, 8)>>>(
        Wq, Wk, Wv, Wproj, Woff);

    // 1) KV: x(6912x768) @ [Wk|Wv] -> g_kv (6912x1536)
    gemm_bf16x3<<<dim3(CKV_ / 128, MKV_ / 128), 256, SMEM_TOTAL>>>(
        xhi, xlo, C_, wkvh, wkvl, nullptr, kvbuf, CKV_, CKV_, C_);
    // 2) Q: query rows (stride T*C, offset C)
    gemm_bf16x3<<<dim3(C_ / 128, BN_ / 128), 256, SMEM_TOTAL>>>(
        xhi + C_, xlo + C_, (long)T_ * C_, wqh, wql, nullptr, qbuf, C_, C_, C_);
    // 3) offsets (+boff), N padded 256 -> store 216
    gemm_bf16x3<<<dim3(NOFFP_ / 128, BN_ / 128), 256, SMEM_TOTAL>>>(
        xhi + C_, xlo + C_, (long)T_ * C_, wofh, wofl, boff, offbuf, NOFF_, NOFF_, C_);
    // 4) attention
    {
        dim3 grid(BN_, T_);
        attn_kernel<<<grid, 384>>>(mask, suppr);
    }
    // 5) average over t, split, project (+bproj)
    sum3_split_kernel<<<(BN_ * C_ / 4 + 255) / 256, 256>>>();
    gemm_bf16x3<<<dim3(C_ / 128, BN_ / 128), 256, SMEM_TOTAL>>>(
        ahi, alo, C_, wph, wpl, bproj, out, C_, C_, C_);
}

// round 6
// speedup vs baseline: 3.0653x; 1.0520x over previous
#include <cuda_runtime.h>
#include <cuda_bf16.h>
#include <cstdint>
#include <math.h>

#define B_  4
#define N_  576
#define T_  3
#define C_  768
#define H_  12
#define P_  9
#define DH_ 64
#define HP_ 24
#define SCALE_ 0.125f
#define BN_ (B_ * N_)
#define CKV_ (2 * C_)       // 1536
#define MKV_ (BN_ * T_)     // 6912
#define NOFF_ (H_ * P_ * 2) // 216
#define NQOFF_ 1024         // 768 (q) + 256 (off padded)

// ---------------- scratch (device globals) -----------------------------------
__device__ __nv_bfloat16 g_xhi[MKV_ * C_];
__device__ __nv_bfloat16 g_xlo[MKV_ * C_];
__device__ __nv_bfloat16 g_wkvT_hi[CKV_ * C_];    // [n][k]; n<768: Wk, else Wv
__device__ __nv_bfloat16 g_wkvT_lo[CKV_ * C_];
__device__ __nv_bfloat16 g_wqoffT_hi[NQOFF_ * C_]; // rows 0-767 Wq^T, 768+ Woff^T
__device__ __nv_bfloat16 g_wqoffT_lo[NQOFF_ * C_];
__device__ __nv_bfloat16 g_wprojT_hi[C_ * C_];
__device__ __nv_bfloat16 g_wprojT_lo[C_ * C_];
__device__ __nv_bfloat16 g_ahi[BN_ * C_];
__device__ __nv_bfloat16 g_alo[BN_ * C_];
__device__ float g_bias_qoff[NQOFF_];

__device__ float g_kv[MKV_ * CKV_];
__device__ float g_qoff[BN_ * NQOFF_];   // per row: q[768] | off[216] | pad
__device__ float g_attn[T_ * BN_ * C_];

// ---------------- PTX helpers ---------------------------------------------------
__device__ __forceinline__ uint32_t smem_to_u32(const void* p) {
    uint32_t a;
    asm("{ .reg .u64 t; cvta.to.shared.u64 t, %1; cvt.u32.u64 %0, t; }"
        : "=r"(a) : "l"(p));
    return a;
}
__device__ __forceinline__ void cp16(uint32_t dst, const void* src) {
    asm volatile("cp.async.cg.shared.global [%0], [%1], 16;"
                 :: "r"(dst), "l"(src));
}
#define CP_COMMIT() asm volatile("cp.async.commit_group;" ::: "memory")
#define CP_WAIT0()  asm volatile("cp.async.wait_group 0;" ::: "memory")
#define CP_WAIT1()  asm volatile("cp.async.wait_group 1;" ::: "memory")

__device__ __forceinline__ void ldm4(uint32_t* r, uint32_t addr) {
    asm volatile("ldmatrix.sync.aligned.m8n8.x4.shared.b16 {%0,%1,%2,%3}, [%4];"
                 : "=r"(r[0]), "=r"(r[1]), "=r"(r[2]), "=r"(r[3]) : "r"(addr));
}
__device__ __forceinline__ void mma_bf16(float* c, const uint32_t* a,
                                         uint32_t b0, uint32_t b1) {
    asm volatile(
        "mma.sync.aligned.m16n8k16.row.col.f32.bf16.bf16.f32 "
        "{%0,%1,%2,%3}, {%4,%5,%6,%7}, {%8,%9}, {%0,%1,%2,%3};"
        : "+f"(c[0]), "+f"(c[1]), "+f"(c[2]), "+f"(c[3])
        : "r"(a[0]), "r"(a[1]), "r"(a[2]), "r"(a[3]), "r"(b0), "r"(b1));
}

// ---------------- prep kernels ---------------------------------------------------
__device__ __forceinline__ void split_bf(float v, __nv_bfloat16& hi, __nv_bfloat16& lo) {
    hi = __float2bfloat16(v);
    lo = __float2bfloat16(v - __bfloat162float(hi));
}

__global__ void split_x_kernel(const float* __restrict__ x) {
    int idx = blockIdx.x * blockDim.x + threadIdx.x;
    if (idx >= MKV_ * C_ / 4) return;
    float4 v = ((const float4*)x)[idx];
    __nv_bfloat16 h0, l0, h1, l1, h2, l2, h3, l3;
    split_bf(v.x, h0, l0); split_bf(v.y, h1, l1);
    split_bf(v.z, h2, l2); split_bf(v.w, h3, l3);
    ((__nv_bfloat162*)g_xhi)[idx * 2]     = __nv_bfloat162(h0, h1);
    ((__nv_bfloat162*)g_xhi)[idx * 2 + 1] = __nv_bfloat162(h2, h3);
    ((__nv_bfloat162*)g_xlo)[idx * 2]     = __nv_bfloat162(l0, l1);
    ((__nv_bfloat162*)g_xlo)[idx * 2 + 1] = __nv_bfloat162(l2, l3);
}

// Fused transpose+split of all weights; blockIdx.z selects matrix.
__global__ void tpose_split_all_kernel(
    const float* __restrict__ Wq, const float* __restrict__ Wk,
    const float* __restrict__ Wv, const float* __restrict__ Wproj,
    const float* __restrict__ Woff, const float* __restrict__ boff)
{
    // bias prep piggyback (block (0,0,0))
    if (blockIdx.z == 0 && blockIdx.x == 0 && blockIdx.y == 0) {
        int t = threadIdx.y * 32 + threadIdx.x;
        for (int i = t; i < NQOFF_; i += 256)
            g_bias_qoff[i] = (i >= 768 && i < 768 + NOFF_) ? boff[i - 768] : 0.f;
    }

    const float* src;
    __nv_bfloat16 *dhi, *dlo;
    int N, dstRows;
    switch (blockIdx.z) {
        case 0: src = Wq;    dhi = g_wqoffT_hi; dlo = g_wqoffT_lo; N = C_; dstRows = C_; break;
        case 1: src = Wk;    dhi = g_wkvT_hi;   dlo = g_wkvT_lo;   N = C_; dstRows = C_; break;
        case 2: src = Wv;    dhi = g_wkvT_hi + (long)C_ * C_;
                             dlo = g_wkvT_lo + (long)C_ * C_;      N = C_; dstRows = C_; break;
        case 3: src = Wproj; dhi = g_wprojT_hi; dlo = g_wprojT_lo; N = C_; dstRows = C_; break;
        default: src = Woff; dhi = g_wqoffT_hi + (long)768 * C_;
                             dlo = g_wqoffT_lo + (long)768 * C_;   N = NOFF_; dstRows = 256; break;
    }
    int n0 = blockIdx.x * 32, k0 = blockIdx.y * 32;
    if (n0 >= dstRows) return;

    __shared__ float tile[32][33];
    int tx = threadIdx.x, ty = threadIdx.y;
#pragma unroll
    for (int j = 0; j < 4; j++) {
        int k = k0 + ty + j * 8, n = n0 + tx;
        tile[ty + j * 8][tx] = (n < N) ? src[(long)k * N + n] : 0.f;
    }
    __syncthreads();
#pragma unroll
    for (int j = 0; j < 4; j++) {
        int n = n0 + ty + j * 8, k = k0 + tx;
        if (n < dstRows) {
            __nv_bfloat16 hi, lo;
            split_bf(tile[tx][ty + j * 8], hi, lo);
            dhi[(long)n * C_ + k] = hi;
            dlo[(long)n * C_ + k] = lo;
        }
    }
}

__global__ void sum3_split_kernel() {
    int idx = blockIdx.x * blockDim.x + threadIdx.x;
    if (idx >= BN_ * C_ / 4) return;
    const float third = 1.0f / 3.0f;
    float4 a = ((const float4*)g_attn)[idx];
    float4 b = ((const float4*)(g_attn + (long)BN_ * C_))[idx];
    float4 c = ((const float4*)(g_attn + 2L * BN_ * C_))[idx];
    float s0 = (a.x + b.x + c.x) * third;
    float s1 = (a.y + b.y + c.y) * third;
    float s2 = (a.z + b.z + c.z) * third;
    float s3 = (a.w + b.w + c.w) * third;
    __nv_bfloat16 h0, l0, h1, l1, h2, l2, h3, l3;
    split_bf(s0, h0, l0); split_bf(s1, h1, l1);
    split_bf(s2, h2, l2); split_bf(s3, h3, l3);
    ((__nv_bfloat162*)g_ahi)[idx * 2]     = __nv_bfloat162(h0, h1);
    ((__nv_bfloat162*)g_ahi)[idx * 2 + 1] = __nv_bfloat162(h2, h3);
    ((__nv_bfloat162*)g_alo)[idx * 2]     = __nv_bfloat162(l0, l1);
    ((__nv_bfloat162*)g_alo)[idx * 2 + 1] = __nv_bfloat162(l2, l3);
}

// ---------------- mma.sync bf16x3 GEMM body (512 threads, 16 warps) --------------
// Tile 128x128, K-chunk 64, SW128 XOR swizzle, double-buffered cp.async.
// Warp grid 4(m) x 4(n); warp tile 32x32.
#define TILE_BYTES 16384              // 128 x 64 bf16
#define STAGE_BYTES (4 * TILE_BYTES)
#define SMEM_TOTAL (2 * STAGE_BYTES)  // 131072

__device__ __forceinline__ void gemm_body(
    const __nv_bfloat16* __restrict__ Ahi,
    const __nv_bfloat16* __restrict__ Alo, long lda,
    const __nv_bfloat16* __restrict__ Bhi,
    const __nv_bfloat16* __restrict__ Blo,
    const float* __restrict__ bias,
    float* __restrict__ C, int ldc, int Nstore, int K,
    int row0, int col0, char* smem)
{
    uint32_t sb = smem_to_u32(smem);
    int tid = threadIdx.x;
    int wid = tid >> 5, lane = tid & 31;
    int warp_m = wid & 3;          // 4 m-warps * 32 rows
    int warp_n = wid >> 2;         // 4 n-warps * 32 cols
    const int NKITER = K / 64;

    int rr[2], cc[2], doff[2];
#pragma unroll
    for (int j = 0; j < 2; j++) {
        int u = tid + j * 512;
        int r = u >> 3, cu = u & 7;
        rr[j] = r; cc[j] = cu;
        doff[j] = ((r << 3) + (cu ^ (r & 7))) << 4;
    }

    const __nv_bfloat16* gp[4] = {Ahi, Alo, Bhi, Blo};
    long  st[4] = {lda, lda, (long)K, (long)K};
    int   rb[4] = {row0, row0, col0, col0};

#pragma unroll
    for (int a = 0; a < 4; a++) {
        uint32_t sdst = sb + a * TILE_BYTES;
        const __nv_bfloat16* g = gp[a];
#pragma unroll
        for (int j = 0; j < 2; j++)
            cp16(sdst + doff[j], g + (long)(rb[a] + rr[j]) * st[a] + cc[j] * 8);
    }
    CP_COMMIT();

    float acc[2][4][4];
#pragma unroll
    for (int mf = 0; mf < 2; mf++)
#pragma unroll
        for (int nf = 0; nf < 4; nf++)
#pragma unroll
            for (int e = 0; e < 4; e++) acc[mf][nf][e] = 0.f;

    int a_r = warp_m * 32 + (lane & 7) + ((lane & 8) ? 8 : 0);
    int a_usel = (lane & 16) ? 1 : 0;
    int b_rbase = warp_n * 32 + (lane & 7) + ((lane & 16) ? 8 : 0);
    int b_usel = (lane & 8) ? 1 : 0;

    for (int kc = 0; kc < NKITER; kc++) {
        if (kc + 1 < NKITER) {
            uint32_t sstage = sb + ((kc + 1) & 1) * STAGE_BYTES;
            int k0 = (kc + 1) * 64;
#pragma unroll
            for (int a = 0; a < 4; a++) {
                uint32_t sdst = sstage + a * TILE_BYTES;
                const __nv_bfloat16* g = gp[a];
#pragma unroll
                for (int j = 0; j < 2; j++)
                    cp16(sdst + doff[j],
                         g + (long)(rb[a] + rr[j]) * st[a] + k0 + cc[j] * 8);
            }
            CP_COMMIT();
            CP_WAIT1();
        } else {
            CP_WAIT0();
        }
        __syncthreads();

        uint32_t s = sb + (kc & 1) * STAGE_BYTES;
        uint32_t sAhi = s, sAlo = s + TILE_BYTES;
        uint32_t sBhi = s + 2 * TILE_BYTES, sBlo = s + 3 * TILE_BYTES;

#pragma unroll
        for (int ks = 0; ks < 4; ks++) {
            uint32_t ah[2][4], al[2][4];
#pragma unroll
            for (int mf = 0; mf < 2; mf++) {
                int r = a_r + mf * 16;
                int u = ks * 2 + a_usel;
                uint32_t off = (uint32_t)(((r << 3) + (u ^ (r & 7))) << 4);
                ldm4(ah[mf], sAhi + off);
                ldm4(al[mf], sAlo + off);
            }
            uint32_t bh[2][4], bl[2][4];
#pragma unroll
            for (int np = 0; np < 2; np++) {
                int r = b_rbase + np * 16;
                int u = ks * 2 + b_usel;
                uint32_t off = (uint32_t)(((r << 3) + (u ^ (r & 7))) << 4);
                ldm4(bh[np], sBhi + off);
                ldm4(bl[np], sBlo + off);
            }
#pragma unroll
            for (int mf = 0; mf < 2; mf++)
#pragma unroll
                for (int nf = 0; nf < 4; nf++) {
                    int np = nf >> 1;
                    int half = (nf & 1) * 2;
                    uint32_t bh0 = bh[np][half], bh1 = bh[np][half + 1];
                    uint32_t bl0 = bl[np][half], bl1 = bl[np][half + 1];
                    mma_bf16(acc[mf][nf], ah[mf], bh0, bh1);
                    mma_bf16(acc[mf][nf], ah[mf], bl0, bl1);
                    mma_bf16(acc[mf][nf], al[mf], bh0, bh1);
                }
        }
        __syncthreads();
    }

#pragma unroll
    for (int mf = 0; mf < 2; mf++) {
        int m = row0 + warp_m * 32 + mf * 16 + (lane >> 2);
#pragma unroll
        for (int nf = 0; nf < 4; nf++) {
            int n = col0 + warp_n * 32 + nf * 8 + (lane & 3) * 2;
            if (n < Nstore) {
                float2 v0, v1;
                v0.x = acc[mf][nf][0]; v0.y = acc[mf][nf][1];
                v1.x = acc[mf][nf][2]; v1.y = acc[mf][nf][3];
                if (bias) {
                    float bx = bias[n], by = bias[n + 1];
                    v0.x += bx; v0.y += by;
                    v1.x += bx; v1.y += by;
                }
                *(float2*)(C + (long)m * ldc + n)       = v0;
                *(float2*)(C + (long)(m + 8) * ldc + n) = v1;
            }
        }
    }
}

// Merged launch: blocks 0..647 = KV gemm (12 x 54), 648..791 = Q+off gemm (8 x 18).
#define KV_BLOCKS 648
__global__ __launch_bounds__(512, 1)
void gemm_merged_kernel()
{
    extern __shared__ char smem[];
    int bid = blockIdx.x;
    if (bid < KV_BLOCKS) {
        int bx = bid % 12, by = bid / 12;
        gemm_body(g_xhi, g_xlo, C_, g_wkvT_hi, g_wkvT_lo, nullptr,
                  g_kv, CKV_, CKV_, C_, by * 128, bx * 128, smem);
    } else {
        int b2 = bid - KV_BLOCKS;
        int bx = b2 % 8, by = b2 / 8;
        gemm_body(g_xhi + C_, g_xlo + C_, (long)T_ * C_,
                  g_wqoffT_hi, g_wqoffT_lo, g_bias_qoff,
                  g_qoff, NQOFF_, 768 + NOFF_, C_, by * 128, bx * 128, smem);
    }
}

__global__ __launch_bounds__(512, 1)
void gemm_proj_kernel(const float* __restrict__ bias, float* __restrict__ C)
{
    extern __shared__ char smem[];
    gemm_body(g_ahi, g_alo, C_, g_wprojT_hi, g_wprojT_lo, bias,
              C, C_, C_, C_, blockIdx.y * 128, blockIdx.x * 128, smem);
}

// ---------------- deformable attention core --------------------------------------
__global__ __launch_bounds__(384, 2) void attn_kernel(
    const float* __restrict__ mask,
    const float* __restrict__ suppress_p)
{
    int bn = blockIdx.x;
    int t  = blockIdx.y;
    int b  = bn / N_;
    int n  = bn % N_;
    int h    = threadIdx.x >> 5;
    int lane = threadIdx.x & 31;

    float suppress = *suppress_p;
    float mk  = mask[bn];
    float sw  = 1.f - suppress * mk;
    float moff = suppress * mk * 0.1f;

    float refx = (float)(n % HP_) * (2.f / 23.f) - 1.f;
    float refy = (float)(n / HP_) * (2.f / 23.f) - 1.f;

    const float* rowbase = g_qoff + (long)bn * NQOFF_;
    float2 q = ((const float2*)(rowbase + h * DH_))[lane];

    // preload this head's 18 offsets via warp broadcast
    const float* offrow = rowbase + 768 + h * (P_ * 2);
    float offv = (lane < P_ * 2) ? offrow[lane] : 0.f;

    float  logit[P_];
    float2 sv[P_];
#pragma unroll
    for (int p = 0; p < P_; p++) {
        float ox = __shfl_sync(0xffffffffu, offv, 2 * p)     - moff;
        float oy = __shfl_sync(0xffffffffu, offv, 2 * p + 1) - moff;
        float xs = (refx + ox + 1.f) * 11.5f;
        float ys = (refy + oy + 1.f) * 11.5f;
        float x0f = floorf(xs), y0f = floorf(ys);
        int   x0 = (int)x0f,  y0 = (int)y0f;
        float wx1 = xs - x0f, wy1 = ys - y0f;
        float wx0 = 1.f - wx1, wy0 = 1.f - wy1;

        float2 kk = make_float2(0.f, 0.f), vv = make_float2(0.f, 0.f);
#pragma unroll
        for (int c = 0; c < 4; c++) {
            int dx = c & 1, dy = c >> 1;
            int ix = x0 + dx, iy = y0 + dy;
            float valid = (ix >= 0 && ix < HP_ && iy >= 0 && iy < HP_) ? 1.f : 0.f;
            float w = (dx ? wx1 : wx0) * (dy ? wy1 : wy0) * valid;
            int ixc = min(max(ix, 0), HP_ - 1);
            int iyc = min(max(iy, 0), HP_ - 1);
            int pix = iyc * HP_ + ixc;
            long base = ((long)((b * N_ + pix) * T_ + t)) * CKV_ + h * DH_ + 2 * lane;
            float2 kl = *(const float2*)(g_kv + base);
            float2 vl = *(const float2*)(g_kv + base + C_);
            kk.x = fmaf(w, kl.x, kk.x); kk.y = fmaf(w, kl.y, kk.y);
            vv.x = fmaf(w, vl.x, vv.x); vv.y = fmaf(w, vl.y, vv.y);
        }
        float dot = q.x * kk.x + q.y * kk.y;
#pragma unroll
        for (int s = 16; s > 0; s >>= 1)
            dot += __shfl_xor_sync(0xffffffffu, dot, s);
        logit[p] = dot * SCALE_ * sw;
        sv[p] = vv;
    }
    float m = logit[0];
#pragma unroll
    for (int p = 1; p < P_; p++) m = fmaxf(m, logit[p]);
    float s = 0.f;
    float e[P_];
#pragma unroll
    for (int p = 0; p < P_; p++) { e[p] = __expf(logit[p] - m); s += e[p]; }
    float inv = 1.f / s;

    float2 o = make_float2(0.f, 0.f);
#pragma unroll
    for (int p = 0; p < P_; p++) {
        float a = e[p] * inv;
        o.x = fmaf(a, sv[p].x, o.x);
        o.y = fmaf(a, sv[p].y, o.y);
    }

    float2* orow = (float2*)(g_attn + ((long)t * BN_ + bn) * C_ + h * DH_);
    orow[lane] = o;
}

// ---------------- launch ----------------------------------------------------------
extern "C" void kernel_launch(void* const* d_in, const int* in_sizes, int n_in,
                              void* d_out, int out_size)
{
    const float* x     = (const float*)d_in[0];
    const float* mask  = (const float*)d_in[1];
    const float* Wq    = (const float*)d_in[2];
    const float* Wk    = (const float*)d_in[3];
    const float* Wv    = (const float*)d_in[4];
    const float* Woff  = (const float*)d_in[5];
    const float* boff  = (const float*)d_in[6];
    const float* Wproj = (const float*)d_in[7];
    const float* bproj = (const float*)d_in[8];
    const float* suppr = (const float*)d_in[9];
    float* out = (float*)d_out;

    cudaFuncSetAttribute(gemm_merged_kernel,
                         cudaFuncAttributeMaxDynamicSharedMemorySize, SMEM_TOTAL);
    cudaFuncSetAttribute(gemm_proj_kernel,
                         cudaFuncAttributeMaxDynamicSharedMemorySize, SMEM_TOTAL);

    // prep: split x, fused transpose+split of all weights (+bias vector)
    split_x_kernel<<<(MKV_ * C_ / 4 + 255) / 256, 256>>>(x);
    tpose_split_all_kernel<<<dim3(C_ / 32, C_ / 32, 5), dim3(32, 8)>>>(
        Wq, Wk, Wv, Wproj, Woff, boff);

    // 1) merged KV + Q/off GEMM (792 CTAs)
    gemm_merged_kernel<<<KV_BLOCKS + 144, 512, SMEM_TOTAL>>>();

    // 2) attention
    {
        dim3 grid(BN_, T_);
        attn_kernel<<<grid, 384>>>(mask, suppr);
    }
    // 3) average over t, split, project (+bproj)
    sum3_split_kernel<<<(BN_ * C_ / 4 + 255) / 256, 256>>>();
    gemm_proj_kernel<<<dim3(C_ / 128, BN_ / 128), 512, SMEM_TOTAL>>>(bproj, out);
}

// round 7
// speedup vs baseline: 3.0813x; 1.0052x over previous
#include <cuda_runtime.h>
#include <cuda_bf16.h>
#include <cstdint>
#include <math.h>

#define B_  4
#define N_  576
#define T_  3
#define C_  768
#define H_  12
#define P_  9
#define DH_ 64
#define HP_ 24
#define SCALE_ 0.125f
#define BN_ (B_ * N_)
#define CKV_ (2 * C_)       // 1536
#define MKV_ (BN_ * T_)     // 6912
#define NOFF_ (H_ * P_ * 2) // 216
#define NQOFF_ 1024         // 768 (q) + 256 (off padded)

// ---------------- scratch (device globals) -----------------------------------
__device__ __nv_bfloat16 g_xhi[MKV_ * C_];
__device__ __nv_bfloat16 g_xlo[MKV_ * C_];
__device__ __nv_bfloat16 g_wkvT_hi[CKV_ * C_];    // [n][k]; n<768: Wk, else Wv
__device__ __nv_bfloat16 g_wkvT_lo[CKV_ * C_];
__device__ __nv_bfloat16 g_wqoffT_hi[NQOFF_ * C_]; // rows 0-767 Wq^T, 768+ Woff^T
__device__ __nv_bfloat16 g_wqoffT_lo[NQOFF_ * C_];
__device__ __nv_bfloat16 g_wprojT_hi[C_ * C_];
__device__ __nv_bfloat16 g_wprojT_lo[C_ * C_];
__device__ __nv_bfloat16 g_ahi[BN_ * C_];
__device__ __nv_bfloat16 g_alo[BN_ * C_];
__device__ float g_bias_qoff[NQOFF_];

__device__ float g_kv[MKV_ * CKV_];
__device__ float g_qoff[BN_ * NQOFF_];   // per row: q[768] | off[216] | pad
__device__ float g_attn[T_ * BN_ * C_];

// ---------------- PTX helpers ---------------------------------------------------
__device__ __forceinline__ uint32_t smem_to_u32(const void* p) {
    uint32_t a;
    asm("{ .reg .u64 t; cvta.to.shared.u64 t, %1; cvt.u32.u64 %0, t; }"
        : "=r"(a) : "l"(p));
    return a;
}
__device__ __forceinline__ void cp16(uint32_t dst, const void* src) {
    asm volatile("cp.async.cg.shared.global [%0], [%1], 16;"
                 :: "r"(dst), "l"(src));
}
#define CP_COMMIT() asm volatile("cp.async.commit_group;" ::: "memory")
#define CP_WAIT0()  asm volatile("cp.async.wait_group 0;" ::: "memory")
#define CP_WAIT1()  asm volatile("cp.async.wait_group 1;" ::: "memory")

__device__ __forceinline__ void ldm4(uint32_t* r, uint32_t addr) {
    asm volatile("ldmatrix.sync.aligned.m8n8.x4.shared.b16 {%0,%1,%2,%3}, [%4];"
                 : "=r"(r[0]), "=r"(r[1]), "=r"(r[2]), "=r"(r[3]) : "r"(addr));
}
__device__ __forceinline__ void mma_bf16(float* c, const uint32_t* a,
                                         uint32_t b0, uint32_t b1) {
    asm volatile(
        "mma.sync.aligned.m16n8k16.row.col.f32.bf16.bf16.f32 "
        "{%0,%1,%2,%3}, {%4,%5,%6,%7}, {%8,%9}, {%0,%1,%2,%3};"
        : "+f"(c[0]), "+f"(c[1]), "+f"(c[2]), "+f"(c[3])
        : "r"(a[0]), "r"(a[1]), "r"(a[2]), "r"(a[3]), "r"(b0), "r"(b1));
}

// ---------------- prep kernels ---------------------------------------------------
__device__ __forceinline__ void split_bf(float v, __nv_bfloat16& hi, __nv_bfloat16& lo) {
    hi = __float2bfloat16(v);
    lo = __float2bfloat16(v - __bfloat162float(hi));
}

__global__ void split_x_kernel(const float* __restrict__ x) {
    int idx = blockIdx.x * blockDim.x + threadIdx.x;
    if (idx >= MKV_ * C_ / 4) return;
    float4 v = ((const float4*)x)[idx];
    __nv_bfloat16 h0, l0, h1, l1, h2, l2, h3, l3;
    split_bf(v.x, h0, l0); split_bf(v.y, h1, l1);
    split_bf(v.z, h2, l2); split_bf(v.w, h3, l3);
    ((__nv_bfloat162*)g_xhi)[idx * 2]     = __nv_bfloat162(h0, h1);
    ((__nv_bfloat162*)g_xhi)[idx * 2 + 1] = __nv_bfloat162(h2, h3);
    ((__nv_bfloat162*)g_xlo)[idx * 2]     = __nv_bfloat162(l0, l1);
    ((__nv_bfloat162*)g_xlo)[idx * 2 + 1] = __nv_bfloat162(l2, l3);
}

// Fused transpose+split of all weights; blockIdx.z selects matrix.
__global__ void tpose_split_all_kernel(
    const float* __restrict__ Wq, const float* __restrict__ Wk,
    const float* __restrict__ Wv, const float* __restrict__ Wproj,
    const float* __restrict__ Woff, const float* __restrict__ boff)
{
    if (blockIdx.z == 0 && blockIdx.x == 0 && blockIdx.y == 0) {
        int t = threadIdx.y * 32 + threadIdx.x;
        for (int i = t; i < NQOFF_; i += 256)
            g_bias_qoff[i] = (i >= 768 && i < 768 + NOFF_) ? boff[i - 768] : 0.f;
    }

    const float* src;
    __nv_bfloat16 *dhi, *dlo;
    int N, dstRows;
    switch (blockIdx.z) {
        case 0: src = Wq;    dhi = g_wqoffT_hi; dlo = g_wqoffT_lo; N = C_; dstRows = C_; break;
        case 1: src = Wk;    dhi = g_wkvT_hi;   dlo = g_wkvT_lo;   N = C_; dstRows = C_; break;
        case 2: src = Wv;    dhi = g_wkvT_hi + (long)C_ * C_;
                             dlo = g_wkvT_lo + (long)C_ * C_;      N = C_; dstRows = C_; break;
        case 3: src = Wproj; dhi = g_wprojT_hi; dlo = g_wprojT_lo; N = C_; dstRows = C_; break;
        default: src = Woff; dhi = g_wqoffT_hi + (long)768 * C_;
                             dlo = g_wqoffT_lo + (long)768 * C_;   N = NOFF_; dstRows = 256; break;
    }
    int n0 = blockIdx.x * 32, k0 = blockIdx.y * 32;
    if (n0 >= dstRows) return;

    __shared__ float tile[32][33];
    int tx = threadIdx.x, ty = threadIdx.y;
#pragma unroll
    for (int j = 0; j < 4; j++) {
        int k = k0 + ty + j * 8, n = n0 + tx;
        tile[ty + j * 8][tx] = (n < N) ? src[(long)k * N + n] : 0.f;
    }
    __syncthreads();
#pragma unroll
    for (int j = 0; j < 4; j++) {
        int n = n0 + ty + j * 8, k = k0 + tx;
        if (n < dstRows) {
            __nv_bfloat16 hi, lo;
            split_bf(tile[tx][ty + j * 8], hi, lo);
            dhi[(long)n * C_ + k] = hi;
            dlo[(long)n * C_ + k] = lo;
        }
    }
}

__global__ void sum3_split_kernel() {
    int idx = blockIdx.x * blockDim.x + threadIdx.x;
    if (idx >= BN_ * C_ / 4) return;
    const float third = 1.0f / 3.0f;
    float4 a = ((const float4*)g_attn)[idx];
    float4 b = ((const float4*)(g_attn + (long)BN_ * C_))[idx];
    float4 c = ((const float4*)(g_attn + 2L * BN_ * C_))[idx];
    float s0 = (a.x + b.x + c.x) * third;
    float s1 = (a.y + b.y + c.y) * third;
    float s2 = (a.z + b.z + c.z) * third;
    float s3 = (a.w + b.w + c.w) * third;
    __nv_bfloat16 h0, l0, h1, l1, h2, l2, h3, l3;
    split_bf(s0, h0, l0); split_bf(s1, h1, l1);
    split_bf(s2, h2, l2); split_bf(s3, h3, l3);
    ((__nv_bfloat162*)g_ahi)[idx * 2]     = __nv_bfloat162(h0, h1);
    ((__nv_bfloat162*)g_ahi)[idx * 2 + 1] = __nv_bfloat162(h2, h3);
    ((__nv_bfloat162*)g_alo)[idx * 2]     = __nv_bfloat162(l0, l1);
    ((__nv_bfloat162*)g_alo)[idx * 2 + 1] = __nv_bfloat162(l2, l3);
}

// ---------------- mma.sync bf16x3 GEMM body (512 threads, 16 warps) --------------
#define TILE_BYTES 16384              // 128 x 64 bf16
#define STAGE_BYTES (4 * TILE_BYTES)
#define SMEM_TOTAL (2 * STAGE_BYTES)  // 131072

__device__ __forceinline__ void gemm_body(
    const __nv_bfloat16* __restrict__ Ahi,
    const __nv_bfloat16* __restrict__ Alo, long lda,
    const __nv_bfloat16* __restrict__ Bhi,
    const __nv_bfloat16* __restrict__ Blo,
    const float* __restrict__ bias,
    float* __restrict__ C, int ldc, int Nstore, int K,
    int row0, int col0, char* smem)
{
    uint32_t sb = smem_to_u32(smem);
    int tid = threadIdx.x;
    int wid = tid >> 5, lane = tid & 31;
    int warp_m = wid & 3;
    int warp_n = wid >> 2;
    const int NKITER = K / 64;

    int rr[2], cc[2], doff[2];
#pragma unroll
    for (int j = 0; j < 2; j++) {
        int u = tid + j * 512;
        int r = u >> 3, cu = u & 7;
        rr[j] = r; cc[j] = cu;
        doff[j] = ((r << 3) + (cu ^ (r & 7))) << 4;
    }

    const __nv_bfloat16* gp[4] = {Ahi, Alo, Bhi, Blo};
    long  st[4] = {lda, lda, (long)K, (long)K};
    int   rb[4] = {row0, row0, col0, col0};

#pragma unroll
    for (int a = 0; a < 4; a++) {
        uint32_t sdst = sb + a * TILE_BYTES;
        const __nv_bfloat16* g = gp[a];
#pragma unroll
        for (int j = 0; j < 2; j++)
            cp16(sdst + doff[j], g + (long)(rb[a] + rr[j]) * st[a] + cc[j] * 8);
    }
    CP_COMMIT();

    float acc[2][4][4];
#pragma unroll
    for (int mf = 0; mf < 2; mf++)
#pragma unroll
        for (int nf = 0; nf < 4; nf++)
#pragma unroll
            for (int e = 0; e < 4; e++) acc[mf][nf][e] = 0.f;

    int a_r = warp_m * 32 + (lane & 7) + ((lane & 8) ? 8 : 0);
    int a_usel = (lane & 16) ? 1 : 0;
    int b_rbase = warp_n * 32 + (lane & 7) + ((lane & 16) ? 8 : 0);
    int b_usel = (lane & 8) ? 1 : 0;

    for (int kc = 0; kc < NKITER; kc++) {
        if (kc + 1 < NKITER) {
            uint32_t sstage = sb + ((kc + 1) & 1) * STAGE_BYTES;
            int k0 = (kc + 1) * 64;
#pragma unroll
            for (int a = 0; a < 4; a++) {
                uint32_t sdst = sstage + a * TILE_BYTES;
                const __nv_bfloat16* g = gp[a];
#pragma unroll
                for (int j = 0; j < 2; j++)
                    cp16(sdst + doff[j],
                         g + (long)(rb[a] + rr[j]) * st[a] + k0 + cc[j] * 8);
            }
            CP_COMMIT();
            CP_WAIT1();
        } else {
            CP_WAIT0();
        }
        __syncthreads();

        uint32_t s = sb + (kc & 1) * STAGE_BYTES;
        uint32_t sAhi = s, sAlo = s + TILE_BYTES;
        uint32_t sBhi = s + 2 * TILE_BYTES, sBlo = s + 3 * TILE_BYTES;

#pragma unroll
        for (int ks = 0; ks < 4; ks++) {
            uint32_t ah[2][4], al[2][4];
#pragma unroll
            for (int mf = 0; mf < 2; mf++) {
                int r = a_r + mf * 16;
                int u = ks * 2 + a_usel;
                uint32_t off = (uint32_t)(((r << 3) + (u ^ (r & 7))) << 4);
                ldm4(ah[mf], sAhi + off);
                ldm4(al[mf], sAlo + off);
            }
            uint32_t bh[2][4], bl[2][4];
#pragma unroll
            for (int np = 0; np < 2; np++) {
                int r = b_rbase + np * 16;
                int u = ks * 2 + b_usel;
                uint32_t off = (uint32_t)(((r << 3) + (u ^ (r & 7))) << 4);
                ldm4(bh[np], sBhi + off);
                ldm4(bl[np], sBlo + off);
            }
#pragma unroll
            for (int mf = 0; mf < 2; mf++)
#pragma unroll
                for (int nf = 0; nf < 4; nf++) {
                    int np = nf >> 1;
                    int half = (nf & 1) * 2;
                    uint32_t bh0 = bh[np][half], bh1 = bh[np][half + 1];
                    uint32_t bl0 = bl[np][half], bl1 = bl[np][half + 1];
                    mma_bf16(acc[mf][nf], ah[mf], bh0, bh1);
                    mma_bf16(acc[mf][nf], ah[mf], bl0, bl1);
                    mma_bf16(acc[mf][nf], al[mf], bh0, bh1);
                }
        }
        __syncthreads();
    }

#pragma unroll
    for (int mf = 0; mf < 2; mf++) {
        int m = row0 + warp_m * 32 + mf * 16 + (lane >> 2);
#pragma unroll
        for (int nf = 0; nf < 4; nf++) {
            int n = col0 + warp_n * 32 + nf * 8 + (lane & 3) * 2;
            if (n < Nstore) {
                float2 v0, v1;
                v0.x = acc[mf][nf][0]; v0.y = acc[mf][nf][1];
                v1.x = acc[mf][nf][2]; v1.y = acc[mf][nf][3];
                if (bias) {
                    float bx = bias[n], by = bias[n + 1];
                    v0.x += bx; v0.y += by;
                    v1.x += bx; v1.y += by;
                }
                *(float2*)(C + (long)m * ldc + n)       = v0;
                *(float2*)(C + (long)(m + 8) * ldc + n) = v1;
            }
        }
    }
}

#define KV_BLOCKS 648
__global__ __launch_bounds__(512, 1)
void gemm_merged_kernel()
{
    extern __shared__ char smem[];
    int bid = blockIdx.x;
    if (bid < KV_BLOCKS) {
        int bx = bid % 12, by = bid / 12;
        gemm_body(g_xhi, g_xlo, C_, g_wkvT_hi, g_wkvT_lo, nullptr,
                  g_kv, CKV_, CKV_, C_, by * 128, bx * 128, smem);
    } else {
        int b2 = bid - KV_BLOCKS;
        int bx = b2 % 8, by = b2 / 8;
        gemm_body(g_xhi + C_, g_xlo + C_, (long)T_ * C_,
                  g_wqoffT_hi, g_wqoffT_lo, g_bias_qoff,
                  g_qoff, NQOFF_, 768 + NOFF_, C_, by * 128, bx * 128, smem);
    }
}

__global__ __launch_bounds__(512, 1)
void gemm_proj_kernel(const float* __restrict__ bias, float* __restrict__ C)
{
    extern __shared__ char smem[];
    gemm_body(g_ahi, g_alo, C_, g_wprojT_hi, g_wprojT_lo, bias,
              C, C_, C_, C_, blockIdx.y * 128, blockIdx.x * 128, smem);
}

// ---------------- deformable attention core --------------------------------------
// grid=(B*N, T), 384 threads = 12 warps (warp h = head h).
// Lanes 0-15 sample K (float4, channels 4*lane..), lanes 16-31 sample V.
// Online softmax: no per-point arrays. 32-bit addressing into g_kv.
__global__ __launch_bounds__(384, 3) void attn_kernel(
    const float* __restrict__ mask,
    const float* __restrict__ suppress_p)
{
    int bn = blockIdx.x;
    int t  = blockIdx.y;
    int b  = bn / N_;
    int n  = bn % N_;
    int h    = threadIdx.x >> 5;
    int lane = threadIdx.x & 31;
    int part = lane >> 4;            // 0 = K half, 1 = V half
    int ch   = (lane & 15) * 4;

    float suppress = *suppress_p;
    float mk  = mask[bn];
    float sw  = 1.f - suppress * mk;
    float moff = suppress * mk * 0.1f;

    float refx = (float)(n % HP_) * (2.f / 23.f) - 1.f;
    float refy = (float)(n / HP_) * (2.f / 23.f) - 1.f;

    const float* rowbase = g_qoff + bn * NQOFF_;
    float4 q4 = *(const float4*)(rowbase + h * DH_ + ch);  // K-lanes use this

    // broadcast this head's 18 offsets
    const float* offrow = rowbase + 768 + h * (P_ * 2);
    float offv = (lane < P_ * 2) ? offrow[lane] : 0.f;

    // per-lane constant part of the g_kv index (32-bit)
    int base_part = h * DH_ + part * C_ + ch;
    int tstride_base = b * N_;        // pixel row base within batch

    float m = -1e30f, ssum = 0.f;
    float4 o4 = make_float4(0.f, 0.f, 0.f, 0.f);

#pragma unroll
    for (int p = 0; p < P_; p++) {
        float ox = __shfl_sync(0xffffffffu, offv, 2 * p)     - moff;
        float oy = __shfl_sync(0xffffffffu, offv, 2 * p + 1) - moff;
        float xs = (refx + ox + 1.f) * 11.5f;
        float ys = (refy + oy + 1.f) * 11.5f;
        float x0f = floorf(xs), y0f = floorf(ys);
        int   x0 = (int)x0f,  y0 = (int)y0f;
        float wx1 = xs - x0f, wy1 = ys - y0f;
        float wx0 = 1.f - wx1, wy0 = 1.f - wy1;

        float4 acc4 = make_float4(0.f, 0.f, 0.f, 0.f);
#pragma unroll
        for (int c = 0; c < 4; c++) {
            int dx = c & 1, dy = c >> 1;
            int ix = x0 + dx, iy = y0 + dy;
            float valid = (ix >= 0 && ix < HP_ && iy >= 0 && iy < HP_) ? 1.f : 0.f;
            float w = (dx ? wx1 : wx0) * (dy ? wy1 : wy0) * valid;
            int ixc = min(max(ix, 0), HP_ - 1);
            int iyc = min(max(iy, 0), HP_ - 1);
            int idx = ((tstride_base + iyc * HP_ + ixc) * T_ + t) * CKV_ + base_part;
            float4 kv = *(const float4*)(g_kv + idx);
            acc4.x = fmaf(w, kv.x, acc4.x);
            acc4.y = fmaf(w, kv.y, acc4.y);
            acc4.z = fmaf(w, kv.z, acc4.z);
            acc4.w = fmaf(w, kv.w, acc4.w);
        }
        // K-half: dot(q, k_sample); reduce within the 16-lane half
        float dot = q4.x * acc4.x + q4.y * acc4.y + q4.z * acc4.z + q4.w * acc4.w;
#pragma unroll
        for (int s = 8; s > 0; s >>= 1)
            dot += __shfl_xor_sync(0xffffffffu, dot, s);
        float l = __shfl_sync(0xffffffffu, dot, 0) * SCALE_ * sw;

        // online softmax update (all lanes identical l; V-lanes carry o4)
        float mn = fmaxf(m, l);
        float c1 = __expf(m - mn);
        float c2 = __expf(l - mn);
        ssum = ssum * c1 + c2;
        o4.x = o4.x * c1 + c2 * acc4.x;
        o4.y = o4.y * c1 + c2 * acc4.y;
        o4.z = o4.z * c1 + c2 * acc4.z;
        o4.w = o4.w * c1 + c2 * acc4.w;
        m = mn;
    }

    if (part == 1) {
        float inv = 1.f / ssum;
        float4 r = make_float4(o4.x * inv, o4.y * inv, o4.z * inv, o4.w * inv);
        *(float4*)(g_attn + ((long)t * BN_ + bn) * C_ + h * DH_ + ch) = r;
    }
}

// ---------------- launch ----------------------------------------------------------
extern "C" void kernel_launch(void* const* d_in, const int* in_sizes, int n_in,
                              void* d_out, int out_size)
{
    const float* x     = (const float*)d_in[0];
    const float* mask  = (const float*)d_in[1];
    const float* Wq    = (const float*)d_in[2];
    const float* Wk    = (const float*)d_in[3];
    const float* Wv    = (const float*)d_in[4];
    const float* Woff  = (const float*)d_in[5];
    const float* boff  = (const float*)d_in[6];
    const float* Wproj = (const float*)d_in[7];
    const float* bproj = (const float*)d_in[8];
    const float* suppr = (const float*)d_in[9];
    float* out = (float*)d_out;

    cudaFuncSetAttribute(gemm_merged_kernel,
                         cudaFuncAttributeMaxDynamicSharedMemorySize, SMEM_TOTAL);
    cudaFuncSetAttribute(gemm_proj_kernel,
                         cudaFuncAttributeMaxDynamicSharedMemorySize, SMEM_TOTAL);

    split_x_kernel<<<(MKV_ * C_ / 4 + 255) / 256, 256>>>(x);
    tpose_split_all_kernel<<<dim3(C_ / 32, C_ / 32, 5), dim3(32, 8)>>>(
        Wq, Wk, Wv, Wproj, Woff, boff);

    gemm_merged_kernel<<<KV_BLOCKS + 144, 512, SMEM_TOTAL>>>();

    {
        dim3 grid(BN_, T_);
        attn_kernel<<<grid, 384>>>(mask, suppr);
    }

    sum3_split_kernel<<<(BN_ * C_ / 4 + 255) / 256, 256>>>();
    gemm_proj_kernel<<<dim3(C_ / 128, BN_ / 128), 512, SMEM_TOTAL>>>(bproj, out);
}

// round 8
// speedup vs baseline: 3.3640x; 1.0917x over previous
#include <cuda_runtime.h>
#include <cuda_bf16.h>
#include <cstdint>
#include <math.h>

#define B_  4
#define N_  576
#define T_  3
#define C_  768
#define H_  12
#define P_  9
#define DH_ 64
#define HP_ 24
#define SCALE_ 0.125f
#define BN_ (B_ * N_)
#define CKV_ (2 * C_)       // 1536
#define MKV_ (BN_ * T_)     // 6912
#define NOFF_ (H_ * P_ * 2) // 216
#define NQOFF_ 1024         // 768 (q) + 256 (off padded)

// ---------------- scratch (device globals) -----------------------------------
__device__ __nv_bfloat16 g_xhi[MKV_ * C_];
__device__ __nv_bfloat16 g_xlo[MKV_ * C_];
__device__ __nv_bfloat16 g_wkvT_hi[CKV_ * C_];    // [n][k]; n<768: Wk, else Wv
__device__ __nv_bfloat16 g_wkvT_lo[CKV_ * C_];
__device__ __nv_bfloat16 g_wqoffT_hi[NQOFF_ * C_]; // rows 0-767 Wq^T, 768+ Woff^T
__device__ __nv_bfloat16 g_wqoffT_lo[NQOFF_ * C_];
__device__ __nv_bfloat16 g_wprojT_hi[C_ * C_];
__device__ __nv_bfloat16 g_wprojT_lo[C_ * C_];
__device__ __nv_bfloat16 g_ahi[BN_ * C_];
__device__ __nv_bfloat16 g_alo[BN_ * C_];
__device__ float g_bias_qoff[NQOFF_];

__device__ float g_kv[MKV_ * CKV_];
__device__ float g_qoff[BN_ * NQOFF_];   // per row: q[768] | off[216] | pad

// ---------------- PTX helpers ---------------------------------------------------
__device__ __forceinline__ uint32_t smem_to_u32(const void* p) {
    uint32_t a;
    asm("{ .reg .u64 t; cvta.to.shared.u64 t, %1; cvt.u32.u64 %0, t; }"
        : "=r"(a) : "l"(p));
    return a;
}
__device__ __forceinline__ void cp16(uint32_t dst, const void* src) {
    asm volatile("cp.async.cg.shared.global [%0], [%1], 16;"
                 :: "r"(dst), "l"(src));
}
#define CP_COMMIT() asm volatile("cp.async.commit_group;" ::: "memory")
#define CP_WAIT0()  asm volatile("cp.async.wait_group 0;" ::: "memory")
#define CP_WAIT1()  asm volatile("cp.async.wait_group 1;" ::: "memory")

__device__ __forceinline__ void ldm4(uint32_t* r, uint32_t addr) {
    asm volatile("ldmatrix.sync.aligned.m8n8.x4.shared.b16 {%0,%1,%2,%3}, [%4];"
                 : "=r"(r[0]), "=r"(r[1]), "=r"(r[2]), "=r"(r[3]) : "r"(addr));
}
__device__ __forceinline__ void mma_bf16(float* c, const uint32_t* a,
                                         uint32_t b0, uint32_t b1) {
    asm volatile(
        "mma.sync.aligned.m16n8k16.row.col.f32.bf16.bf16.f32 "
        "{%0,%1,%2,%3}, {%4,%5,%6,%7}, {%8,%9}, {%0,%1,%2,%3};"
        : "+f"(c[0]), "+f"(c[1]), "+f"(c[2]), "+f"(c[3])
        : "r"(a[0]), "r"(a[1]), "r"(a[2]), "r"(a[3]), "r"(b0), "r"(b1));
}

// ---------------- prep kernels ---------------------------------------------------
__device__ __forceinline__ void split_bf(float v, __nv_bfloat16& hi, __nv_bfloat16& lo) {
    hi = __float2bfloat16(v);
    lo = __float2bfloat16(v - __bfloat162float(hi));
}

__global__ void split_x_kernel(const float* __restrict__ x) {
    int idx = blockIdx.x * blockDim.x + threadIdx.x;
    if (idx >= MKV_ * C_ / 4) return;
    float4 v = ((const float4*)x)[idx];
    __nv_bfloat16 h0, l0, h1, l1, h2, l2, h3, l3;
    split_bf(v.x, h0, l0); split_bf(v.y, h1, l1);
    split_bf(v.z, h2, l2); split_bf(v.w, h3, l3);
    ((__nv_bfloat162*)g_xhi)[idx * 2]     = __nv_bfloat162(h0, h1);
    ((__nv_bfloat162*)g_xhi)[idx * 2 + 1] = __nv_bfloat162(h2, h3);
    ((__nv_bfloat162*)g_xlo)[idx * 2]     = __nv_bfloat162(l0, l1);
    ((__nv_bfloat162*)g_xlo)[idx * 2 + 1] = __nv_bfloat162(l2, l3);
}

// Fused transpose+split of all weights; blockIdx.z selects matrix.
__global__ void tpose_split_all_kernel(
    const float* __restrict__ Wq, const float* __restrict__ Wk,
    const float* __restrict__ Wv, const float* __restrict__ Wproj,
    const float* __restrict__ Woff, const float* __restrict__ boff)
{
    if (blockIdx.z == 0 && blockIdx.x == 0 && blockIdx.y == 0) {
        int t = threadIdx.y * 32 + threadIdx.x;
        for (int i = t; i < NQOFF_; i += 256)
            g_bias_qoff[i] = (i >= 768 && i < 768 + NOFF_) ? boff[i - 768] : 0.f;
    }

    const float* src;
    __nv_bfloat16 *dhi, *dlo;
    int N, dstRows;
    switch (blockIdx.z) {
        case 0: src = Wq;    dhi = g_wqoffT_hi; dlo = g_wqoffT_lo; N = C_; dstRows = C_; break;
        case 1: src = Wk;    dhi = g_wkvT_hi;   dlo = g_wkvT_lo;   N = C_; dstRows = C_; break;
        case 2: src = Wv;    dhi = g_wkvT_hi + (long)C_ * C_;
                             dlo = g_wkvT_lo + (long)C_ * C_;      N = C_; dstRows = C_; break;
        case 3: src = Wproj; dhi = g_wprojT_hi; dlo = g_wprojT_lo; N = C_; dstRows = C_; break;
        default: src = Woff; dhi = g_wqoffT_hi + (long)768 * C_;
                             dlo = g_wqoffT_lo + (long)768 * C_;   N = NOFF_; dstRows = 256; break;
    }
    int n0 = blockIdx.x * 32, k0 = blockIdx.y * 32;
    if (n0 >= dstRows) return;

    __shared__ float tile[32][33];
    int tx = threadIdx.x, ty = threadIdx.y;
#pragma unroll
    for (int j = 0; j < 4; j++) {
        int k = k0 + ty + j * 8, n = n0 + tx;
        tile[ty + j * 8][tx] = (n < N) ? src[(long)k * N + n] : 0.f;
    }
    __syncthreads();
#pragma unroll
    for (int j = 0; j < 4; j++) {
        int n = n0 + ty + j * 8, k = k0 + tx;
        if (n < dstRows) {
            __nv_bfloat16 hi, lo;
            split_bf(tile[tx][ty + j * 8], hi, lo);
            dhi[(long)n * C_ + k] = hi;
            dlo[(long)n * C_ + k] = lo;
        }
    }
}

// ---------------- mma.sync bf16x3 GEMM body (512 threads, 16 warps) --------------
#define TILE_BYTES 16384              // 128 x 64 bf16
#define STAGE_BYTES (4 * TILE_BYTES)
#define SMEM_TOTAL (2 * STAGE_BYTES)  // 131072

__device__ __forceinline__ void gemm_body(
    const __nv_bfloat16* __restrict__ Ahi,
    const __nv_bfloat16* __restrict__ Alo, long lda,
    const __nv_bfloat16* __restrict__ Bhi,
    const __nv_bfloat16* __restrict__ Blo,
    const float* __restrict__ bias,
    float* __restrict__ C, int ldc, int Nstore, int K,
    int row0, int col0, char* smem)
{
    uint32_t sb = smem_to_u32(smem);
    int tid = threadIdx.x;
    int wid = tid >> 5, lane = tid & 31;
    int warp_m = wid & 3;
    int warp_n = wid >> 2;
    const int NKITER = K / 64;

    int rr[2], cc[2], doff[2];
#pragma unroll
    for (int j = 0; j < 2; j++) {
        int u = tid + j * 512;
        int r = u >> 3, cu = u & 7;
        rr[j] = r; cc[j] = cu;
        doff[j] = ((r << 3) + (cu ^ (r & 7))) << 4;
    }

    const __nv_bfloat16* gp[4] = {Ahi, Alo, Bhi, Blo};
    long  st[4] = {lda, lda, (long)K, (long)K};
    int   rb[4] = {row0, row0, col0, col0};

#pragma unroll
    for (int a = 0; a < 4; a++) {
        uint32_t sdst = sb + a * TILE_BYTES;
        const __nv_bfloat16* g = gp[a];
#pragma unroll
        for (int j = 0; j < 2; j++)
            cp16(sdst + doff[j], g + (long)(rb[a] + rr[j]) * st[a] + cc[j] * 8);
    }
    CP_COMMIT();

    float acc[2][4][4];
#pragma unroll
    for (int mf = 0; mf < 2; mf++)
#pragma unroll
        for (int nf = 0; nf < 4; nf++)
#pragma unroll
            for (int e = 0; e < 4; e++) acc[mf][nf][e] = 0.f;

    int a_r = warp_m * 32 + (lane & 7) + ((lane & 8) ? 8 : 0);
    int a_usel = (lane & 16) ? 1 : 0;
    int b_rbase = warp_n * 32 + (lane & 7) + ((lane & 16) ? 8 : 0);
    int b_usel = (lane & 8) ? 1 : 0;

    for (int kc = 0; kc < NKITER; kc++) {
        if (kc + 1 < NKITER) {
            uint32_t sstage = sb + ((kc + 1) & 1) * STAGE_BYTES;
            int k0 = (kc + 1) * 64;
#pragma unroll
            for (int a = 0; a < 4; a++) {
                uint32_t sdst = sstage + a * TILE_BYTES;
                const __nv_bfloat16* g = gp[a];
#pragma unroll
                for (int j = 0; j < 2; j++)
                    cp16(sdst + doff[j],
                         g + (long)(rb[a] + rr[j]) * st[a] + k0 + cc[j] * 8);
            }
            CP_COMMIT();
            CP_WAIT1();
        } else {
            CP_WAIT0();
        }
        __syncthreads();

        uint32_t s = sb + (kc & 1) * STAGE_BYTES;
        uint32_t sAhi = s, sAlo = s + TILE_BYTES;
        uint32_t sBhi = s + 2 * TILE_BYTES, sBlo = s + 3 * TILE_BYTES;

#pragma unroll
        for (int ks = 0; ks < 4; ks++) {
            uint32_t ah[2][4], al[2][4];
#pragma unroll
            for (int mf = 0; mf < 2; mf++) {
                int r = a_r + mf * 16;
                int u = ks * 2 + a_usel;
                uint32_t off = (uint32_t)(((r << 3) + (u ^ (r & 7))) << 4);
                ldm4(ah[mf], sAhi + off);
                ldm4(al[mf], sAlo + off);
            }
            uint32_t bh[2][4], bl[2][4];
#pragma unroll
            for (int np = 0; np < 2; np++) {
                int r = b_rbase + np * 16;
                int u = ks * 2 + b_usel;
                uint32_t off = (uint32_t)(((r << 3) + (u ^ (r & 7))) << 4);
                ldm4(bh[np], sBhi + off);
                ldm4(bl[np], sBlo + off);
            }
#pragma unroll
            for (int mf = 0; mf < 2; mf++)
#pragma unroll
                for (int nf = 0; nf < 4; nf++) {
                    int np = nf >> 1;
                    int half = (nf & 1) * 2;
                    uint32_t bh0 = bh[np][half], bh1 = bh[np][half + 1];
                    uint32_t bl0 = bl[np][half], bl1 = bl[np][half + 1];
                    mma_bf16(acc[mf][nf], ah[mf], bh0, bh1);
                    mma_bf16(acc[mf][nf], ah[mf], bl0, bl1);
                    mma_bf16(acc[mf][nf], al[mf], bh0, bh1);
                }
        }
        __syncthreads();
    }

#pragma unroll
    for (int mf = 0; mf < 2; mf++) {
        int m = row0 + warp_m * 32 + mf * 16 + (lane >> 2);
#pragma unroll
        for (int nf = 0; nf < 4; nf++) {
            int n = col0 + warp_n * 32 + nf * 8 + (lane & 3) * 2;
            if (n < Nstore) {
                float2 v0, v1;
                v0.x = acc[mf][nf][0]; v0.y = acc[mf][nf][1];
                v1.x = acc[mf][nf][2]; v1.y = acc[mf][nf][3];
                if (bias) {
                    float bx = bias[n], by = bias[n + 1];
                    v0.x += bx; v0.y += by;
                    v1.x += bx; v1.y += by;
                }
                *(float2*)(C + (long)m * ldc + n)       = v0;
                *(float2*)(C + (long)(m + 8) * ldc + n) = v1;
            }
        }
    }
}

#define KV_BLOCKS 648
__global__ __launch_bounds__(512, 1)
void gemm_merged_kernel()
{
    extern __shared__ char smem[];
    int bid = blockIdx.x;
    if (bid < KV_BLOCKS) {
        int bx = bid % 12, by = bid / 12;
        gemm_body(g_xhi, g_xlo, C_, g_wkvT_hi, g_wkvT_lo, nullptr,
                  g_kv, CKV_, CKV_, C_, by * 128, bx * 128, smem);
    } else {
        int b2 = bid - KV_BLOCKS;
        int bx = b2 % 8, by = b2 / 8;
        gemm_body(g_xhi + C_, g_xlo + C_, (long)T_ * C_,
                  g_wqoffT_hi, g_wqoffT_lo, g_bias_qoff,
                  g_qoff, NQOFF_, 768 + NOFF_, C_, by * 128, bx * 128, smem);
    }
}

__global__ __launch_bounds__(512, 1)
void gemm_proj_kernel(const float* __restrict__ bias, float* __restrict__ C)
{
    extern __shared__ char smem[];
    gemm_body(g_ahi, g_alo, C_, g_wprojT_hi, g_wprojT_lo, bias,
              C, C_, C_, C_, blockIdx.y * 128, blockIdx.x * 128, smem);
}

// ---------------- deformable attention core --------------------------------------
// grid = B*N blocks, 384 threads = 12 warps (warp h = head h).
// Lanes 0-15 sample K (float4 channels), lanes 16-31 sample V.
// t-loop INSIDE: sample addresses/weights computed once, 3 t-slices loaded at
// immediate offsets. Per-t online softmax; t-average + bf16 split fused here.
__global__ __launch_bounds__(384, 2) void attn_kernel(
    const float* __restrict__ mask,
    const float* __restrict__ suppress_p)
{
    int bn = blockIdx.x;
    int b  = bn / N_;
    int n  = bn % N_;
    int h    = threadIdx.x >> 5;
    int lane = threadIdx.x & 31;
    int part = lane >> 4;            // 0 = K half, 1 = V half
    int ch   = (lane & 15) * 4;

    float suppress = *suppress_p;
    float mk  = mask[bn];
    float sw  = 1.f - suppress * mk;
    float moff = suppress * mk * 0.1f;

    float refx = (float)(n % HP_) * (2.f / 23.f) - 1.f;
    float refy = (float)(n / HP_) * (2.f / 23.f) - 1.f;

    const float* rowbase = g_qoff + bn * NQOFF_;
    float4 q4 = *(const float4*)(rowbase + h * DH_ + ch);

    const float* offrow = rowbase + 768 + h * (P_ * 2);
    float offv = (lane < P_ * 2) ? offrow[lane] : 0.f;

    int base_part = h * DH_ + part * C_ + ch;
    int pixbase = b * N_;

    float m0 = -1e30f, m1 = -1e30f, m2 = -1e30f;
    float s0 = 0.f, s1 = 0.f, s2 = 0.f;
    float4 o0 = make_float4(0.f, 0.f, 0.f, 0.f);
    float4 o1 = make_float4(0.f, 0.f, 0.f, 0.f);
    float4 o2 = make_float4(0.f, 0.f, 0.f, 0.f);

#pragma unroll
    for (int p = 0; p < P_; p++) {
        float ox = __shfl_sync(0xffffffffu, offv, 2 * p)     - moff;
        float oy = __shfl_sync(0xffffffffu, offv, 2 * p + 1) - moff;
        float xs = (refx + ox + 1.f) * 11.5f;
        float ys = (refy + oy + 1.f) * 11.5f;
        float x0f = floorf(xs), y0f = floorf(ys);
        int   x0 = (int)x0f,  y0 = (int)y0f;
        float wx1 = xs - x0f, wy1 = ys - y0f;
        float wx0 = 1.f - wx1, wy0 = 1.f - wy1;

        float4 a0 = make_float4(0.f, 0.f, 0.f, 0.f);
        float4 a1 = make_float4(0.f, 0.f, 0.f, 0.f);
        float4 a2 = make_float4(0.f, 0.f, 0.f, 0.f);
#pragma unroll
        for (int c = 0; c < 4; c++) {
            int dx = c & 1, dy = c >> 1;
            int ix = x0 + dx, iy = y0 + dy;
            float valid = (ix >= 0 && ix < HP_ && iy >= 0 && iy < HP_) ? 1.f : 0.f;
            float w = (dx ? wx1 : wx0) * (dy ? wy1 : wy0) * valid;
            int ixc = min(max(ix, 0), HP_ - 1);
            int iyc = min(max(iy, 0), HP_ - 1);
            int idx = (pixbase + iyc * HP_ + ixc) * (T_ * CKV_) + base_part;
            float4 kv0 = *(const float4*)(g_kv + idx);
            float4 kv1 = *(const float4*)(g_kv + idx + CKV_);
            float4 kv2 = *(const float4*)(g_kv + idx + 2 * CKV_);
            a0.x = fmaf(w, kv0.x, a0.x); a0.y = fmaf(w, kv0.y, a0.y);
            a0.z = fmaf(w, kv0.z, a0.z); a0.w = fmaf(w, kv0.w, a0.w);
            a1.x = fmaf(w, kv1.x, a1.x); a1.y = fmaf(w, kv1.y, a1.y);
            a1.z = fmaf(w, kv1.z, a1.z); a1.w = fmaf(w, kv1.w, a1.w);
            a2.x = fmaf(w, kv2.x, a2.x); a2.y = fmaf(w, kv2.y, a2.y);
            a2.z = fmaf(w, kv2.z, a2.z); a2.w = fmaf(w, kv2.w, a2.w);
        }
        // dots (K half produces the valid value; broadcast from lane 0)
        float d0 = q4.x * a0.x + q4.y * a0.y + q4.z * a0.z + q4.w * a0.w;
        float d1 = q4.x * a1.x + q4.y * a1.y + q4.z * a1.z + q4.w * a1.w;
        float d2 = q4.x * a2.x + q4.y * a2.y + q4.z * a2.z + q4.w * a2.w;
#pragma unroll
        for (int s = 8; s > 0; s >>= 1) {
            d0 += __shfl_xor_sync(0xffffffffu, d0, s);
            d1 += __shfl_xor_sync(0xffffffffu, d1, s);
            d2 += __shfl_xor_sync(0xffffffffu, d2, s);
        }
        float l0 = __shfl_sync(0xffffffffu, d0, 0) * SCALE_ * sw;
        float l1 = __shfl_sync(0xffffffffu, d1, 0) * SCALE_ * sw;
        float l2 = __shfl_sync(0xffffffffu, d2, 0) * SCALE_ * sw;

        // online softmax per t
        {
            float mn = fmaxf(m0, l0);
            float c1 = __expf(m0 - mn), c2 = __expf(l0 - mn);
            s0 = s0 * c1 + c2;
            o0.x = o0.x * c1 + c2 * a0.x; o0.y = o0.y * c1 + c2 * a0.y;
            o0.z = o0.z * c1 + c2 * a0.z; o0.w = o0.w * c1 + c2 * a0.w;
            m0 = mn;
        }
        {
            float mn = fmaxf(m1, l1);
            float c1 = __expf(m1 - mn), c2 = __expf(l1 - mn);
            s1 = s1 * c1 + c2;
            o1.x = o1.x * c1 + c2 * a1.x; o1.y = o1.y * c1 + c2 * a1.y;
            o1.z = o1.z * c1 + c2 * a1.z; o1.w = o1.w * c1 + c2 * a1.w;
            m1 = mn;
        }
        {
            float mn = fmaxf(m2, l2);
            float c1 = __expf(m2 - mn), c2 = __expf(l2 - mn);
            s2 = s2 * c1 + c2;
            o2.x = o2.x * c1 + c2 * a2.x; o2.y = o2.y * c1 + c2 * a2.y;
            o2.z = o2.z * c1 + c2 * a2.z; o2.w = o2.w * c1 + c2 * a2.w;
            m2 = mn;
        }
    }

    if (part == 1) {
        const float third = 1.0f / 3.0f;
        float i0 = third / s0, i1 = third / s1, i2 = third / s2;
        float rx = o0.x * i0 + o1.x * i1 + o2.x * i2;
        float ry = o0.y * i0 + o1.y * i1 + o2.y * i2;
        float rz = o0.z * i0 + o1.z * i1 + o2.z * i2;
        float rw = o0.w * i0 + o1.w * i1 + o2.w * i2;

        __nv_bfloat16 hx, lx, hy, ly, hz, lz, hw, lw;
        split_bf(rx, hx, lx); split_bf(ry, hy, ly);
        split_bf(rz, hz, lz); split_bf(rw, hw, lw);
        int oidx = bn * C_ + h * DH_ + ch;
        __nv_bfloat162 hi01(hx, hy), hi23(hz, hw);
        __nv_bfloat162 lo01(lx, ly), lo23(lz, lw);
        uint2 hpack, lpack;
        hpack.x = *(uint32_t*)&hi01; hpack.y = *(uint32_t*)&hi23;
        lpack.x = *(uint32_t*)&lo01; lpack.y = *(uint32_t*)&lo23;
        *(uint2*)(g_ahi + oidx) = hpack;
        *(uint2*)(g_alo + oidx) = lpack;
    }
}

// ---------------- launch ----------------------------------------------------------
extern "C" void kernel_launch(void* const* d_in, const int* in_sizes, int n_in,
                              void* d_out, int out_size)
{
    const float* x     = (const float*)d_in[0];
    const float* mask  = (const float*)d_in[1];
    const float* Wq    = (const float*)d_in[2];
    const float* Wk    = (const float*)d_in[3];
    const float* Wv    = (const float*)d_in[4];
    const float* Woff  = (const float*)d_in[5];
    const float* boff  = (const float*)d_in[6];
    const float* Wproj = (const float*)d_in[7];
    const float* bproj = (const float*)d_in[8];
    const float* suppr = (const float*)d_in[9];
    float* out = (float*)d_out;

    cudaFuncSetAttribute(gemm_merged_kernel,
                         cudaFuncAttributeMaxDynamicSharedMemorySize, SMEM_TOTAL);
    cudaFuncSetAttribute(gemm_proj_kernel,
                         cudaFuncAttributeMaxDynamicSharedMemorySize, SMEM_TOTAL);

    split_x_kernel<<<(MKV_ * C_ / 4 + 255) / 256, 256>>>(x);
    tpose_split_all_kernel<<<dim3(C_ / 32, C_ / 32, 5), dim3(32, 8)>>>(
        Wq, Wk, Wv, Wproj, Woff, boff);

    gemm_merged_kernel<<<KV_BLOCKS + 144, 512, SMEM_TOTAL>>>();

    attn_kernel<<<BN_, 384>>>(mask, suppr);

    gemm_proj_kernel<<<dim3(C_ / 128, BN_ / 128), 512, SMEM_TOTAL>>>(bproj, out);
}

// round 10
// speedup vs baseline: 3.8245x; 1.1369x over previous
#include <cuda_runtime.h>
#include <cuda_bf16.h>
#include <cuda_fp16.h>
#include <cstdint>
#include <math.h>

#define B_  4
#define N_  576
#define T_  3
#define C_  768
#define H_  12
#define P_  9
#define DH_ 64
#define HP_ 24
#define SCALE_ 0.125f
#define BN_ (B_ * N_)
#define CKV_ (2 * C_)       // 1536
#define MKV_ (BN_ * T_)     // 6912
#define NOFF_ (H_ * P_ * 2) // 216
#define NQOFF_ 1024         // 768 (q) + 256 (off padded)

// ---------------- scratch (device globals) -----------------------------------
// fp16 2-term path (KV GEMM only)
__device__ __half g_xhi[MKV_ * C_];
__device__ __half g_xlo[MKV_ * C_];
__device__ __half g_wkvT[CKV_ * C_];      // [n][k]; n<768: Wk, else Wv (fp16)
// bf16x3 path (Q/off + projection GEMMs)
__device__ __nv_bfloat16 g_qbf_hi[BN_ * C_];      // query rows (t=1), contiguous
__device__ __nv_bfloat16 g_qbf_lo[BN_ * C_];
__device__ __nv_bfloat16 g_wqoffT_hi[NQOFF_ * C_]; // rows 0-767 Wq^T, 768+ Woff^T
__device__ __nv_bfloat16 g_wqoffT_lo[NQOFF_ * C_];
__device__ __nv_bfloat16 g_wprojT_hi[C_ * C_];
__device__ __nv_bfloat16 g_wprojT_lo[C_ * C_];
__device__ __nv_bfloat16 g_ahi[BN_ * C_];
__device__ __nv_bfloat16 g_alo[BN_ * C_];
__device__ float g_bias_qoff[NQOFF_];

__device__ float g_kv[MKV_ * CKV_];
__device__ float g_qoff[BN_ * NQOFF_];   // per row: q[768] | off[216] | pad

// ---------------- PTX helpers ---------------------------------------------------
__device__ __forceinline__ uint32_t smem_to_u32(const void* p) {
    uint32_t a;
    asm("{ .reg .u64 t; cvta.to.shared.u64 t, %1; cvt.u32.u64 %0, t; }"
        : "=r"(a) : "l"(p));
    return a;
}
__device__ __forceinline__ void cp16(uint32_t dst, const void* src) {
    asm volatile("cp.async.cg.shared.global [%0], [%1], 16;"
                 :: "r"(dst), "l"(src));
}
#define CP_COMMIT() asm volatile("cp.async.commit_group;" ::: "memory")
#define CP_WAIT0()  asm volatile("cp.async.wait_group 0;" ::: "memory")
#define CP_WAIT1()  asm volatile("cp.async.wait_group 1;" ::: "memory")

__device__ __forceinline__ void ldm4(uint32_t* r, uint32_t addr) {
    asm volatile("ldmatrix.sync.aligned.m8n8.x4.shared.b16 {%0,%1,%2,%3}, [%4];"
                 : "=r"(r[0]), "=r"(r[1]), "=r"(r[2]), "=r"(r[3]) : "r"(addr));
}
__device__ __forceinline__ void mma_bf16(float* c, const uint32_t* a,
                                         uint32_t b0, uint32_t b1) {
    asm volatile(
        "mma.sync.aligned.m16n8k16.row.col.f32.bf16.bf16.f32 "
        "{%0,%1,%2,%3}, {%4,%5,%6,%7}, {%8,%9}, {%0,%1,%2,%3};"
        : "+f"(c[0]), "+f"(c[1]), "+f"(c[2]), "+f"(c[3])
        : "r"(a[0]), "r"(a[1]), "r"(a[2]), "r"(a[3]), "r"(b0), "r"(b1));
}
__device__ __forceinline__ void mma_fp16(float* c, const uint32_t* a,
                                         uint32_t b0, uint32_t b1) {
    asm volatile(
        "mma.sync.aligned.m16n8k16.row.col.f32.f16.f16.f32 "
        "{%0,%1,%2,%3}, {%4,%5,%6,%7}, {%8,%9}, {%0,%1,%2,%3};"
        : "+f"(c[0]), "+f"(c[1]), "+f"(c[2]), "+f"(c[3])
        : "r"(a[0]), "r"(a[1]), "r"(a[2]), "r"(a[3]), "r"(b0), "r"(b1));
}

// ---------------- prep kernels ---------------------------------------------------
__device__ __forceinline__ void split_bf(float v, __nv_bfloat16& hi, __nv_bfloat16& lo) {
    hi = __float2bfloat16(v);
    lo = __float2bfloat16(v - __bfloat162float(hi));
}
__device__ __forceinline__ void split_h(float v, __half& hi, __half& lo) {
    hi = __float2half_rn(v);
    lo = __float2half_rn(v - __half2float(hi));
}

__global__ void split_x_kernel(const float* __restrict__ x) {
    int idx = blockIdx.x * blockDim.x + threadIdx.x;
    if (idx >= MKV_ * C_ / 4) return;
    float4 v = ((const float4*)x)[idx];
    __half h0, l0, h1, l1, h2, l2, h3, l3;
    split_h(v.x, h0, l0); split_h(v.y, h1, l1);
    split_h(v.z, h2, l2); split_h(v.w, h3, l3);
    ((__half2*)g_xhi)[idx * 2]     = __halves2half2(h0, h1);
    ((__half2*)g_xhi)[idx * 2 + 1] = __halves2half2(h2, h3);
    ((__half2*)g_xlo)[idx * 2]     = __halves2half2(l0, l1);
    ((__half2*)g_xlo)[idx * 2 + 1] = __halves2half2(l2, l3);
}

// bf16 split of query rows (t = 1), stored contiguously [BN_, C_]
__global__ void split_q_kernel(const float* __restrict__ x) {
    int idx = blockIdx.x * blockDim.x + threadIdx.x;   // over BN_*C_/4
    if (idx >= BN_ * C_ / 4) return;
    int row = idx / (C_ / 4);
    int c4  = idx % (C_ / 4);
    float4 v = *(const float4*)(x + ((long)row * T_ + 1) * C_ + c4 * 4);
    __nv_bfloat16 h0, l0, h1, l1, h2, l2, h3, l3;
    split_bf(v.x, h0, l0); split_bf(v.y, h1, l1);
    split_bf(v.z, h2, l2); split_bf(v.w, h3, l3);
    ((__nv_bfloat162*)g_qbf_hi)[idx * 2]     = __nv_bfloat162(h0, h1);
    ((__nv_bfloat162*)g_qbf_hi)[idx * 2 + 1] = __nv_bfloat162(h2, h3);
    ((__nv_bfloat162*)g_qbf_lo)[idx * 2]     = __nv_bfloat162(l0, l1);
    ((__nv_bfloat162*)g_qbf_lo)[idx * 2 + 1] = __nv_bfloat162(l2, l3);
}

// Fused transpose of all weights; blockIdx.z selects matrix.
// Wk/Wv -> fp16; Wq/Woff/Wproj -> bf16 hi/lo.
__global__ void tpose_split_all_kernel(
    const float* __restrict__ Wq, const float* __restrict__ Wk,
    const float* __restrict__ Wv, const float* __restrict__ Wproj,
    const float* __restrict__ Woff, const float* __restrict__ boff)
{
    if (blockIdx.z == 0 && blockIdx.x == 0 && blockIdx.y == 0) {
        int t = threadIdx.y * 32 + threadIdx.x;
        for (int i = t; i < NQOFF_; i += 256)
            g_bias_qoff[i] = (i >= 768 && i < 768 + NOFF_) ? boff[i - 768] : 0.f;
    }

    const float* src;
    __half* dh = nullptr;
    __nv_bfloat16 *dhi = nullptr, *dlo = nullptr;
    int N, dstRows;
    switch (blockIdx.z) {
        case 0: src = Wq;    dhi = g_wqoffT_hi; dlo = g_wqoffT_lo; N = C_; dstRows = C_; break;
        case 1: src = Wk;    dh = g_wkvT;                 N = C_;   dstRows = C_;  break;
        case 2: src = Wv;    dh = g_wkvT + (long)C_ * C_; N = C_;   dstRows = C_;  break;
        case 3: src = Wproj; dhi = g_wprojT_hi; dlo = g_wprojT_lo; N = C_; dstRows = C_; break;
        default: src = Woff; dhi = g_wqoffT_hi + (long)768 * C_;
                             dlo = g_wqoffT_lo + (long)768 * C_;   N = NOFF_; dstRows = 256; break;
    }
    int n0 = blockIdx.x * 32, k0 = blockIdx.y * 32;
    if (n0 >= dstRows) return;

    __shared__ float tile[32][33];
    int tx = threadIdx.x, ty = threadIdx.y;
#pragma unroll
    for (int j = 0; j < 4; j++) {
        int k = k0 + ty + j * 8, n = n0 + tx;
        tile[ty + j * 8][tx] = (n < N) ? src[(long)k * N + n] : 0.f;
    }
    __syncthreads();
#pragma unroll
    for (int j = 0; j < 4; j++) {
        int n = n0 + ty + j * 8, k = k0 + tx;
        if (n < dstRows) {
            float v = tile[tx][ty + j * 8];
            if (dh) {
                dh[(long)n * C_ + k] = __float2half_rn(v);
            } else {
                __nv_bfloat16 hi, lo;
                split_bf(v, hi, lo);
                dhi[(long)n * C_ + k] = hi;
                dlo[(long)n * C_ + k] = lo;
            }
        }
    }
}

// ---------------- fp16 2-term GEMM body (512 threads, 16 warps) ------------------
#define FTILE 16384
#define FSTAGE (3 * FTILE)

__device__ __forceinline__ void gemm_fp16_body(
    const __half* __restrict__ Ahi,
    const __half* __restrict__ Alo, long lda,
    const __half* __restrict__ Bh,
    const float* __restrict__ bias,
    float* __restrict__ C, int ldc, int Nstore, int K,
    int row0, int col0, char* smem)
{
    uint32_t sb = smem_to_u32(smem);
    int tid = threadIdx.x;
    int wid = tid >> 5, lane = tid & 31;
    int warp_m = wid & 3;
    int warp_n = wid >> 2;
    const int NKITER = K / 64;

    int rr[2], cc[2], doff[2];
#pragma unroll
    for (int j = 0; j < 2; j++) {
        int u = tid + j * 512;
        int r = u >> 3, cu = u & 7;
        rr[j] = r; cc[j] = cu;
        doff[j] = ((r << 3) + (cu ^ (r & 7))) << 4;
    }

    const __half* gp[3] = {Ahi, Alo, Bh};
    long  st[3] = {lda, lda, (long)K};
    int   rb[3] = {row0, row0, col0};

#pragma unroll
    for (int a = 0; a < 3; a++) {
        uint32_t sdst = sb + a * FTILE;
        const __half* g = gp[a];
#pragma unroll
        for (int j = 0; j < 2; j++)
            cp16(sdst + doff[j], g + (long)(rb[a] + rr[j]) * st[a] + cc[j] * 8);
    }
    CP_COMMIT();

    float acc[2][4][4];
#pragma unroll
    for (int mf = 0; mf < 2; mf++)
#pragma unroll
        for (int nf = 0; nf < 4; nf++)
#pragma unroll
            for (int e = 0; e < 4; e++) acc[mf][nf][e] = 0.f;

    int a_r = warp_m * 32 + (lane & 7) + ((lane & 8) ? 8 : 0);
    int a_usel = (lane & 16) ? 1 : 0;
    int b_rbase = warp_n * 32 + (lane & 7) + ((lane & 16) ? 8 : 0);
    int b_usel = (lane & 8) ? 1 : 0;

    for (int kc = 0; kc < NKITER; kc++) {
        if (kc + 1 < NKITER) {
            uint32_t sstage = sb + ((kc + 1) & 1) * FSTAGE;
            int k0 = (kc + 1) * 64;
#pragma unroll
            for (int a = 0; a < 3; a++) {
                uint32_t sdst = sstage + a * FTILE;
                const __half* g = gp[a];
#pragma unroll
                for (int j = 0; j < 2; j++)
                    cp16(sdst + doff[j],
                         g + (long)(rb[a] + rr[j]) * st[a] + k0 + cc[j] * 8);
            }
            CP_COMMIT();
            CP_WAIT1();
        } else {
            CP_WAIT0();
        }
        __syncthreads();

        uint32_t s = sb + (kc & 1) * FSTAGE;
        uint32_t sAhi = s, sAlo = s + FTILE, sBh = s + 2 * FTILE;

#pragma unroll
        for (int ks = 0; ks < 4; ks++) {
            uint32_t ah[2][4], al[2][4];
#pragma unroll
            for (int mf = 0; mf < 2; mf++) {
                int r = a_r + mf * 16;
                int u = ks * 2 + a_usel;
                uint32_t off = (uint32_t)(((r << 3) + (u ^ (r & 7))) << 4);
                ldm4(ah[mf], sAhi + off);
                ldm4(al[mf], sAlo + off);
            }
            uint32_t bh[2][4];
#pragma unroll
            for (int np = 0; np < 2; np++) {
                int r = b_rbase + np * 16;
                int u = ks * 2 + b_usel;
                uint32_t off = (uint32_t)(((r << 3) + (u ^ (r & 7))) << 4);
                ldm4(bh[np], sBh + off);
            }
#pragma unroll
            for (int mf = 0; mf < 2; mf++)
#pragma unroll
                for (int nf = 0; nf < 4; nf++) {
                    int np = nf >> 1;
                    int half = (nf & 1) * 2;
                    uint32_t b0 = bh[np][half], b1 = bh[np][half + 1];
                    mma_fp16(acc[mf][nf], ah[mf], b0, b1);
                    mma_fp16(acc[mf][nf], al[mf], b0, b1);
                }
        }
        __syncthreads();
    }

#pragma unroll
    for (int mf = 0; mf < 2; mf++) {
        int m = row0 + warp_m * 32 + mf * 16 + (lane >> 2);
#pragma unroll
        for (int nf = 0; nf < 4; nf++) {
            int n = col0 + warp_n * 32 + nf * 8 + (lane & 3) * 2;
            if (n < Nstore) {
                float2 v0, v1;
                v0.x = acc[mf][nf][0]; v0.y = acc[mf][nf][1];
                v1.x = acc[mf][nf][2]; v1.y = acc[mf][nf][3];
                if (bias) {
                    float bx = bias[n], by = bias[n + 1];
                    v0.x += bx; v0.y += by;
                    v1.x += bx; v1.y += by;
                }
                *(float2*)(C + (long)m * ldc + n)       = v0;
                *(float2*)(C + (long)(m + 8) * ldc + n) = v1;
            }
        }
    }
}

// ---------------- bf16x3 GEMM body (Q/off + proj) --------------------------------
#define TILE_BYTES 16384
#define STAGE_BYTES (4 * TILE_BYTES)
#define SMEM_TOTAL (2 * STAGE_BYTES)  // 131072

__device__ __forceinline__ void gemm_body(
    const __nv_bfloat16* __restrict__ Ahi,
    const __nv_bfloat16* __restrict__ Alo, long lda,
    const __nv_bfloat16* __restrict__ Bhi,
    const __nv_bfloat16* __restrict__ Blo,
    const float* __restrict__ bias,
    float* __restrict__ C, int ldc, int Nstore, int K,
    int row0, int col0, char* smem)
{
    uint32_t sb = smem_to_u32(smem);
    int tid = threadIdx.x;
    int wid = tid >> 5, lane = tid & 31;
    int warp_m = wid & 3;
    int warp_n = wid >> 2;
    const int NKITER = K / 64;

    int rr[2], cc[2], doff[2];
#pragma unroll
    for (int j = 0; j < 2; j++) {
        int u = tid + j * 512;
        int r = u >> 3, cu = u & 7;
        rr[j] = r; cc[j] = cu;
        doff[j] = ((r << 3) + (cu ^ (r & 7))) << 4;
    }

    const __nv_bfloat16* gp[4] = {Ahi, Alo, Bhi, Blo};
    long  st[4] = {lda, lda, (long)K, (long)K};
    int   rb[4] = {row0, row0, col0, col0};

#pragma unroll
    for (int a = 0; a < 4; a++) {
        uint32_t sdst = sb + a * TILE_BYTES;
        const __nv_bfloat16* g = gp[a];
#pragma unroll
        for (int j = 0; j < 2; j++)
            cp16(sdst + doff[j], g + (long)(rb[a] + rr[j]) * st[a] + cc[j] * 8);
    }
    CP_COMMIT();

    float acc[2][4][4];
#pragma unroll
    for (int mf = 0; mf < 2; mf++)
#pragma unroll
        for (int nf = 0; nf < 4; nf++)
#pragma unroll
            for (int e = 0; e < 4; e++) acc[mf][nf][e] = 0.f;

    int a_r = warp_m * 32 + (lane & 7) + ((lane & 8) ? 8 : 0);
    int a_usel = (lane & 16) ? 1 : 0;
    int b_rbase = warp_n * 32 + (lane & 7) + ((lane & 16) ? 8 : 0);
    int b_usel = (lane & 8) ? 1 : 0;

    for (int kc = 0; kc < NKITER; kc++) {
        if (kc + 1 < NKITER) {
            uint32_t sstage = sb + ((kc + 1) & 1) * STAGE_BYTES;
            int k0 = (kc + 1) * 64;
#pragma unroll
            for (int a = 0; a < 4; a++) {
                uint32_t sdst = sstage + a * TILE_BYTES;
                const __nv_bfloat16* g = gp[a];
#pragma unroll
                for (int j = 0; j < 2; j++)
                    cp16(sdst + doff[j],
                         g + (long)(rb[a] + rr[j]) * st[a] + k0 + cc[j] * 8);
            }
            CP_COMMIT();
            CP_WAIT1();
        } else {
            CP_WAIT0();
        }
        __syncthreads();

        uint32_t s = sb + (kc & 1) * STAGE_BYTES;
        uint32_t sAhi = s, sAlo = s + TILE_BYTES;
        uint32_t sBhi = s + 2 * TILE_BYTES, sBlo = s + 3 * TILE_BYTES;

#pragma unroll
        for (int ks = 0; ks < 4; ks++) {
            uint32_t ah[2][4], al[2][4];
#pragma unroll
            for (int mf = 0; mf < 2; mf++) {
                int r = a_r + mf * 16;
                int u = ks * 2 + a_usel;
                uint32_t off = (uint32_t)(((r << 3) + (u ^ (r & 7))) << 4);
                ldm4(ah[mf], sAhi + off);
                ldm4(al[mf], sAlo + off);
            }
            uint32_t bh[2][4], bl[2][4];
#pragma unroll
            for (int np = 0; np < 2; np++) {
                int r = b_rbase + np * 16;
                int u = ks * 2 + b_usel;
                uint32_t off = (uint32_t)(((r << 3) + (u ^ (r & 7))) << 4);
                ldm4(bh[np], sBhi + off);
                ldm4(bl[np], sBlo + off);
            }
#pragma unroll
            for (int mf = 0; mf < 2; mf++)
#pragma unroll
                for (int nf = 0; nf < 4; nf++) {
                    int np = nf >> 1;
                    int half = (nf & 1) * 2;
                    uint32_t bh0 = bh[np][half], bh1 = bh[np][half + 1];
                    uint32_t bl0 = bl[np][half], bl1 = bl[np][half + 1];
                    mma_bf16(acc[mf][nf], ah[mf], bh0, bh1);
                    mma_bf16(acc[mf][nf], ah[mf], bl0, bl1);
                    mma_bf16(acc[mf][nf], al[mf], bh0, bh1);
                }
        }
        __syncthreads();
    }

#pragma unroll
    for (int mf = 0; mf < 2; mf++) {
        int m = row0 + warp_m * 32 + mf * 16 + (lane >> 2);
#pragma unroll
        for (int nf = 0; nf < 4; nf++) {
            int n = col0 + warp_n * 32 + nf * 8 + (lane & 3) * 2;
            if (n < Nstore) {
                float2 v0, v1;
                v0.x = acc[mf][nf][0]; v0.y = acc[mf][nf][1];
                v1.x = acc[mf][nf][2]; v1.y = acc[mf][nf][3];
                if (bias) {
                    float bx = bias[n], by = bias[n + 1];
                    v0.x += bx; v0.y += by;
                    v1.x += bx; v1.y += by;
                }
                *(float2*)(C + (long)m * ldc + n)       = v0;
                *(float2*)(C + (long)(m + 8) * ldc + n) = v1;
            }
        }
    }
}

// Merged launch: blocks 0..647 = KV fp16 gemm; 648..791 = Q/off bf16x3 gemm.
#define KV_BLOCKS 648
__global__ __launch_bounds__(512, 1)
void gemm_merged_kernel()
{
    extern __shared__ char smem[];
    int bid = blockIdx.x;
    if (bid < KV_BLOCKS) {
        int bx = bid % 12, by = bid / 12;
        gemm_fp16_body(g_xhi, g_xlo, C_, g_wkvT, nullptr,
                       g_kv, CKV_, CKV_, C_, by * 128, bx * 128, smem);
    } else {
        int b2 = bid - KV_BLOCKS;
        int bx = b2 % 8, by = b2 / 8;
        gemm_body(g_qbf_hi, g_qbf_lo, C_,
                  g_wqoffT_hi, g_wqoffT_lo, g_bias_qoff,
                  g_qoff, NQOFF_, 768 + NOFF_, C_, by * 128, bx * 128, smem);
    }
}

__global__ __launch_bounds__(512, 1)
void gemm_proj_kernel(const float* __restrict__ bias, float* __restrict__ C)
{
    extern __shared__ char smem[];
    gemm_body(g_ahi, g_alo, C_, g_wprojT_hi, g_wprojT_lo, bias,
              C, C_, C_, C_, blockIdx.y * 128, blockIdx.x * 128, smem);
}

// ---------------- deformable attention core --------------------------------------
__global__ __launch_bounds__(384, 2) void attn_kernel(
    const float* __restrict__ mask,
    const float* __restrict__ suppress_p)
{
    int bn = blockIdx.x;
    int b  = bn / N_;
    int n  = bn % N_;
    int h    = threadIdx.x >> 5;
    int lane = threadIdx.x & 31;
    int part = lane >> 4;            // 0 = K half, 1 = V half
    int ch   = (lane & 15) * 4;

    float suppress = *suppress_p;
    float mk  = mask[bn];
    float sw  = 1.f - suppress * mk;
    float moff = suppress * mk * 0.1f;

    float refx = (float)(n % HP_) * (2.f / 23.f) - 1.f;
    float refy = (float)(n / HP_) * (2.f / 23.f) - 1.f;

    const float* rowbase = g_qoff + bn * NQOFF_;
    float4 q4 = *(const float4*)(rowbase + h * DH_ + ch);

    const float* offrow = rowbase + 768 + h * (P_ * 2);
    float offv = (lane < P_ * 2) ? offrow[lane] : 0.f;

    int base_part = h * DH_ + part * C_ + ch;
    int pixbase = b * N_;

    float m0 = -1e30f, m1 = -1e30f, m2 = -1e30f;
    float s0 = 0.f, s1 = 0.f, s2 = 0.f;
    float4 o0 = make_float4(0.f, 0.f, 0.f, 0.f);
    float4 o1 = make_float4(0.f, 0.f, 0.f, 0.f);
    float4 o2 = make_float4(0.f, 0.f, 0.f, 0.f);

#pragma unroll
    for (int p = 0; p < P_; p++) {
        float ox = __shfl_sync(0xffffffffu, offv, 2 * p)     - moff;
        float oy = __shfl_sync(0xffffffffu, offv, 2 * p + 1) - moff;
        float xs = (refx + ox + 1.f) * 11.5f;
        float ys = (refy + oy + 1.f) * 11.5f;
        float x0f = floorf(xs), y0f = floorf(ys);
        int   x0 = (int)x0f,  y0 = (int)y0f;
        float wx1 = xs - x0f, wy1 = ys - y0f;
        float wx0 = 1.f - wx1, wy0 = 1.f - wy1;

        float4 a0 = make_float4(0.f, 0.f, 0.f, 0.f);
        float4 a1 = make_float4(0.f, 0.f, 0.f, 0.f);
        float4 a2 = make_float4(0.f, 0.f, 0.f, 0.f);
#pragma unroll
        for (int c = 0; c < 4; c++) {
            int dx = c & 1, dy = c >> 1;
            int ix = x0 + dx, iy = y0 + dy;
            float valid = (ix >= 0 && ix < HP_ && iy >= 0 && iy < HP_) ? 1.f : 0.f;
            float w = (dx ? wx1 : wx0) * (dy ? wy1 : wy0) * valid;
            int ixc = min(max(ix, 0), HP_ - 1);
            int iyc = min(max(iy, 0), HP_ - 1);
            int idx = (pixbase + iyc * HP_ + ixc) * (T_ * CKV_) + base_part;
            float4 kv0 = *(const float4*)(g_kv + idx);
            float4 kv1 = *(const float4*)(g_kv + idx + CKV_);
            float4 kv2 = *(const float4*)(g_kv + idx + 2 * CKV_);
            a0.x = fmaf(w, kv0.x, a0.x); a0.y = fmaf(w, kv0.y, a0.y);
            a0.z = fmaf(w, kv0.z, a0.z); a0.w = fmaf(w, kv0.w, a0.w);
            a1.x = fmaf(w, kv1.x, a1.x); a1.y = fmaf(w, kv1.y, a1.y);
            a1.z = fmaf(w, kv1.z, a1.z); a1.w = fmaf(w, kv1.w, a1.w);
            a2.x = fmaf(w, kv2.x, a2.x); a2.y = fmaf(w, kv2.y, a2.y);
            a2.z = fmaf(w, kv2.z, a2.z); a2.w = fmaf(w, kv2.w, a2.w);
        }
        float d0 = q4.x * a0.x + q4.y * a0.y + q4.z * a0.z + q4.w * a0.w;
        float d1 = q4.x * a1.x + q4.y * a1.y + q4.z * a1.z + q4.w * a1.w;
        float d2 = q4.x * a2.x + q4.y * a2.y + q4.z * a2.z + q4.w * a2.w;
#pragma unroll
        for (int s = 8; s > 0; s >>= 1) {
            d0 += __shfl_xor_sync(0xffffffffu, d0, s);
            d1 += __shfl_xor_sync(0xffffffffu, d1, s);
            d2 += __shfl_xor_sync(0xffffffffu, d2, s);
        }
        float l0 = __shfl_sync(0xffffffffu, d0, 0) * SCALE_ * sw;
        float l1 = __shfl_sync(0xffffffffu, d1, 0) * SCALE_ * sw;
        float l2 = __shfl_sync(0xffffffffu, d2, 0) * SCALE_ * sw;

        {
            float mn = fmaxf(m0, l0);
            float c1 = __expf(m0 - mn), c2 = __expf(l0 - mn);
            s0 = s0 * c1 + c2;
            o0.x = o0.x * c1 + c2 * a0.x; o0.y = o0.y * c1 + c2 * a0.y;
            o0.z = o0.z * c1 + c2 * a0.z; o0.w = o0.w * c1 + c2 * a0.w;
            m0 = mn;
        }
        {
            float mn = fmaxf(m1, l1);
            float c1 = __expf(m1 - mn), c2 = __expf(l1 - mn);
            s1 = s1 * c1 + c2;
            o1.x = o1.x * c1 + c2 * a1.x; o1.y = o1.y * c1 + c2 * a1.y;
            o1.z = o1.z * c1 + c2 * a1.z; o1.w = o1.w * c1 + c2 * a1.w;
            m1 = mn;
        }
        {
            float mn = fmaxf(m2, l2);
            float c1 = __expf(m2 - mn), c2 = __expf(l2 - mn);
            s2 = s2 * c1 + c2;
            o2.x = o2.x * c1 + c2 * a2.x; o2.y = o2.y * c1 + c2 * a2.y;
            o2.z = o2.z * c1 + c2 * a2.z; o2.w = o2.w * c1 + c2 * a2.w;
            m2 = mn;
        }
    }

    if (part == 1) {
        const float third = 1.0f / 3.0f;
        float i0 = third / s0, i1 = third / s1, i2 = third / s2;
        float rx = o0.x * i0 + o1.x * i1 + o2.x * i2;
        float ry = o0.y * i0 + o1.y * i1 + o2.y * i2;
        float rz = o0.z * i0 + o1.z * i1 + o2.z * i2;
        float rw = o0.w * i0 + o1.w * i1 + o2.w * i2;

        __nv_bfloat16 hx, lx, hy, ly, hz, lz, hw, lw;
        split_bf(rx, hx, lx); split_bf(ry, hy, ly);
        split_bf(rz, hz, lz); split_bf(rw, hw, lw);
        int oidx = bn * C_ + h * DH_ + ch;
        __nv_bfloat162 hi01(hx, hy), hi23(hz, hw);
        __nv_bfloat162 lo01(lx, ly), lo23(lz, lw);
        uint2 hpack, lpack;
        hpack.x = *(uint32_t*)&hi01; hpack.y = *(uint32_t*)&hi23;
        lpack.x = *(uint32_t*)&lo01; lpack.y = *(uint32_t*)&lo23;
        *(uint2*)(g_ahi + oidx) = hpack;
        *(uint2*)(g_alo + oidx) = lpack;
    }
}

// ---------------- launch ----------------------------------------------------------
extern "C" void kernel_launch(void* const* d_in, const int* in_sizes, int n_in,
                              void* d_out, int out_size)
{
    const float* x     = (const float*)d_in[0];
    const float* mask  = (const float*)d_in[1];
    const float* Wq    = (const float*)d_in[2];
    const float* Wk    = (const float*)d_in[3];
    const float* Wv    = (const float*)d_in[4];
    const float* Woff  = (const float*)d_in[5];
    const float* boff  = (const float*)d_in[6];
    const float* Wproj = (const float*)d_in[7];
    const float* bproj = (const float*)d_in[8];
    const float* suppr = (const float*)d_in[9];
    float* out = (float*)d_out;

    cudaFuncSetAttribute(gemm_merged_kernel,
                         cudaFuncAttributeMaxDynamicSharedMemorySize, SMEM_TOTAL);
    cudaFuncSetAttribute(gemm_proj_kernel,
                         cudaFuncAttributeMaxDynamicSharedMemorySize, SMEM_TOTAL);

    split_x_kernel<<<(MKV_ * C_ / 4 + 255) / 256, 256>>>(x);
    split_q_kernel<<<(BN_ * C_ / 4 + 255) / 256, 256>>>(x);
    tpose_split_all_kernel<<<dim3(C_ / 32, C_ / 32, 5), dim3(32, 8)>>>(
        Wq, Wk, Wv, Wproj, Woff, boff);

    gemm_merged_kernel<<<KV_BLOCKS + 144, 512, SMEM_TOTAL>>>();

    attn_kernel<<<BN_, 384>>>(mask, suppr);

    gemm_proj_kernel<<<dim3(C_ / 128, BN_ / 128), 512, SMEM_TOTAL>>>(bproj, out);
}

// round 11
// speedup vs baseline: 3.8620x; 1.0098x over previous
#include <cuda_runtime.h>
#include <cuda_bf16.h>
#include <cuda_fp16.h>
#include <cstdint>
#include <math.h>

#define B_  4
#define N_  576
#define T_  3
#define C_  768
#define H_  12
#define P_  9
#define DH_ 64
#define HP_ 24
#define SCALE_ 0.125f
#define BN_ (B_ * N_)
#define CKV_ (2 * C_)       // 1536
#define MKV_ (BN_ * T_)     // 6912
#define NOFF_ (H_ * P_ * 2) // 216
#define NQOFF_ 1024         // 768 (q) + 256 (off padded)

// ---------------- scratch (device globals) -----------------------------------
// fp16 2-term path (KV GEMM only)
__device__ __half g_xhi[MKV_ * C_];
__device__ __half g_xlo[MKV_ * C_];
__device__ __half g_wkvT[CKV_ * C_];      // [n][k]; n<768: Wk, else Wv (fp16)
// bf16x3 path (Q/off + projection GEMMs)
__device__ __nv_bfloat16 g_qbf_hi[BN_ * C_];      // query rows (t=1), contiguous
__device__ __nv_bfloat16 g_qbf_lo[BN_ * C_];
__device__ __nv_bfloat16 g_wqoffT_hi[NQOFF_ * C_]; // rows 0-767 Wq^T, 768+ Woff^T
__device__ __nv_bfloat16 g_wqoffT_lo[NQOFF_ * C_];
__device__ __nv_bfloat16 g_wprojT_hi[C_ * C_];
__device__ __nv_bfloat16 g_wprojT_lo[C_ * C_];
__device__ __nv_bfloat16 g_ahi[BN_ * C_];
__device__ __nv_bfloat16 g_alo[BN_ * C_];
__device__ float g_bias_qoff[NQOFF_];

__device__ __half g_kv[MKV_ * CKV_];     // fp16 KV (halves attn memory traffic)
__device__ float g_qoff[BN_ * NQOFF_];   // per row: q[768] | off[216] | pad

// ---------------- PTX helpers ---------------------------------------------------
__device__ __forceinline__ uint32_t smem_to_u32(const void* p) {
    uint32_t a;
    asm("{ .reg .u64 t; cvta.to.shared.u64 t, %1; cvt.u32.u64 %0, t; }"
        : "=r"(a) : "l"(p));
    return a;
}
__device__ __forceinline__ void cp16(uint32_t dst, const void* src) {
    asm volatile("cp.async.cg.shared.global [%0], [%1], 16;"
                 :: "r"(dst), "l"(src));
}
#define CP_COMMIT() asm volatile("cp.async.commit_group;" ::: "memory")
#define CP_WAIT0()  asm volatile("cp.async.wait_group 0;" ::: "memory")
#define CP_WAIT1()  asm volatile("cp.async.wait_group 1;" ::: "memory")
#define CP_WAIT2()  asm volatile("cp.async.wait_group 2;" ::: "memory")

__device__ __forceinline__ void ldm4(uint32_t* r, uint32_t addr) {
    asm volatile("ldmatrix.sync.aligned.m8n8.x4.shared.b16 {%0,%1,%2,%3}, [%4];"
                 : "=r"(r[0]), "=r"(r[1]), "=r"(r[2]), "=r"(r[3]) : "r"(addr));
}
__device__ __forceinline__ void mma_bf16(float* c, const uint32_t* a,
                                         uint32_t b0, uint32_t b1) {
    asm volatile(
        "mma.sync.aligned.m16n8k16.row.col.f32.bf16.bf16.f32 "
        "{%0,%1,%2,%3}, {%4,%5,%6,%7}, {%8,%9}, {%0,%1,%2,%3};"
        : "+f"(c[0]), "+f"(c[1]), "+f"(c[2]), "+f"(c[3])
        : "r"(a[0]), "r"(a[1]), "r"(a[2]), "r"(a[3]), "r"(b0), "r"(b1));
}
__device__ __forceinline__ void mma_fp16(float* c, const uint32_t* a,
                                         uint32_t b0, uint32_t b1) {
    asm volatile(
        "mma.sync.aligned.m16n8k16.row.col.f32.f16.f16.f32 "
        "{%0,%1,%2,%3}, {%4,%5,%6,%7}, {%8,%9}, {%0,%1,%2,%3};"
        : "+f"(c[0]), "+f"(c[1]), "+f"(c[2]), "+f"(c[3])
        : "r"(a[0]), "r"(a[1]), "r"(a[2]), "r"(a[3]), "r"(b0), "r"(b1));
}

// ---------------- prep kernels ---------------------------------------------------
__device__ __forceinline__ void split_bf(float v, __nv_bfloat16& hi, __nv_bfloat16& lo) {
    hi = __float2bfloat16(v);
    lo = __float2bfloat16(v - __bfloat162float(hi));
}
__device__ __forceinline__ void split_h(float v, __half& hi, __half& lo) {
    hi = __float2half_rn(v);
    lo = __float2half_rn(v - __half2float(hi));
}

__global__ void split_x_kernel(const float* __restrict__ x) {
    int idx = blockIdx.x * blockDim.x + threadIdx.x;
    if (idx >= MKV_ * C_ / 4) return;
    float4 v = ((const float4*)x)[idx];
    __half h0, l0, h1, l1, h2, l2, h3, l3;
    split_h(v.x, h0, l0); split_h(v.y, h1, l1);
    split_h(v.z, h2, l2); split_h(v.w, h3, l3);
    ((__half2*)g_xhi)[idx * 2]     = __halves2half2(h0, h1);
    ((__half2*)g_xhi)[idx * 2 + 1] = __halves2half2(h2, h3);
    ((__half2*)g_xlo)[idx * 2]     = __halves2half2(l0, l1);
    ((__half2*)g_xlo)[idx * 2 + 1] = __halves2half2(l2, l3);
}

// bf16 split of query rows (t = 1), stored contiguously [BN_, C_]
__global__ void split_q_kernel(const float* __restrict__ x) {
    int idx = blockIdx.x * blockDim.x + threadIdx.x;   // over BN_*C_/4
    if (idx >= BN_ * C_ / 4) return;
    int row = idx / (C_ / 4);
    int c4  = idx % (C_ / 4);
    float4 v = *(const float4*)(x + ((long)row * T_ + 1) * C_ + c4 * 4);
    __nv_bfloat16 h0, l0, h1, l1, h2, l2, h3, l3;
    split_bf(v.x, h0, l0); split_bf(v.y, h1, l1);
    split_bf(v.z, h2, l2); split_bf(v.w, h3, l3);
    ((__nv_bfloat162*)g_qbf_hi)[idx * 2]     = __nv_bfloat162(h0, h1);
    ((__nv_bfloat162*)g_qbf_hi)[idx * 2 + 1] = __nv_bfloat162(h2, h3);
    ((__nv_bfloat162*)g_qbf_lo)[idx * 2]     = __nv_bfloat162(l0, l1);
    ((__nv_bfloat162*)g_qbf_lo)[idx * 2 + 1] = __nv_bfloat162(l2, l3);
}

// Fused transpose of all weights; blockIdx.z selects matrix.
// Wk/Wv -> fp16; Wq/Woff/Wproj -> bf16 hi/lo.
__global__ void tpose_split_all_kernel(
    const float* __restrict__ Wq, const float* __restrict__ Wk,
    const float* __restrict__ Wv, const float* __restrict__ Wproj,
    const float* __restrict__ Woff, const float* __restrict__ boff)
{
    if (blockIdx.z == 0 && blockIdx.x == 0 && blockIdx.y == 0) {
        int t = threadIdx.y * 32 + threadIdx.x;
        for (int i = t; i < NQOFF_; i += 256)
            g_bias_qoff[i] = (i >= 768 && i < 768 + NOFF_) ? boff[i - 768] : 0.f;
    }

    const float* src;
    __half* dh = nullptr;
    __nv_bfloat16 *dhi = nullptr, *dlo = nullptr;
    int N, dstRows;
    switch (blockIdx.z) {
        case 0: src = Wq;    dhi = g_wqoffT_hi; dlo = g_wqoffT_lo; N = C_; dstRows = C_; break;
        case 1: src = Wk;    dh = g_wkvT;                 N = C_;   dstRows = C_;  break;
        case 2: src = Wv;    dh = g_wkvT + (long)C_ * C_; N = C_;   dstRows = C_;  break;
        case 3: src = Wproj; dhi = g_wprojT_hi; dlo = g_wprojT_lo; N = C_; dstRows = C_; break;
        default: src = Woff; dhi = g_wqoffT_hi + (long)768 * C_;
                             dlo = g_wqoffT_lo + (long)768 * C_;   N = NOFF_; dstRows = 256; break;
    }
    int n0 = blockIdx.x * 32, k0 = blockIdx.y * 32;
    if (n0 >= dstRows) return;

    __shared__ float tile[32][33];
    int tx = threadIdx.x, ty = threadIdx.y;
#pragma unroll
    for (int j = 0; j < 4; j++) {
        int k = k0 + ty + j * 8, n = n0 + tx;
        tile[ty + j * 8][tx] = (n < N) ? src[(long)k * N + n] : 0.f;
    }
    __syncthreads();
#pragma unroll
    for (int j = 0; j < 4; j++) {
        int n = n0 + ty + j * 8, k = k0 + tx;
        if (n < dstRows) {
            float v = tile[tx][ty + j * 8];
            if (dh) {
                dh[(long)n * C_ + k] = __float2half_rn(v);
            } else {
                __nv_bfloat16 hi, lo;
                split_bf(v, hi, lo);
                dhi[(long)n * C_ + k] = hi;
                dlo[(long)n * C_ + k] = lo;
            }
        }
    }
}

// ---------------- fp16 2-term GEMM body (512 threads, 3-stage pipeline) ----------
// C(half) = (Ahi+Alo) @ Bh^T. Tile 128x128, K-chunk 64, SW128 swizzle.
#define FTILE 16384
#define FSTAGE (3 * FTILE)
#define FSMEM3 (3 * FSTAGE)   // 147456

__device__ __forceinline__ void gemm_fp16_body(
    const __half* __restrict__ Ahi,
    const __half* __restrict__ Alo, long lda,
    const __half* __restrict__ Bh,
    __half* __restrict__ C, int ldc, int K,
    int row0, int col0, char* smem)
{
    uint32_t sb = smem_to_u32(smem);
    int tid = threadIdx.x;
    int wid = tid >> 5, lane = tid & 31;
    int warp_m = wid & 3;
    int warp_n = wid >> 2;
    const int NKITER = K / 64;

    int rr[2], cc[2], doff[2];
#pragma unroll
    for (int j = 0; j < 2; j++) {
        int u = tid + j * 512;
        int r = u >> 3, cu = u & 7;
        rr[j] = r; cc[j] = cu;
        doff[j] = ((r << 3) + (cu ^ (r & 7))) << 4;
    }

    const __half* gp[3] = {Ahi, Alo, Bh};
    long  st[3] = {lda, lda, (long)K};
    int   rb[3] = {row0, row0, col0};

    // prologue: stages 0 and 1
#pragma unroll
    for (int s = 0; s < 2; s++) {
        uint32_t sstage = sb + s * FSTAGE;
        int k0 = s * 64;
#pragma unroll
        for (int a = 0; a < 3; a++) {
            uint32_t sdst = sstage + a * FTILE;
            const __half* g = gp[a];
#pragma unroll
            for (int j = 0; j < 2; j++)
                cp16(sdst + doff[j],
                     g + (long)(rb[a] + rr[j]) * st[a] + k0 + cc[j] * 8);
        }
        CP_COMMIT();
    }

    float acc[2][4][4];
#pragma unroll
    for (int mf = 0; mf < 2; mf++)
#pragma unroll
        for (int nf = 0; nf < 4; nf++)
#pragma unroll
            for (int e = 0; e < 4; e++) acc[mf][nf][e] = 0.f;

    int a_r = warp_m * 32 + (lane & 7) + ((lane & 8) ? 8 : 0);
    int a_usel = (lane & 16) ? 1 : 0;
    int b_rbase = warp_n * 32 + (lane & 7) + ((lane & 16) ? 8 : 0);
    int b_usel = (lane & 8) ? 1 : 0;

    int bufc = 0;   // kc % 3
    int bufn = 2;   // (kc+2) % 3
    for (int kc = 0; kc < NKITER; kc++) {
        if (kc + 2 < NKITER) {
            uint32_t sstage = sb + bufn * FSTAGE;
            int k0 = (kc + 2) * 64;
#pragma unroll
            for (int a = 0; a < 3; a++) {
                uint32_t sdst = sstage + a * FTILE;
                const __half* g = gp[a];
#pragma unroll
                for (int j = 0; j < 2; j++)
                    cp16(sdst + doff[j],
                         g + (long)(rb[a] + rr[j]) * st[a] + k0 + cc[j] * 8);
            }
            CP_COMMIT();
            CP_WAIT2();
        } else if (kc + 1 < NKITER) {
            CP_WAIT1();
        } else {
            CP_WAIT0();
        }
        __syncthreads();

        uint32_t s = sb + bufc * FSTAGE;
        uint32_t sAhi = s, sAlo = s + FTILE, sBh = s + 2 * FTILE;

#pragma unroll
        for (int ks = 0; ks < 4; ks++) {
            uint32_t ah[2][4], al[2][4];
#pragma unroll
            for (int mf = 0; mf < 2; mf++) {
                int r = a_r + mf * 16;
                int u = ks * 2 + a_usel;
                uint32_t off = (uint32_t)(((r << 3) + (u ^ (r & 7))) << 4);
                ldm4(ah[mf], sAhi + off);
                ldm4(al[mf], sAlo + off);
            }
            uint32_t bh[2][4];
#pragma unroll
            for (int np = 0; np < 2; np++) {
                int r = b_rbase + np * 16;
                int u = ks * 2 + b_usel;
                uint32_t off = (uint32_t)(((r << 3) + (u ^ (r & 7))) << 4);
                ldm4(bh[np], sBh + off);
            }
#pragma unroll
            for (int mf = 0; mf < 2; mf++)
#pragma unroll
                for (int nf = 0; nf < 4; nf++) {
                    int np = nf >> 1;
                    int half = (nf & 1) * 2;
                    uint32_t b0 = bh[np][half], b1 = bh[np][half + 1];
                    mma_fp16(acc[mf][nf], ah[mf], b0, b1);
                    mma_fp16(acc[mf][nf], al[mf], b0, b1);
                }
        }
        __syncthreads();
        bufc = (bufc == 2) ? 0 : bufc + 1;
        bufn = (bufn == 2) ? 0 : bufn + 1;
    }

    // epilogue: convert to fp16, store half2 pairs
#pragma unroll
    for (int mf = 0; mf < 2; mf++) {
        int m = row0 + warp_m * 32 + mf * 16 + (lane >> 2);
#pragma unroll
        for (int nf = 0; nf < 4; nf++) {
            int n = col0 + warp_n * 32 + nf * 8 + (lane & 3) * 2;
            __half2 v0 = __floats2half2_rn(acc[mf][nf][0], acc[mf][nf][1]);
            __half2 v1 = __floats2half2_rn(acc[mf][nf][2], acc[mf][nf][3]);
            *(__half2*)(C + (long)m * ldc + n)       = v0;
            *(__half2*)(C + (long)(m + 8) * ldc + n) = v1;
        }
    }
}

// ---------------- bf16x3 GEMM body (Q/off + proj) --------------------------------
#define TILE_BYTES 16384
#define STAGE_BYTES (4 * TILE_BYTES)
#define SMEM_TOTAL (2 * STAGE_BYTES)  // 131072
#define SMEM_MERGED (FSMEM3 > SMEM_TOTAL ? FSMEM3 : SMEM_TOTAL)

__device__ __forceinline__ void gemm_body(
    const __nv_bfloat16* __restrict__ Ahi,
    const __nv_bfloat16* __restrict__ Alo, long lda,
    const __nv_bfloat16* __restrict__ Bhi,
    const __nv_bfloat16* __restrict__ Blo,
    const float* __restrict__ bias,
    float* __restrict__ C, int ldc, int Nstore, int K,
    int row0, int col0, char* smem)
{
    uint32_t sb = smem_to_u32(smem);
    int tid = threadIdx.x;
    int wid = tid >> 5, lane = tid & 31;
    int warp_m = wid & 3;
    int warp_n = wid >> 2;
    const int NKITER = K / 64;

    int rr[2], cc[2], doff[2];
#pragma unroll
    for (int j = 0; j < 2; j++) {
        int u = tid + j * 512;
        int r = u >> 3, cu = u & 7;
        rr[j] = r; cc[j] = cu;
        doff[j] = ((r << 3) + (cu ^ (r & 7))) << 4;
    }

    const __nv_bfloat16* gp[4] = {Ahi, Alo, Bhi, Blo};
    long  st[4] = {lda, lda, (long)K, (long)K};
    int   rb[4] = {row0, row0, col0, col0};

#pragma unroll
    for (int a = 0; a < 4; a++) {
        uint32_t sdst = sb + a * TILE_BYTES;
        const __nv_bfloat16* g = gp[a];
#pragma unroll
        for (int j = 0; j < 2; j++)
            cp16(sdst + doff[j], g + (long)(rb[a] + rr[j]) * st[a] + cc[j] * 8);
    }
    CP_COMMIT();

    float acc[2][4][4];
#pragma unroll
    for (int mf = 0; mf < 2; mf++)
#pragma unroll
        for (int nf = 0; nf < 4; nf++)
#pragma unroll
            for (int e = 0; e < 4; e++) acc[mf][nf][e] = 0.f;

    int a_r = warp_m * 32 + (lane & 7) + ((lane & 8) ? 8 : 0);
    int a_usel = (lane & 16) ? 1 : 0;
    int b_rbase = warp_n * 32 + (lane & 7) + ((lane & 16) ? 8 : 0);
    int b_usel = (lane & 8) ? 1 : 0;

    for (int kc = 0; kc < NKITER; kc++) {
        if (kc + 1 < NKITER) {
            uint32_t sstage = sb + ((kc + 1) & 1) * STAGE_BYTES;
            int k0 = (kc + 1) * 64;
#pragma unroll
            for (int a = 0; a < 4; a++) {
                uint32_t sdst = sstage + a * TILE_BYTES;
                const __nv_bfloat16* g = gp[a];
#pragma unroll
                for (int j = 0; j < 2; j++)
                    cp16(sdst + doff[j],
                         g + (long)(rb[a] + rr[j]) * st[a] + k0 + cc[j] * 8);
            }
            CP_COMMIT();
            CP_WAIT1();
        } else {
            CP_WAIT0();
        }
        __syncthreads();

        uint32_t s = sb + (kc & 1) * STAGE_BYTES;
        uint32_t sAhi = s, sAlo = s + TILE_BYTES;
        uint32_t sBhi = s + 2 * TILE_BYTES, sBlo = s + 3 * TILE_BYTES;

#pragma unroll
        for (int ks = 0; ks < 4; ks++) {
            uint32_t ah[2][4], al[2][4];
#pragma unroll
            for (int mf = 0; mf < 2; mf++) {
                int r = a_r + mf * 16;
                int u = ks * 2 + a_usel;
                uint32_t off = (uint32_t)(((r << 3) + (u ^ (r & 7))) << 4);
                ldm4(ah[mf], sAhi + off);
                ldm4(al[mf], sAlo + off);
            }
            uint32_t bh[2][4], bl[2][4];
#pragma unroll
            for (int np = 0; np < 2; np++) {
                int r = b_rbase + np * 16;
                int u = ks * 2 + b_usel;
                uint32_t off = (uint32_t)(((r << 3) + (u ^ (r & 7))) << 4);
                ldm4(bh[np], sBhi + off);
                ldm4(bl[np], sBlo + off);
            }
#pragma unroll
            for (int mf = 0; mf < 2; mf++)
#pragma unroll
                for (int nf = 0; nf < 4; nf++) {
                    int np = nf >> 1;
                    int half = (nf & 1) * 2;
                    uint32_t bh0 = bh[np][half], bh1 = bh[np][half + 1];
                    uint32_t bl0 = bl[np][half], bl1 = bl[np][half + 1];
                    mma_bf16(acc[mf][nf], ah[mf], bh0, bh1);
                    mma_bf16(acc[mf][nf], ah[mf], bl0, bl1);
                    mma_bf16(acc[mf][nf], al[mf], bh0, bh1);
                }
        }
        __syncthreads();
    }

#pragma unroll
    for (int mf = 0; mf < 2; mf++) {
        int m = row0 + warp_m * 32 + mf * 16 + (lane >> 2);
#pragma unroll
        for (int nf = 0; nf < 4; nf++) {
            int n = col0 + warp_n * 32 + nf * 8 + (lane & 3) * 2;
            if (n < Nstore) {
                float2 v0, v1;
                v0.x = acc[mf][nf][0]; v0.y = acc[mf][nf][1];
                v1.x = acc[mf][nf][2]; v1.y = acc[mf][nf][3];
                if (bias) {
                    float bx = bias[n], by = bias[n + 1];
                    v0.x += bx; v0.y += by;
                    v1.x += bx; v1.y += by;
                }
                *(float2*)(C + (long)m * ldc + n)       = v0;
                *(float2*)(C + (long)(m + 8) * ldc + n) = v1;
            }
        }
    }
}

// Merged launch: blocks 0..647 = KV fp16 gemm; 648..791 = Q/off bf16x3 gemm.
#define KV_BLOCKS 648
__global__ __launch_bounds__(512, 1)
void gemm_merged_kernel()
{
    extern __shared__ char smem[];
    int bid = blockIdx.x;
    if (bid < KV_BLOCKS) {
        int bx = bid % 12, by = bid / 12;
        gemm_fp16_body(g_xhi, g_xlo, C_, g_wkvT,
                       g_kv, CKV_, C_, by * 128, bx * 128, smem);
    } else {
        int b2 = bid - KV_BLOCKS;
        int bx = b2 % 8, by = b2 / 8;
        gemm_body(g_qbf_hi, g_qbf_lo, C_,
                  g_wqoffT_hi, g_wqoffT_lo, g_bias_qoff,
                  g_qoff, NQOFF_, 768 + NOFF_, C_, by * 128, bx * 128, smem);
    }
}

__global__ __launch_bounds__(512, 1)
void gemm_proj_kernel(const float* __restrict__ bias, float* __restrict__ C)
{
    extern __shared__ char smem[];
    gemm_body(g_ahi, g_alo, C_, g_wprojT_hi, g_wprojT_lo, bias,
              C, C_, C_, C_, blockIdx.y * 128, blockIdx.x * 128, smem);
}

// ---------------- deformable attention core --------------------------------------
__device__ __forceinline__ float4 h4_to_f4(uint2 r) {
    __half2 a = *(__half2*)&r.x;
    __half2 b = *(__half2*)&r.y;
    float2 fa = __half22float2(a);
    float2 fb = __half22float2(b);
    return make_float4(fa.x, fa.y, fb.x, fb.y);
}

__global__ __launch_bounds__(384, 2) void attn_kernel(
    const float* __restrict__ mask,
    const float* __restrict__ suppress_p)
{
    int bn = blockIdx.x;
    int b  = bn / N_;
    int n  = bn % N_;
    int h    = threadIdx.x >> 5;
    int lane = threadIdx.x & 31;
    int part = lane >> 4;            // 0 = K half, 1 = V half
    int ch   = (lane & 15) * 4;

    float suppress = *suppress_p;
    float mk  = mask[bn];
    float sw  = 1.f - suppress * mk;
    float moff = suppress * mk * 0.1f;

    float refx = (float)(n % HP_) * (2.f / 23.f) - 1.f;
    float refy = (float)(n / HP_) * (2.f / 23.f) - 1.f;

    const float* rowbase = g_qoff + bn * NQOFF_;
    float4 q4 = *(const float4*)(rowbase + h * DH_ + ch);

    const float* offrow = rowbase + 768 + h * (P_ * 2);
    float offv = (lane < P_ * 2) ? offrow[lane] : 0.f;

    int base_part = h * DH_ + part * C_ + ch;
    int pixbase = b * N_;

    float m0 = -1e30f, m1 = -1e30f, m2 = -1e30f;
    float s0 = 0.f, s1 = 0.f, s2 = 0.f;
    float4 o0 = make_float4(0.f, 0.f, 0.f, 0.f);
    float4 o1 = make_float4(0.f, 0.f, 0.f, 0.f);
    float4 o2 = make_float4(0.f, 0.f, 0.f, 0.f);

#pragma unroll
    for (int p = 0; p < P_; p++) {
        float ox = __shfl_sync(0xffffffffu, offv, 2 * p)     - moff;
        float oy = __shfl_sync(0xffffffffu, offv, 2 * p + 1) - moff;
        float xs = (refx + ox + 1.f) * 11.5f;
        float ys = (refy + oy + 1.f) * 11.5f;
        float x0f = floorf(xs), y0f = floorf(ys);
        int   x0 = (int)x0f,  y0 = (int)y0f;
        float wx1 = xs - x0f, wy1 = ys - y0f;
        float wx0 = 1.f - wx1, wy0 = 1.f - wy1;

        float4 a0 = make_float4(0.f, 0.f, 0.f, 0.f);
        float4 a1 = make_float4(0.f, 0.f, 0.f, 0.f);
        float4 a2 = make_float4(0.f, 0.f, 0.f, 0.f);
#pragma unroll
        for (int c = 0; c < 4; c++) {
            int dx = c & 1, dy = c >> 1;
            int ix = x0 + dx, iy = y0 + dy;
            float valid = (ix >= 0 && ix < HP_ && iy >= 0 && iy < HP_) ? 1.f : 0.f;
            float w = (dx ? wx1 : wx0) * (dy ? wy1 : wy0) * valid;
            int ixc = min(max(ix, 0), HP_ - 1);
            int iyc = min(max(iy, 0), HP_ - 1);
            int idx = (pixbase + iyc * HP_ + ixc) * (T_ * CKV_) + base_part;
            const __half* kvp = g_kv + idx;
            float4 kv0 = h4_to_f4(*(const uint2*)(kvp));
            float4 kv1 = h4_to_f4(*(const uint2*)(kvp + CKV_));
            float4 kv2 = h4_to_f4(*(const uint2*)(kvp + 2 * CKV_));
            a0.x = fmaf(w, kv0.x, a0.x); a0.y = fmaf(w, kv0.y, a0.y);
            a0.z = fmaf(w, kv0.z, a0.z); a0.w = fmaf(w, kv0.w, a0.w);
            a1.x = fmaf(w, kv1.x, a1.x); a1.y = fmaf(w, kv1.y, a1.y);
            a1.z = fmaf(w, kv1.z, a1.z); a1.w = fmaf(w, kv1.w, a1.w);
            a2.x = fmaf(w, kv2.x, a2.x); a2.y = fmaf(w, kv2.y, a2.y);
            a2.z = fmaf(w, kv2.z, a2.z); a2.w = fmaf(w, kv2.w, a2.w);
        }
        float d0 = q4.x * a0.x + q4.y * a0.y + q4.z * a0.z + q4.w * a0.w;
        float d1 = q4.x * a1.x + q4.y * a1.y + q4.z * a1.z + q4.w * a1.w;
        float d2 = q4.x * a2.x + q4.y * a2.y + q4.z * a2.z + q4.w * a2.w;
#pragma unroll
        for (int s = 8; s > 0; s >>= 1) {
            d0 += __shfl_xor_sync(0xffffffffu, d0, s);
            d1 += __shfl_xor_sync(0xffffffffu, d1, s);
            d2 += __shfl_xor_sync(0xffffffffu, d2, s);
        }
        float l0 = __shfl_sync(0xffffffffu, d0, 0) * SCALE_ * sw;
        float l1 = __shfl_sync(0xffffffffu, d1, 0) * SCALE_ * sw;
        float l2 = __shfl_sync(0xffffffffu, d2, 0) * SCALE_ * sw;

        {
            float mn = fmaxf(m0, l0);
            float c1 = __expf(m0 - mn), c2 = __expf(l0 - mn);
            s0 = s0 * c1 + c2;
            o0.x = o0.x * c1 + c2 * a0.x; o0.y = o0.y * c1 + c2 * a0.y;
            o0.z = o0.z * c1 + c2 * a0.z; o0.w = o0.w * c1 + c2 * a0.w;
            m0 = mn;
        }
        {
            float mn = fmaxf(m1, l1);
            float c1 = __expf(m1 - mn), c2 = __expf(l1 - mn);
            s1 = s1 * c1 + c2;
            o1.x = o1.x * c1 + c2 * a1.x; o1.y = o1.y * c1 + c2 * a1.y;
            o1.z = o1.z * c1 + c2 * a1.z; o1.w = o1.w * c1 + c2 * a1.w;
            m1 = mn;
        }
        {
            float mn = fmaxf(m2, l2);
            float c1 = __expf(m2 - mn), c2 = __expf(l2 - mn);
            s2 = s2 * c1 + c2;
            o2.x = o2.x * c1 + c2 * a2.x; o2.y = o2.y * c1 + c2 * a2.y;
            o2.z = o2.z * c1 + c2 * a2.z; o2.w = o2.w * c1 + c2 * a2.w;
            m2 = mn;
        }
    }

    if (part == 1) {
        const float third = 1.0f / 3.0f;
        float i0 = third / s0, i1 = third / s1, i2 = third / s2;
        float rx = o0.x * i0 + o1.x * i1 + o2.x * i2;
        float ry = o0.y * i0 + o1.y * i1 + o2.y * i2;
        float rz = o0.z * i0 + o1.z * i1 + o2.z * i2;
        float rw = o0.w * i0 + o1.w * i1 + o2.w * i2;

        __nv_bfloat16 hx, lx, hy, ly, hz, lz, hw, lw;
        split_bf(rx, hx, lx); split_bf(ry, hy, ly);
        split_bf(rz, hz, lz); split_bf(rw, hw, lw);
        int oidx = bn * C_ + h * DH_ + ch;
        __nv_bfloat162 hi01(hx, hy), hi23(hz, hw);
        __nv_bfloat162 lo01(lx, ly), lo23(lz, lw);
        uint2 hpack, lpack;
        hpack.x = *(uint32_t*)&hi01; hpack.y = *(uint32_t*)&hi23;
        lpack.x = *(uint32_t*)&lo01; lpack.y = *(uint32_t*)&lo23;
        *(uint2*)(g_ahi + oidx) = hpack;
        *(uint2*)(g_alo + oidx) = lpack;
    }
}

// ---------------- launch ----------------------------------------------------------
extern "C" void kernel_launch(void* const* d_in, const int* in_sizes, int n_in,
                              void* d_out, int out_size)
{
    const float* x     = (const float*)d_in[0];
    const float* mask  = (const float*)d_in[1];
    const float* Wq    = (const float*)d_in[2];
    const float* Wk    = (const float*)d_in[3];
    const float* Wv    = (const float*)d_in[4];
    const float* Woff  = (const float*)d_in[5];
    const float* boff  = (const float*)d_in[6];
    const float* Wproj = (const float*)d_in[7];
    const float* bproj = (const float*)d_in[8];
    const float* suppr = (const float*)d_in[9];
    float* out = (float*)d_out;

    cudaFuncSetAttribute(gemm_merged_kernel,
                         cudaFuncAttributeMaxDynamicSharedMemorySize, SMEM_MERGED);
    cudaFuncSetAttribute(gemm_proj_kernel,
                         cudaFuncAttributeMaxDynamicSharedMemorySize, SMEM_TOTAL);

    split_x_kernel<<<(MKV_ * C_ / 4 + 255) / 256, 256>>>(x);
    split_q_kernel<<<(BN_ * C_ / 4 + 255) / 256, 256>>>(x);
    tpose_split_all_kernel<<<dim3(C_ / 32, C_ / 32, 5), dim3(32, 8)>>>(
        Wq, Wk, Wv, Wproj, Woff, boff);

    gemm_merged_kernel<<<KV_BLOCKS + 144, 512, SMEM_MERGED>>>();

    attn_kernel<<<BN_, 384>>>(mask, suppr);

    gemm_proj_kernel<<<dim3(C_ / 128, BN_ / 128), 512, SMEM_TOTAL>>>(bproj, out);
}

// round 12
// speedup vs baseline: 4.5325x; 1.1736x over previous
#include <cuda_runtime.h>
#include <cuda_bf16.h>
#include <cuda_fp16.h>
#include <cstdint>
#include <math.h>

#define B_  4
#define N_  576
#define T_  3
#define C_  768
#define H_  12
#define P_  9
#define DH_ 64
#define HP_ 24
#define SCALE_ 0.125f
#define BN_ (B_ * N_)
#define CKV_ (2 * C_)       // 1536
#define MKV_ (BN_ * T_)     // 6912
#define NOFF_ (H_ * P_ * 2) // 216
#define NQOFF_ 1024         // 768 (q) + 256 (off padded)

// ---------------- scratch (device globals) -----------------------------------
// fp16 single-pass path (KV GEMM)
__device__ __half g_xh[MKV_ * C_];        // x in fp16
__device__ __half g_wkvT[CKV_ * C_];      // [n][k]; n<768: Wk, else Wv (fp16)
// bf16x3 path (Q/off + projection GEMMs)
__device__ __nv_bfloat16 g_qbf_hi[BN_ * C_];      // query rows (t=1), contiguous
__device__ __nv_bfloat16 g_qbf_lo[BN_ * C_];
__device__ __nv_bfloat16 g_wqoffT_hi[NQOFF_ * C_]; // rows 0-767 Wq^T, 768+ Woff^T
__device__ __nv_bfloat16 g_wqoffT_lo[NQOFF_ * C_];
__device__ __nv_bfloat16 g_wprojT_hi[C_ * C_];
__device__ __nv_bfloat16 g_wprojT_lo[C_ * C_];
__device__ __nv_bfloat16 g_ahi[BN_ * C_];
__device__ __nv_bfloat16 g_alo[BN_ * C_];
__device__ float g_bias_qoff[NQOFF_];

__device__ __half g_kv[MKV_ * CKV_];     // fp16 KV
__device__ float g_qoff[BN_ * NQOFF_];   // per row: q[768] | off[216] | pad

// ---------------- PTX helpers ---------------------------------------------------
__device__ __forceinline__ uint32_t smem_to_u32(const void* p) {
    uint32_t a;
    asm("{ .reg .u64 t; cvta.to.shared.u64 t, %1; cvt.u32.u64 %0, t; }"
        : "=r"(a) : "l"(p));
    return a;
}
__device__ __forceinline__ void cp16(uint32_t dst, const void* src) {
    asm volatile("cp.async.cg.shared.global [%0], [%1], 16;"
                 :: "r"(dst), "l"(src));
}
#define CP_COMMIT() asm volatile("cp.async.commit_group;" ::: "memory")
#define CP_WAIT0()  asm volatile("cp.async.wait_group 0;" ::: "memory")
#define CP_WAIT1()  asm volatile("cp.async.wait_group 1;" ::: "memory")
#define CP_WAIT2()  asm volatile("cp.async.wait_group 2;" ::: "memory")

__device__ __forceinline__ void ldm4(uint32_t* r, uint32_t addr) {
    asm volatile("ldmatrix.sync.aligned.m8n8.x4.shared.b16 {%0,%1,%2,%3}, [%4];"
                 : "=r"(r[0]), "=r"(r[1]), "=r"(r[2]), "=r"(r[3]) : "r"(addr));
}
__device__ __forceinline__ void mma_bf16(float* c, const uint32_t* a,
                                         uint32_t b0, uint32_t b1) {
    asm volatile(
        "mma.sync.aligned.m16n8k16.row.col.f32.bf16.bf16.f32 "
        "{%0,%1,%2,%3}, {%4,%5,%6,%7}, {%8,%9}, {%0,%1,%2,%3};"
        : "+f"(c[0]), "+f"(c[1]), "+f"(c[2]), "+f"(c[3])
        : "r"(a[0]), "r"(a[1]), "r"(a[2]), "r"(a[3]), "r"(b0), "r"(b1));
}
__device__ __forceinline__ void mma_fp16(float* c, const uint32_t* a,
                                         uint32_t b0, uint32_t b1) {
    asm volatile(
        "mma.sync.aligned.m16n8k16.row.col.f32.f16.f16.f32 "
        "{%0,%1,%2,%3}, {%4,%5,%6,%7}, {%8,%9}, {%0,%1,%2,%3};"
        : "+f"(c[0]), "+f"(c[1]), "+f"(c[2]), "+f"(c[3])
        : "r"(a[0]), "r"(a[1]), "r"(a[2]), "r"(a[3]), "r"(b0), "r"(b1));
}

// ---------------- prep kernels ---------------------------------------------------
__device__ __forceinline__ void split_bf(float v, __nv_bfloat16& hi, __nv_bfloat16& lo) {
    hi = __float2bfloat16(v);
    lo = __float2bfloat16(v - __bfloat162float(hi));
}

__global__ void conv_x_kernel(const float* __restrict__ x) {
    int idx = blockIdx.x * blockDim.x + threadIdx.x;
    if (idx >= MKV_ * C_ / 4) return;
    float4 v = ((const float4*)x)[idx];
    __half2 a = __floats2half2_rn(v.x, v.y);
    __half2 b = __floats2half2_rn(v.z, v.w);
    ((__half2*)g_xh)[idx * 2]     = a;
    ((__half2*)g_xh)[idx * 2 + 1] = b;
}

// bf16 split of query rows (t = 1), stored contiguously [BN_, C_]
__global__ void split_q_kernel(const float* __restrict__ x) {
    int idx = blockIdx.x * blockDim.x + threadIdx.x;   // over BN_*C_/4
    if (idx >= BN_ * C_ / 4) return;
    int row = idx / (C_ / 4);
    int c4  = idx % (C_ / 4);
    float4 v = *(const float4*)(x + ((long)row * T_ + 1) * C_ + c4 * 4);
    __nv_bfloat16 h0, l0, h1, l1, h2, l2, h3, l3;
    split_bf(v.x, h0, l0); split_bf(v.y, h1, l1);
    split_bf(v.z, h2, l2); split_bf(v.w, h3, l3);
    ((__nv_bfloat162*)g_qbf_hi)[idx * 2]     = __nv_bfloat162(h0, h1);
    ((__nv_bfloat162*)g_qbf_hi)[idx * 2 + 1] = __nv_bfloat162(h2, h3);
    ((__nv_bfloat162*)g_qbf_lo)[idx * 2]     = __nv_bfloat162(l0, l1);
    ((__nv_bfloat162*)g_qbf_lo)[idx * 2 + 1] = __nv_bfloat162(l2, l3);
}

// Fused transpose of all weights; blockIdx.z selects matrix.
// Wk/Wv -> fp16; Wq/Woff/Wproj -> bf16 hi/lo.
__global__ void tpose_split_all_kernel(
    const float* __restrict__ Wq, const float* __restrict__ Wk,
    const float* __restrict__ Wv, const float* __restrict__ Wproj,
    const float* __restrict__ Woff, const float* __restrict__ boff)
{
    if (blockIdx.z == 0 && blockIdx.x == 0 && blockIdx.y == 0) {
        int t = threadIdx.y * 32 + threadIdx.x;
        for (int i = t; i < NQOFF_; i += 256)
            g_bias_qoff[i] = (i >= 768 && i < 768 + NOFF_) ? boff[i - 768] : 0.f;
    }

    const float* src;
    __half* dh = nullptr;
    __nv_bfloat16 *dhi = nullptr, *dlo = nullptr;
    int N, dstRows;
    switch (blockIdx.z) {
        case 0: src = Wq;    dhi = g_wqoffT_hi; dlo = g_wqoffT_lo; N = C_; dstRows = C_; break;
        case 1: src = Wk;    dh = g_wkvT;                 N = C_;   dstRows = C_;  break;
        case 2: src = Wv;    dh = g_wkvT + (long)C_ * C_; N = C_;   dstRows = C_;  break;
        case 3: src = Wproj; dhi = g_wprojT_hi; dlo = g_wprojT_lo; N = C_; dstRows = C_; break;
        default: src = Woff; dhi = g_wqoffT_hi + (long)768 * C_;
                             dlo = g_wqoffT_lo + (long)768 * C_;   N = NOFF_; dstRows = 256; break;
    }
    int n0 = blockIdx.x * 32, k0 = blockIdx.y * 32;
    if (n0 >= dstRows) return;

    __shared__ float tile[32][33];
    int tx = threadIdx.x, ty = threadIdx.y;
#pragma unroll
    for (int j = 0; j < 4; j++) {
        int k = k0 + ty + j * 8, n = n0 + tx;
        tile[ty + j * 8][tx] = (n < N) ? src[(long)k * N + n] : 0.f;
    }
    __syncthreads();
#pragma unroll
    for (int j = 0; j < 4; j++) {
        int n = n0 + ty + j * 8, k = k0 + tx;
        if (n < dstRows) {
            float v = tile[tx][ty + j * 8];
            if (dh) {
                dh[(long)n * C_ + k] = __float2half_rn(v);
            } else {
                __nv_bfloat16 hi, lo;
                split_bf(v, hi, lo);
                dhi[(long)n * C_ + k] = hi;
                dlo[(long)n * C_ + k] = lo;
            }
        }
    }
}

// ---------------- fp16 single-pass GEMM body (512 threads, 3-stage) --------------
// C(half) = Ah @ Bh^T. Tile 128x128, K-chunk 64, SW128 swizzle.
#define FTILE 16384
#define FSTAGE (2 * FTILE)    // A, B
#define FSMEM3 (3 * FSTAGE)   // 98304

__device__ __forceinline__ void gemm_fp16_body(
    const __half* __restrict__ Ah, long lda,
    const __half* __restrict__ Bh,
    __half* __restrict__ C, int ldc, int K,
    int row0, int col0, char* smem)
{
    uint32_t sb = smem_to_u32(smem);
    int tid = threadIdx.x;
    int wid = tid >> 5, lane = tid & 31;
    int warp_m = wid & 3;
    int warp_n = wid >> 2;
    const int NKITER = K / 64;

    int rr[2], cc[2], doff[2];
#pragma unroll
    for (int j = 0; j < 2; j++) {
        int u = tid + j * 512;
        int r = u >> 3, cu = u & 7;
        rr[j] = r; cc[j] = cu;
        doff[j] = ((r << 3) + (cu ^ (r & 7))) << 4;
    }

    const __half* gp[2] = {Ah, Bh};
    long  st[2] = {lda, (long)K};
    int   rb[2] = {row0, col0};

    // prologue: stages 0 and 1
#pragma unroll
    for (int s = 0; s < 2; s++) {
        uint32_t sstage = sb + s * FSTAGE;
        int k0 = s * 64;
#pragma unroll
        for (int a = 0; a < 2; a++) {
            uint32_t sdst = sstage + a * FTILE;
            const __half* g = gp[a];
#pragma unroll
            for (int j = 0; j < 2; j++)
                cp16(sdst + doff[j],
                     g + (long)(rb[a] + rr[j]) * st[a] + k0 + cc[j] * 8);
        }
        CP_COMMIT();
    }

    float acc[2][4][4];
#pragma unroll
    for (int mf = 0; mf < 2; mf++)
#pragma unroll
        for (int nf = 0; nf < 4; nf++)
#pragma unroll
            for (int e = 0; e < 4; e++) acc[mf][nf][e] = 0.f;

    int a_r = warp_m * 32 + (lane & 7) + ((lane & 8) ? 8 : 0);
    int a_usel = (lane & 16) ? 1 : 0;
    int b_rbase = warp_n * 32 + (lane & 7) + ((lane & 16) ? 8 : 0);
    int b_usel = (lane & 8) ? 1 : 0;

    int bufc = 0;
    int bufn = 2;
    for (int kc = 0; kc < NKITER; kc++) {
        if (kc + 2 < NKITER) {
            uint32_t sstage = sb + bufn * FSTAGE;
            int k0 = (kc + 2) * 64;
#pragma unroll
            for (int a = 0; a < 2; a++) {
                uint32_t sdst = sstage + a * FTILE;
                const __half* g = gp[a];
#pragma unroll
                for (int j = 0; j < 2; j++)
                    cp16(sdst + doff[j],
                         g + (long)(rb[a] + rr[j]) * st[a] + k0 + cc[j] * 8);
            }
            CP_COMMIT();
            CP_WAIT2();
        } else if (kc + 1 < NKITER) {
            CP_WAIT1();
        } else {
            CP_WAIT0();
        }
        __syncthreads();

        uint32_t s = sb + bufc * FSTAGE;
        uint32_t sA = s, sB = s + FTILE;

#pragma unroll
        for (int ks = 0; ks < 4; ks++) {
            uint32_t af[2][4];
#pragma unroll
            for (int mf = 0; mf < 2; mf++) {
                int r = a_r + mf * 16;
                int u = ks * 2 + a_usel;
                uint32_t off = (uint32_t)(((r << 3) + (u ^ (r & 7))) << 4);
                ldm4(af[mf], sA + off);
            }
            uint32_t bh[2][4];
#pragma unroll
            for (int np = 0; np < 2; np++) {
                int r = b_rbase + np * 16;
                int u = ks * 2 + b_usel;
                uint32_t off = (uint32_t)(((r << 3) + (u ^ (r & 7))) << 4);
                ldm4(bh[np], sB + off);
            }
#pragma unroll
            for (int mf = 0; mf < 2; mf++)
#pragma unroll
                for (int nf = 0; nf < 4; nf++) {
                    int np = nf >> 1;
                    int half = (nf & 1) * 2;
                    mma_fp16(acc[mf][nf], af[mf], bh[np][half], bh[np][half + 1]);
                }
        }
        __syncthreads();
        bufc = (bufc == 2) ? 0 : bufc + 1;
        bufn = (bufn == 2) ? 0 : bufn + 1;
    }

    // epilogue: convert to fp16, store half2 pairs
#pragma unroll
    for (int mf = 0; mf < 2; mf++) {
        int m = row0 + warp_m * 32 + mf * 16 + (lane >> 2);
#pragma unroll
        for (int nf = 0; nf < 4; nf++) {
            int n = col0 + warp_n * 32 + nf * 8 + (lane & 3) * 2;
            __half2 v0 = __floats2half2_rn(acc[mf][nf][0], acc[mf][nf][1]);
            __half2 v1 = __floats2half2_rn(acc[mf][nf][2], acc[mf][nf][3]);
            *(__half2*)(C + (long)m * ldc + n)       = v0;
            *(__half2*)(C + (long)(m + 8) * ldc + n) = v1;
        }
    }
}

// ---------------- bf16x3 GEMM body (Q/off + proj) --------------------------------
#define TILE_BYTES 16384
#define STAGE_BYTES (4 * TILE_BYTES)
#define SMEM_TOTAL (2 * STAGE_BYTES)  // 131072
#define SMEM_MERGED (FSMEM3 > SMEM_TOTAL ? FSMEM3 : SMEM_TOTAL)

__device__ __forceinline__ void gemm_body(
    const __nv_bfloat16* __restrict__ Ahi,
    const __nv_bfloat16* __restrict__ Alo, long lda,
    const __nv_bfloat16* __restrict__ Bhi,
    const __nv_bfloat16* __restrict__ Blo,
    const float* __restrict__ bias,
    float* __restrict__ C, int ldc, int Nstore, int K,
    int row0, int col0, char* smem)
{
    uint32_t sb = smem_to_u32(smem);
    int tid = threadIdx.x;
    int wid = tid >> 5, lane = tid & 31;
    int warp_m = wid & 3;
    int warp_n = wid >> 2;
    const int NKITER = K / 64;

    int rr[2], cc[2], doff[2];
#pragma unroll
    for (int j = 0; j < 2; j++) {
        int u = tid + j * 512;
        int r = u >> 3, cu = u & 7;
        rr[j] = r; cc[j] = cu;
        doff[j] = ((r << 3) + (cu ^ (r & 7))) << 4;
    }

    const __nv_bfloat16* gp[4] = {Ahi, Alo, Bhi, Blo};
    long  st[4] = {lda, lda, (long)K, (long)K};
    int   rb[4] = {row0, row0, col0, col0};

#pragma unroll
    for (int a = 0; a < 4; a++) {
        uint32_t sdst = sb + a * TILE_BYTES;
        const __nv_bfloat16* g = gp[a];
#pragma unroll
        for (int j = 0; j < 2; j++)
            cp16(sdst + doff[j], g + (long)(rb[a] + rr[j]) * st[a] + cc[j] * 8);
    }
    CP_COMMIT();

    float acc[2][4][4];
#pragma unroll
    for (int mf = 0; mf < 2; mf++)
#pragma unroll
        for (int nf = 0; nf < 4; nf++)
#pragma unroll
            for (int e = 0; e < 4; e++) acc[mf][nf][e] = 0.f;

    int a_r = warp_m * 32 + (lane & 7) + ((lane & 8) ? 8 : 0);
    int a_usel = (lane & 16) ? 1 : 0;
    int b_rbase = warp_n * 32 + (lane & 7) + ((lane & 16) ? 8 : 0);
    int b_usel = (lane & 8) ? 1 : 0;

    for (int kc = 0; kc < NKITER; kc++) {
        if (kc + 1 < NKITER) {
            uint32_t sstage = sb + ((kc + 1) & 1) * STAGE_BYTES;
            int k0 = (kc + 1) * 64;
#pragma unroll
            for (int a = 0; a < 4; a++) {
                uint32_t sdst = sstage + a * TILE_BYTES;
                const __nv_bfloat16* g = gp[a];
#pragma unroll
                for (int j = 0; j < 2; j++)
                    cp16(sdst + doff[j],
                         g + (long)(rb[a] + rr[j]) * st[a] + k0 + cc[j] * 8);
            }
            CP_COMMIT();
            CP_WAIT1();
        } else {
            CP_WAIT0();
        }
        __syncthreads();

        uint32_t s = sb + (kc & 1) * STAGE_BYTES;
        uint32_t sAhi = s, sAlo = s + TILE_BYTES;
        uint32_t sBhi = s + 2 * TILE_BYTES, sBlo = s + 3 * TILE_BYTES;

#pragma unroll
        for (int ks = 0; ks < 4; ks++) {
            uint32_t ah[2][4], al[2][4];
#pragma unroll
            for (int mf = 0; mf < 2; mf++) {
                int r = a_r + mf * 16;
                int u = ks * 2 + a_usel;
                uint32_t off = (uint32_t)(((r << 3) + (u ^ (r & 7))) << 4);
                ldm4(ah[mf], sAhi + off);
                ldm4(al[mf], sAlo + off);
            }
            uint32_t bh[2][4], bl[2][4];
#pragma unroll
            for (int np = 0; np < 2; np++) {
                int r = b_rbase + np * 16;
                int u = ks * 2 + b_usel;
                uint32_t off = (uint32_t)(((r << 3) + (u ^ (r & 7))) << 4);
                ldm4(bh[np], sBhi + off);
                ldm4(bl[np], sBlo + off);
            }
#pragma unroll
            for (int mf = 0; mf < 2; mf++)
#pragma unroll
                for (int nf = 0; nf < 4; nf++) {
                    int np = nf >> 1;
                    int half = (nf & 1) * 2;
                    uint32_t bh0 = bh[np][half], bh1 = bh[np][half + 1];
                    uint32_t bl0 = bl[np][half], bl1 = bl[np][half + 1];
                    mma_bf16(acc[mf][nf], ah[mf], bh0, bh1);
                    mma_bf16(acc[mf][nf], ah[mf], bl0, bl1);
                    mma_bf16(acc[mf][nf], al[mf], bh0, bh1);
                }
        }
        __syncthreads();
    }

#pragma unroll
    for (int mf = 0; mf < 2; mf++) {
        int m = row0 + warp_m * 32 + mf * 16 + (lane >> 2);
#pragma unroll
        for (int nf = 0; nf < 4; nf++) {
            int n = col0 + warp_n * 32 + nf * 8 + (lane & 3) * 2;
            if (n < Nstore) {
                float2 v0, v1;
                v0.x = acc[mf][nf][0]; v0.y = acc[mf][nf][1];
                v1.x = acc[mf][nf][2]; v1.y = acc[mf][nf][3];
                if (bias) {
                    float bx = bias[n], by = bias[n + 1];
                    v0.x += bx; v0.y += by;
                    v1.x += bx; v1.y += by;
                }
                *(float2*)(C + (long)m * ldc + n)       = v0;
                *(float2*)(C + (long)(m + 8) * ldc + n) = v1;
            }
        }
    }
}

// Merged launch: blocks 0..143 = Q/off bf16x3 gemm (long pole, scheduled first);
// blocks 144..791 = KV fp16 gemm.
#define QO_BLOCKS 144
__global__ __launch_bounds__(512, 1)
void gemm_merged_kernel()
{
    extern __shared__ char smem[];
    int bid = blockIdx.x;
    if (bid < QO_BLOCKS) {
        int bx = bid % 8, by = bid / 8;
        gemm_body(g_qbf_hi, g_qbf_lo, C_,
                  g_wqoffT_hi, g_wqoffT_lo, g_bias_qoff,
                  g_qoff, NQOFF_, 768 + NOFF_, C_, by * 128, bx * 128, smem);
    } else {
        int b2 = bid - QO_BLOCKS;
        int bx = b2 % 12, by = b2 / 12;
        gemm_fp16_body(g_xh, C_, g_wkvT,
                       g_kv, CKV_, C_, by * 128, bx * 128, smem);
    }
}

__global__ __launch_bounds__(512, 1)
void gemm_proj_kernel(const float* __restrict__ bias, float* __restrict__ C)
{
    extern __shared__ char smem[];
    gemm_body(g_ahi, g_alo, C_, g_wprojT_hi, g_wprojT_lo, bias,
              C, C_, C_, C_, blockIdx.y * 128, blockIdx.x * 128, smem);
}

// ---------------- deformable attention core --------------------------------------
__device__ __forceinline__ float4 h4_to_f4(uint2 r) {
    __half2 a = *(__half2*)&r.x;
    __half2 b = *(__half2*)&r.y;
    float2 fa = __half22float2(a);
    float2 fb = __half22float2(b);
    return make_float4(fa.x, fa.y, fb.x, fb.y);
}

__global__ __launch_bounds__(384, 2) void attn_kernel(
    const float* __restrict__ mask,
    const float* __restrict__ suppress_p)
{
    int bn = blockIdx.x;
    int b  = bn / N_;
    int n  = bn % N_;
    int h    = threadIdx.x >> 5;
    int lane = threadIdx.x & 31;
    int part = lane >> 4;            // 0 = K half, 1 = V half
    int ch   = (lane & 15) * 4;

    float suppress = *suppress_p;
    float mk  = mask[bn];
    float sw  = 1.f - suppress * mk;
    float moff = suppress * mk * 0.1f;

    float refx = (float)(n % HP_) * (2.f / 23.f) - 1.f;
    float refy = (float)(n / HP_) * (2.f / 23.f) - 1.f;

    const float* rowbase = g_qoff + bn * NQOFF_;
    float4 q4 = *(const float4*)(rowbase + h * DH_ + ch);

    const float* offrow = rowbase + 768 + h * (P_ * 2);
    float offv = (lane < P_ * 2) ? offrow[lane] : 0.f;

    int base_part = h * DH_ + part * C_ + ch;
    int pixbase = b * N_;

    float m0 = -1e30f, m1 = -1e30f, m2 = -1e30f;
    float s0 = 0.f, s1 = 0.f, s2 = 0.f;
    float4 o0 = make_float4(0.f, 0.f, 0.f, 0.f);
    float4 o1 = make_float4(0.f, 0.f, 0.f, 0.f);
    float4 o2 = make_float4(0.f, 0.f, 0.f, 0.f);

#pragma unroll
    for (int p = 0; p < P_; p++) {
        float ox = __shfl_sync(0xffffffffu, offv, 2 * p)     - moff;
        float oy = __shfl_sync(0xffffffffu, offv, 2 * p + 1) - moff;
        float xs = (refx + ox + 1.f) * 11.5f;
        float ys = (refy + oy + 1.f) * 11.5f;
        float x0f = floorf(xs), y0f = floorf(ys);
        int   x0 = (int)x0f,  y0 = (int)y0f;
        float wx1 = xs - x0f, wy1 = ys - y0f;
        float wx0 = 1.f - wx1, wy0 = 1.f - wy1;

        float4 a0 = make_float4(0.f, 0.f, 0.f, 0.f);
        float4 a1 = make_float4(0.f, 0.f, 0.f, 0.f);
        float4 a2 = make_float4(0.f, 0.f, 0.f, 0.f);
#pragma unroll
        for (int c = 0; c < 4; c++) {
            int dx = c & 1, dy = c >> 1;
            int ix = x0 + dx, iy = y0 + dy;
            float valid = (ix >= 0 && ix < HP_ && iy >= 0 && iy < HP_) ? 1.f : 0.f;
            float w = (dx ? wx1 : wx0) * (dy ? wy1 : wy0) * valid;
            int ixc = min(max(ix, 0), HP_ - 1);
            int iyc = min(max(iy, 0), HP_ - 1);
            int idx = (pixbase + iyc * HP_ + ixc) * (T_ * CKV_) + base_part;
            const __half* kvp = g_kv + idx;
            float4 kv0 = h4_to_f4(*(const uint2*)(kvp));
            float4 kv1 = h4_to_f4(*(const uint2*)(kvp + CKV_));
            float4 kv2 = h4_to_f4(*(const uint2*)(kvp + 2 * CKV_));
            a0.x = fmaf(w, kv0.x, a0.x); a0.y = fmaf(w, kv0.y, a0.y);
            a0.z = fmaf(w, kv0.z, a0.z); a0.w = fmaf(w, kv0.w, a0.w);
            a1.x = fmaf(w, kv1.x, a1.x); a1.y = fmaf(w, kv1.y, a1.y);
            a1.z = fmaf(w, kv1.z, a1.z); a1.w = fmaf(w, kv1.w, a1.w);
            a2.x = fmaf(w, kv2.x, a2.x); a2.y = fmaf(w, kv2.y, a2.y);
            a2.z = fmaf(w, kv2.z, a2.z); a2.w = fmaf(w, kv2.w, a2.w);
        }
        float d0 = q4.x * a0.x + q4.y * a0.y + q4.z * a0.z + q4.w * a0.w;
        float d1 = q4.x * a1.x + q4.y * a1.y + q4.z * a1.z + q4.w * a1.w;
        float d2 = q4.x * a2.x + q4.y * a2.y + q4.z * a2.z + q4.w * a2.w;
#pragma unroll
        for (int s = 8; s > 0; s >>= 1) {
            d0 += __shfl_xor_sync(0xffffffffu, d0, s);
            d1 += __shfl_xor_sync(0xffffffffu, d1, s);
            d2 += __shfl_xor_sync(0xffffffffu, d2, s);
        }
        float l0 = __shfl_sync(0xffffffffu, d0, 0) * SCALE_ * sw;
        float l1 = __shfl_sync(0xffffffffu, d1, 0) * SCALE_ * sw;
        float l2 = __shfl_sync(0xffffffffu, d2, 0) * SCALE_ * sw;

        {
            float mn = fmaxf(m0, l0);
            float c1 = __expf(m0 - mn), c2 = __expf(l0 - mn);
            s0 = s0 * c1 + c2;
            o0.x = o0.x * c1 + c2 * a0.x; o0.y = o0.y * c1 + c2 * a0.y;
            o0.z = o0.z * c1 + c2 * a0.z; o0.w = o0.w * c1 + c2 * a0.w;
            m0 = mn;
        }
        {
            float mn = fmaxf(m1, l1);
            float c1 = __expf(m1 - mn), c2 = __expf(l1 - mn);
            s1 = s1 * c1 + c2;
            o1.x = o1.x * c1 + c2 * a1.x; o1.y = o1.y * c1 + c2 * a1.y;
            o1.z = o1.z * c1 + c2 * a1.z; o1.w = o1.w * c1 + c2 * a1.w;
            m1 = mn;
        }
        {
            float mn = fmaxf(m2, l2);
            float c1 = __expf(m2 - mn), c2 = __expf(l2 - mn);
            s2 = s2 * c1 + c2;
            o2.x = o2.x * c1 + c2 * a2.x; o2.y = o2.y * c1 + c2 * a2.y;
            o2.z = o2.z * c1 + c2 * a2.z; o2.w = o2.w * c1 + c2 * a2.w;
            m2 = mn;
        }
    }

    if (part == 1) {
        const float third = 1.0f / 3.0f;
        float i0 = third / s0, i1 = third / s1, i2 = third / s2;
        float rx = o0.x * i0 + o1.x * i1 + o2.x * i2;
        float ry = o0.y * i0 + o1.y * i1 + o2.y * i2;
        float rz = o0.z * i0 + o1.z * i1 + o2.z * i2;
        float rw = o0.w * i0 + o1.w * i1 + o2.w * i2;

        __nv_bfloat16 hx, lx, hy, ly, hz, lz, hw, lw;
        split_bf(rx, hx, lx); split_bf(ry, hy, ly);
        split_bf(rz, hz, lz); split_bf(rw, hw, lw);
        int oidx = bn * C_ + h * DH_ + ch;
        __nv_bfloat162 hi01(hx, hy), hi23(hz, hw);
        __nv_bfloat162 lo01(lx, ly), lo23(lz, lw);
        uint2 hpack, lpack;
        hpack.x = *(uint32_t*)&hi01; hpack.y = *(uint32_t*)&hi23;
        lpack.x = *(uint32_t*)&lo01; lpack.y = *(uint32_t*)&lo23;
        *(uint2*)(g_ahi + oidx) = hpack;
        *(uint2*)(g_alo + oidx) = lpack;
    }
}

// ---------------- launch ----------------------------------------------------------
extern "C" void kernel_launch(void* const* d_in, const int* in_sizes, int n_in,
                              void* d_out, int out_size)
{
    const float* x     = (const float*)d_in[0];
    const float* mask  = (const float*)d_in[1];
    const float* Wq    = (const float*)d_in[2];
    const float* Wk    = (const float*)d_in[3];
    const float* Wv    = (const float*)d_in[4];
    const float* Woff  = (const float*)d_in[5];
    const float* boff  = (const float*)d_in[6];
    const float* Wproj = (const float*)d_in[7];
    const float* bproj = (const float*)d_in[8];
    const float* suppr = (const float*)d_in[9];
    float* out = (float*)d_out;

    cudaFuncSetAttribute(gemm_merged_kernel,
                         cudaFuncAttributeMaxDynamicSharedMemorySize, SMEM_MERGED);
    cudaFuncSetAttribute(gemm_proj_kernel,
                         cudaFuncAttributeMaxDynamicSharedMemorySize, SMEM_TOTAL);

    conv_x_kernel<<<(MKV_ * C_ / 4 + 255) / 256, 256>>>(x);
    split_q_kernel<<<(BN_ * C_ / 4 + 255) / 256, 256>>>(x);
    tpose_split_all_kernel<<<dim3(C_ / 32, C_ / 32, 5), dim3(32, 8)>>>(
        Wq, Wk, Wv, Wproj, Woff, boff);

    gemm_merged_kernel<<<QO_BLOCKS + 648, 512, SMEM_MERGED>>>();

    attn_kernel<<<BN_, 384>>>(mask, suppr);

    gemm_proj_kernel<<<dim3(C_ / 128, BN_ / 128), 512, SMEM_TOTAL>>>(bproj, out);
}

// round 13
// speedup vs baseline: 4.9769x; 1.0981x over previous
#include <cuda_runtime.h>
#include <cuda_bf16.h>
#include <cuda_fp16.h>
#include <cstdint>
#include <math.h>

#define B_  4
#define N_  576
#define T_  3
#define C_  768
#define H_  12
#define P_  9
#define DH_ 64
#define HP_ 24
#define SCALE_ 0.125f
#define BN_ (B_ * N_)
#define CKV_ (2 * C_)       // 1536
#define MKV_ (BN_ * T_)     // 6912
#define NOFF_ (H_ * P_ * 2) // 216
#define NQOFF_ 1024         // 768 (q) + 256 (off padded)

// ---------------- scratch (device globals) -----------------------------------
__device__ __half g_xh[MKV_ * C_];        // x in fp16
__device__ __half g_wkvT[CKV_ * C_];      // [n][k]; n<768: Wk, else Wv (fp16)
__device__ __nv_bfloat16 g_qbf_hi[BN_ * C_];
__device__ __nv_bfloat16 g_qbf_lo[BN_ * C_];
__device__ __nv_bfloat16 g_wqoffT_hi[NQOFF_ * C_];
__device__ __nv_bfloat16 g_wqoffT_lo[NQOFF_ * C_];
__device__ __nv_bfloat16 g_wprojT_hi[C_ * C_];
__device__ __nv_bfloat16 g_wprojT_lo[C_ * C_];
__device__ __nv_bfloat16 g_ahi[BN_ * C_];
__device__ __nv_bfloat16 g_alo[BN_ * C_];
__device__ float g_bias_qoff[NQOFF_];

__device__ __half g_kv[MKV_ * CKV_];
__device__ float g_qoff[BN_ * NQOFF_];

// ---------------- PTX helpers ---------------------------------------------------
__device__ __forceinline__ uint32_t smem_to_u32(const void* p) {
    uint32_t a;
    asm("{ .reg .u64 t; cvta.to.shared.u64 t, %1; cvt.u32.u64 %0, t; }"
        : "=r"(a) : "l"(p));
    return a;
}
__device__ __forceinline__ void cp16(uint32_t dst, const void* src) {
    asm volatile("cp.async.cg.shared.global [%0], [%1], 16;"
                 :: "r"(dst), "l"(src));
}
#define CP_COMMIT() asm volatile("cp.async.commit_group;" ::: "memory")
#define CP_WAIT0()  asm volatile("cp.async.wait_group 0;" ::: "memory")
#define CP_WAIT1()  asm volatile("cp.async.wait_group 1;" ::: "memory")
#define CP_WAIT2()  asm volatile("cp.async.wait_group 2;" ::: "memory")

__device__ __forceinline__ void ldm4(uint32_t* r, uint32_t addr) {
    asm volatile("ldmatrix.sync.aligned.m8n8.x4.shared.b16 {%0,%1,%2,%3}, [%4];"
                 : "=r"(r[0]), "=r"(r[1]), "=r"(r[2]), "=r"(r[3]) : "r"(addr));
}
__device__ __forceinline__ void mma_bf16(float* c, const uint32_t* a,
                                         uint32_t b0, uint32_t b1) {
    asm volatile(
        "mma.sync.aligned.m16n8k16.row.col.f32.bf16.bf16.f32 "
        "{%0,%1,%2,%3}, {%4,%5,%6,%7}, {%8,%9}, {%0,%1,%2,%3};"
        : "+f"(c[0]), "+f"(c[1]), "+f"(c[2]), "+f"(c[3])
        : "r"(a[0]), "r"(a[1]), "r"(a[2]), "r"(a[3]), "r"(b0), "r"(b1));
}
__device__ __forceinline__ void mma_fp16(float* c, const uint32_t* a,
                                         uint32_t b0, uint32_t b1) {
    asm volatile(
        "mma.sync.aligned.m16n8k16.row.col.f32.f16.f16.f32 "
        "{%0,%1,%2,%3}, {%4,%5,%6,%7}, {%8,%9}, {%0,%1,%2,%3};"
        : "+f"(c[0]), "+f"(c[1]), "+f"(c[2]), "+f"(c[3])
        : "r"(a[0]), "r"(a[1]), "r"(a[2]), "r"(a[3]), "r"(b0), "r"(b1));
}

// ---------------- prep kernels ---------------------------------------------------
__device__ __forceinline__ void split_bf(float v, __nv_bfloat16& hi, __nv_bfloat16& lo) {
    hi = __float2bfloat16(v);
    lo = __float2bfloat16(v - __bfloat162float(hi));
}

// fp16 convert of all x + bf16 split of the t=1 (query) rows, fused.
__global__ void conv_x_kernel(const float* __restrict__ x) {
    int idx = blockIdx.x * blockDim.x + threadIdx.x;  // over MKV_*C_/4
    if (idx >= MKV_ * C_ / 4) return;
    float4 v = ((const float4*)x)[idx];
    ((__half2*)g_xh)[idx * 2]     = __floats2half2_rn(v.x, v.y);
    ((__half2*)g_xh)[idx * 2 + 1] = __floats2half2_rn(v.z, v.w);

    int token = idx / (C_ / 4);
    if (token % T_ == 1) {
        int bn = token / T_;
        int c4 = idx % (C_ / 4);
        int qidx = bn * (C_ / 4) + c4;
        __nv_bfloat16 h0, l0, h1, l1, h2, l2, h3, l3;
        split_bf(v.x, h0, l0); split_bf(v.y, h1, l1);
        split_bf(v.z, h2, l2); split_bf(v.w, h3, l3);
        ((__nv_bfloat162*)g_qbf_hi)[qidx * 2]     = __nv_bfloat162(h0, h1);
        ((__nv_bfloat162*)g_qbf_hi)[qidx * 2 + 1] = __nv_bfloat162(h2, h3);
        ((__nv_bfloat162*)g_qbf_lo)[qidx * 2]     = __nv_bfloat162(l0, l1);
        ((__nv_bfloat162*)g_qbf_lo)[qidx * 2 + 1] = __nv_bfloat162(l2, l3);
    }
}

// Fused transpose of all weights; blockIdx.z selects matrix.
__global__ void tpose_split_all_kernel(
    const float* __restrict__ Wq, const float* __restrict__ Wk,
    const float* __restrict__ Wv, const float* __restrict__ Wproj,
    const float* __restrict__ Woff, const float* __restrict__ boff)
{
    if (blockIdx.z == 0 && blockIdx.x == 0 && blockIdx.y == 0) {
        int t = threadIdx.y * 32 + threadIdx.x;
        for (int i = t; i < NQOFF_; i += 256)
            g_bias_qoff[i] = (i >= 768 && i < 768 + NOFF_) ? boff[i - 768] : 0.f;
    }

    const float* src;
    __half* dh = nullptr;
    __nv_bfloat16 *dhi = nullptr, *dlo = nullptr;
    int N, dstRows;
    switch (blockIdx.z) {
        case 0: src = Wq;    dhi = g_wqoffT_hi; dlo = g_wqoffT_lo; N = C_; dstRows = C_; break;
        case 1: src = Wk;    dh = g_wkvT;                 N = C_;   dstRows = C_;  break;
        case 2: src = Wv;    dh = g_wkvT + (long)C_ * C_; N = C_;   dstRows = C_;  break;
        case 3: src = Wproj; dhi = g_wprojT_hi; dlo = g_wprojT_lo; N = C_; dstRows = C_; break;
        default: src = Woff; dhi = g_wqoffT_hi + (long)768 * C_;
                             dlo = g_wqoffT_lo + (long)768 * C_;   N = NOFF_; dstRows = 256; break;
    }
    int n0 = blockIdx.x * 32, k0 = blockIdx.y * 32;
    if (n0 >= dstRows) return;

    __shared__ float tile[32][33];
    int tx = threadIdx.x, ty = threadIdx.y;
#pragma unroll
    for (int j = 0; j < 4; j++) {
        int k = k0 + ty + j * 8, n = n0 + tx;
        tile[ty + j * 8][tx] = (n < N) ? src[(long)k * N + n] : 0.f;
    }
    __syncthreads();
#pragma unroll
    for (int j = 0; j < 4; j++) {
        int n = n0 + ty + j * 8, k = k0 + tx;
        if (n < dstRows) {
            float v = tile[tx][ty + j * 8];
            if (dh) {
                dh[(long)n * C_ + k] = __float2half_rn(v);
            } else {
                __nv_bfloat16 hi, lo;
                split_bf(v, hi, lo);
                dhi[(long)n * C_ + k] = hi;
                dlo[(long)n * C_ + k] = lo;
            }
        }
    }
}

// ---------------- merged GEMM kernel: 256 threads, 2 CTAs/SM ---------------------
// KV fp16: tile 128x128, warp tile 32x64 (4m x 2n warps), 3-stage (96 KB).
// QO bf16x3: same tile, single-buffered (64 KB); hidden by co-resident KV CTA.
#define FTILE 16384
#define FSTAGE (2 * FTILE)    // A, B fp16 tiles
#define MSMEM  (3 * FSTAGE)   // 98304

__device__ __forceinline__ void gemm_fp16_body256(
    const __half* __restrict__ Ah, long lda,
    const __half* __restrict__ Bh,
    __half* __restrict__ C, int ldc, int K,
    int row0, int col0, char* smem)
{
    uint32_t sb = smem_to_u32(smem);
    int tid = threadIdx.x;
    int wid = tid >> 5, lane = tid & 31;
    int warp_m = wid & 3;
    int warp_n = wid >> 2;        // 0..1
    const int NKITER = K / 64;

    int rr[4], cc[4], doff[4];
#pragma unroll
    for (int j = 0; j < 4; j++) {
        int u = tid + j * 256;
        int r = u >> 3, cu = u & 7;
        rr[j] = r; cc[j] = cu;
        doff[j] = ((r << 3) + (cu ^ (r & 7))) << 4;
    }

    const __half* gp[2] = {Ah, Bh};
    long  st[2] = {lda, (long)K};
    int   rb[2] = {row0, col0};

#pragma unroll
    for (int s = 0; s < 2; s++) {
        uint32_t sstage = sb + s * FSTAGE;
        int k0 = s * 64;
#pragma unroll
        for (int a = 0; a < 2; a++) {
            uint32_t sdst = sstage + a * FTILE;
            const __half* g = gp[a];
#pragma unroll
            for (int j = 0; j < 4; j++)
                cp16(sdst + doff[j],
                     g + (long)(rb[a] + rr[j]) * st[a] + k0 + cc[j] * 8);
        }
        CP_COMMIT();
    }

    float acc[2][8][4];
#pragma unroll
    for (int mf = 0; mf < 2; mf++)
#pragma unroll
        for (int nf = 0; nf < 8; nf++)
#pragma unroll
            for (int e = 0; e < 4; e++) acc[mf][nf][e] = 0.f;

    int a_r = warp_m * 32 + (lane & 7) + ((lane & 8) ? 8 : 0);
    int a_usel = (lane & 16) ? 1 : 0;
    int b_rbase = warp_n * 64 + (lane & 7) + ((lane & 16) ? 8 : 0);
    int b_usel = (lane & 8) ? 1 : 0;

    int bufc = 0, bufn = 2;
    for (int kc = 0; kc < NKITER; kc++) {
        if (kc + 2 < NKITER) {
            uint32_t sstage = sb + bufn * FSTAGE;
            int k0 = (kc + 2) * 64;
#pragma unroll
            for (int a = 0; a < 2; a++) {
                uint32_t sdst = sstage + a * FTILE;
                const __half* g = gp[a];
#pragma unroll
                for (int j = 0; j < 4; j++)
                    cp16(sdst + doff[j],
                         g + (long)(rb[a] + rr[j]) * st[a] + k0 + cc[j] * 8);
            }
            CP_COMMIT();
            CP_WAIT2();
        } else if (kc + 1 < NKITER) {
            CP_WAIT1();
        } else {
            CP_WAIT0();
        }
        __syncthreads();

        uint32_t s = sb + bufc * FSTAGE;
        uint32_t sA = s, sB = s + FTILE;

#pragma unroll
        for (int ks = 0; ks < 4; ks++) {
            uint32_t af[2][4];
#pragma unroll
            for (int mf = 0; mf < 2; mf++) {
                int r = a_r + mf * 16;
                int u = ks * 2 + a_usel;
                uint32_t off = (uint32_t)(((r << 3) + (u ^ (r & 7))) << 4);
                ldm4(af[mf], sA + off);
            }
#pragma unroll
            for (int np = 0; np < 4; np++) {
                uint32_t bf[4];
                int r = b_rbase + np * 16;
                int u = ks * 2 + b_usel;
                uint32_t off = (uint32_t)(((r << 3) + (u ^ (r & 7))) << 4);
                ldm4(bf, sB + off);
#pragma unroll
                for (int mf = 0; mf < 2; mf++)
#pragma unroll
                    for (int jj = 0; jj < 2; jj++)
                        mma_fp16(acc[mf][np * 2 + jj], af[mf],
                                 bf[jj * 2], bf[jj * 2 + 1]);
            }
        }
        __syncthreads();
        bufc = (bufc == 2) ? 0 : bufc + 1;
        bufn = (bufn == 2) ? 0 : bufn + 1;
    }

#pragma unroll
    for (int mf = 0; mf < 2; mf++) {
        int m = row0 + warp_m * 32 + mf * 16 + (lane >> 2);
#pragma unroll
        for (int nf = 0; nf < 8; nf++) {
            int n = col0 + warp_n * 64 + nf * 8 + (lane & 3) * 2;
            __half2 v0 = __floats2half2_rn(acc[mf][nf][0], acc[mf][nf][1]);
            __half2 v1 = __floats2half2_rn(acc[mf][nf][2], acc[mf][nf][3]);
            *(__half2*)(C + (long)m * ldc + n)       = v0;
            *(__half2*)(C + (long)(m + 8) * ldc + n) = v1;
        }
    }
}

#define QTILE 16384
__device__ __forceinline__ void gemm_bf16x3_body256(
    const __nv_bfloat16* __restrict__ Ahi,
    const __nv_bfloat16* __restrict__ Alo, long lda,
    const __nv_bfloat16* __restrict__ Bhi,
    const __nv_bfloat16* __restrict__ Blo,
    const float* __restrict__ bias,
    float* __restrict__ C, int ldc, int Nstore, int K,
    int row0, int col0, char* smem)
{
    uint32_t sb = smem_to_u32(smem);
    int tid = threadIdx.x;
    int wid = tid >> 5, lane = tid & 31;
    int warp_m = wid & 3;
    int warp_n = wid >> 2;
    const int NKITER = K / 64;

    int rr[4], cc[4], doff[4];
#pragma unroll
    for (int j = 0; j < 4; j++) {
        int u = tid + j * 256;
        int r = u >> 3, cu = u & 7;
        rr[j] = r; cc[j] = cu;
        doff[j] = ((r << 3) + (cu ^ (r & 7))) << 4;
    }

    const __nv_bfloat16* gp[4] = {Ahi, Alo, Bhi, Blo};
    long  st[4] = {lda, lda, (long)K, (long)K};
    int   rb[4] = {row0, row0, col0, col0};

    float acc[2][8][4];
#pragma unroll
    for (int mf = 0; mf < 2; mf++)
#pragma unroll
        for (int nf = 0; nf < 8; nf++)
#pragma unroll
            for (int e = 0; e < 4; e++) acc[mf][nf][e] = 0.f;

    int a_r = warp_m * 32 + (lane & 7) + ((lane & 8) ? 8 : 0);
    int a_usel = (lane & 16) ? 1 : 0;
    int b_rbase = warp_n * 64 + (lane & 7) + ((lane & 16) ? 8 : 0);
    int b_usel = (lane & 8) ? 1 : 0;

    for (int kc = 0; kc < NKITER; kc++) {
        int k0 = kc * 64;
#pragma unroll
        for (int a = 0; a < 4; a++) {
            uint32_t sdst = sb + a * QTILE;
            const __nv_bfloat16* g = gp[a];
#pragma unroll
            for (int j = 0; j < 4; j++)
                cp16(sdst + doff[j],
                     g + (long)(rb[a] + rr[j]) * st[a] + k0 + cc[j] * 8);
        }
        CP_COMMIT();
        CP_WAIT0();
        __syncthreads();

        uint32_t sAhi = sb, sAlo = sb + QTILE;
        uint32_t sBhi = sb + 2 * QTILE, sBlo = sb + 3 * QTILE;

#pragma unroll
        for (int ks = 0; ks < 4; ks++) {
            uint32_t ah[2][4], al[2][4];
#pragma unroll
            for (int mf = 0; mf < 2; mf++) {
                int r = a_r + mf * 16;
                int u = ks * 2 + a_usel;
                uint32_t off = (uint32_t)(((r << 3) + (u ^ (r & 7))) << 4);
                ldm4(ah[mf], sAhi + off);
                ldm4(al[mf], sAlo + off);
            }
#pragma unroll
            for (int np = 0; np < 4; np++) {
                uint32_t bh[4], bl[4];
                int r = b_rbase + np * 16;
                int u = ks * 2 + b_usel;
                uint32_t off = (uint32_t)(((r << 3) + (u ^ (r & 7))) << 4);
                ldm4(bh, sBhi + off);
                ldm4(bl, sBlo + off);
#pragma unroll
                for (int mf = 0; mf < 2; mf++)
#pragma unroll
                    for (int jj = 0; jj < 2; jj++) {
                        float* a4 = acc[mf][np * 2 + jj];
                        mma_bf16(a4, ah[mf], bh[jj * 2], bh[jj * 2 + 1]);
                        mma_bf16(a4, ah[mf], bl[jj * 2], bl[jj * 2 + 1]);
                        mma_bf16(a4, al[mf], bh[jj * 2], bh[jj * 2 + 1]);
                    }
            }
        }
        __syncthreads();
    }

#pragma unroll
    for (int mf = 0; mf < 2; mf++) {
        int m = row0 + warp_m * 32 + mf * 16 + (lane >> 2);
#pragma unroll
        for (int nf = 0; nf < 8; nf++) {
            int n = col0 + warp_n * 64 + nf * 8 + (lane & 3) * 2;
            if (n < Nstore) {
                float2 v0, v1;
                v0.x = acc[mf][nf][0]; v0.y = acc[mf][nf][1];
                v1.x = acc[mf][nf][2]; v1.y = acc[mf][nf][3];
                if (bias) {
                    float bx = bias[n], by = bias[n + 1];
                    v0.x += bx; v0.y += by;
                    v1.x += bx; v1.y += by;
                }
                *(float2*)(C + (long)m * ldc + n)       = v0;
                *(float2*)(C + (long)(m + 8) * ldc + n) = v1;
            }
        }
    }
}

// blocks 0..143 = Q/off bf16x3 (long pole first); 144..791 = KV fp16.
#define QO_BLOCKS 144
__global__ __launch_bounds__(256, 2)
void gemm_merged_kernel()
{
    extern __shared__ char smem[];
    int bid = blockIdx.x;
    if (bid < QO_BLOCKS) {
        int bx = bid % 8, by = bid / 8;
        gemm_bf16x3_body256(g_qbf_hi, g_qbf_lo, C_,
                            g_wqoffT_hi, g_wqoffT_lo, g_bias_qoff,
                            g_qoff, NQOFF_, 768 + NOFF_, C_,
                            by * 128, bx * 128, smem);
    } else {
        int b2 = bid - QO_BLOCKS;
        int bx = b2 % 12, by = b2 / 12;
        gemm_fp16_body256(g_xh, C_, g_wkvT,
                          g_kv, CKV_, C_, by * 128, bx * 128, smem);
    }
}

__global__ __launch_bounds__(256, 2)
void gemm_proj_kernel(const float* __restrict__ bias, float* __restrict__ C)
{
    extern __shared__ char smem[];
    gemm_bf16x3_body256(g_ahi, g_alo, C_, g_wprojT_hi, g_wprojT_lo, bias,
                        C, C_, C_, C_, blockIdx.y * 128, blockIdx.x * 128, smem);
}

// ---------------- deformable attention core --------------------------------------
__device__ __forceinline__ float4 h4_to_f4(uint2 r) {
    __half2 a = *(__half2*)&r.x;
    __half2 b = *(__half2*)&r.y;
    float2 fa = __half22float2(a);
    float2 fb = __half22float2(b);
    return make_float4(fa.x, fa.y, fb.x, fb.y);
}

__global__ __launch_bounds__(384, 2) void attn_kernel(
    const float* __restrict__ mask,
    const float* __restrict__ suppress_p)
{
    int bn = blockIdx.x;
    int b  = bn / N_;
    int n  = bn % N_;
    int h    = threadIdx.x >> 5;
    int lane = threadIdx.x & 31;
    int part = lane >> 4;
    int ch   = (lane & 15) * 4;

    float suppress = *suppress_p;
    float mk  = mask[bn];
    float sw  = 1.f - suppress * mk;
    float moff = suppress * mk * 0.1f;

    float refx = (float)(n % HP_) * (2.f / 23.f) - 1.f;
    float refy = (float)(n / HP_) * (2.f / 23.f) - 1.f;

    const float* rowbase = g_qoff + bn * NQOFF_;
    float4 q4 = *(const float4*)(rowbase + h * DH_ + ch);

    const float* offrow = rowbase + 768 + h * (P_ * 2);
    float offv = (lane < P_ * 2) ? offrow[lane] : 0.f;

    int base_part = h * DH_ + part * C_ + ch;
    int pixbase = b * N_;

    float m0 = -1e30f, m1 = -1e30f, m2 = -1e30f;
    float s0 = 0.f, s1 = 0.f, s2 = 0.f;
    float4 o0 = make_float4(0.f, 0.f, 0.f, 0.f);
    float4 o1 = make_float4(0.f, 0.f, 0.f, 0.f);
    float4 o2 = make_float4(0.f, 0.f, 0.f, 0.f);

#pragma unroll
    for (int p = 0; p < P_; p++) {
        float ox = __shfl_sync(0xffffffffu, offv, 2 * p)     - moff;
        float oy = __shfl_sync(0xffffffffu, offv, 2 * p + 1) - moff;
        float xs = (refx + ox + 1.f) * 11.5f;
        float ys = (refy + oy + 1.f) * 11.5f;
        float x0f = floorf(xs), y0f = floorf(ys);
        int   x0 = (int)x0f,  y0 = (int)y0f;
        float wx1 = xs - x0f, wy1 = ys - y0f;
        float wx0 = 1.f - wx1, wy0 = 1.f - wy1;

        float4 a0 = make_float4(0.f, 0.f, 0.f, 0.f);
        float4 a1 = make_float4(0.f, 0.f, 0.f, 0.f);
        float4 a2 = make_float4(0.f, 0.f, 0.f, 0.f);
#pragma unroll
        for (int c = 0; c < 4; c++) {
            int dx = c & 1, dy = c >> 1;
            int ix = x0 + dx, iy = y0 + dy;
            float valid = (ix >= 0 && ix < HP_ && iy >= 0 && iy < HP_) ? 1.f : 0.f;
            float w = (dx ? wx1 : wx0) * (dy ? wy1 : wy0) * valid;
            int ixc = min(max(ix, 0), HP_ - 1);
            int iyc = min(max(iy, 0), HP_ - 1);
            int idx = (pixbase + iyc * HP_ + ixc) * (T_ * CKV_) + base_part;
            const __half* kvp = g_kv + idx;
            float4 kv0 = h4_to_f4(*(const uint2*)(kvp));
            float4 kv1 = h4_to_f4(*(const uint2*)(kvp + CKV_));
            float4 kv2 = h4_to_f4(*(const uint2*)(kvp + 2 * CKV_));
            a0.x = fmaf(w, kv0.x, a0.x); a0.y = fmaf(w, kv0.y, a0.y);
            a0.z = fmaf(w, kv0.z, a0.z); a0.w = fmaf(w, kv0.w, a0.w);
            a1.x = fmaf(w, kv1.x, a1.x); a1.y = fmaf(w, kv1.y, a1.y);
            a1.z = fmaf(w, kv1.z, a1.z); a1.w = fmaf(w, kv1.w, a1.w);
            a2.x = fmaf(w, kv2.x, a2.x); a2.y = fmaf(w, kv2.y, a2.y);
            a2.z = fmaf(w, kv2.z, a2.z); a2.w = fmaf(w, kv2.w, a2.w);
        }
        float d0 = q4.x * a0.x + q4.y * a0.y + q4.z * a0.z + q4.w * a0.w;
        float d1 = q4.x * a1.x + q4.y * a1.y + q4.z * a1.z + q4.w * a1.w;
        float d2 = q4.x * a2.x + q4.y * a2.y + q4.z * a2.z + q4.w * a2.w;
#pragma unroll
        for (int s = 8; s > 0; s >>= 1) {
            d0 += __shfl_xor_sync(0xffffffffu, d0, s);
            d1 += __shfl_xor_sync(0xffffffffu, d1, s);
            d2 += __shfl_xor_sync(0xffffffffu, d2, s);
        }
        float l0 = __shfl_sync(0xffffffffu, d0, 0) * SCALE_ * sw;
        float l1 = __shfl_sync(0xffffffffu, d1, 0) * SCALE_ * sw;
        float l2 = __shfl_sync(0xffffffffu, d2, 0) * SCALE_ * sw;

        {
            float mn = fmaxf(m0, l0);
            float c1 = __expf(m0 - mn), c2 = __expf(l0 - mn);
            s0 = s0 * c1 + c2;
            o0.x = o0.x * c1 + c2 * a0.x; o0.y = o0.y * c1 + c2 * a0.y;
            o0.z = o0.z * c1 + c2 * a0.z; o0.w = o0.w * c1 + c2 * a0.w;
            m0 = mn;
        }
        {
            float mn = fmaxf(m1, l1);
            float c1 = __expf(m1 - mn), c2 = __expf(l1 - mn);
            s1 = s1 * c1 + c2;
            o1.x = o1.x * c1 + c2 * a1.x; o1.y = o1.y * c1 + c2 * a1.y;
            o1.z = o1.z * c1 + c2 * a1.z; o1.w = o1.w * c1 + c2 * a1.w;
            m1 = mn;
        }
        {
            float mn = fmaxf(m2, l2);
            float c1 = __expf(m2 - mn), c2 = __expf(l2 - mn);
            s2 = s2 * c1 + c2;
            o2.x = o2.x * c1 + c2 * a2.x; o2.y = o2.y * c1 + c2 * a2.y;
            o2.z = o2.z * c1 + c2 * a2.z; o2.w = o2.w * c1 + c2 * a2.w;
            m2 = mn;
        }
    }

    if (part == 1) {
        const float third = 1.0f / 3.0f;
        float i0 = third / s0, i1 = third / s1, i2 = third / s2;
        float rx = o0.x * i0 + o1.x * i1 + o2.x * i2;
        float ry = o0.y * i0 + o1.y * i1 + o2.y * i2;
        float rz = o0.z * i0 + o1.z * i1 + o2.z * i2;
        float rw = o0.w * i0 + o1.w * i1 + o2.w * i2;

        __nv_bfloat16 hx, lx, hy, ly, hz, lz, hw, lw;
        split_bf(rx, hx, lx); split_bf(ry, hy, ly);
        split_bf(rz, hz, lz); split_bf(rw, hw, lw);
        int oidx = bn * C_ + h * DH_ + ch;
        __nv_bfloat162 hi01(hx, hy), hi23(hz, hw);
        __nv_bfloat162 lo01(lx, ly), lo23(lz, lw);
        uint2 hpack, lpack;
        hpack.x = *(uint32_t*)&hi01; hpack.y = *(uint32_t*)&hi23;
        lpack.x = *(uint32_t*)&lo01; lpack.y = *(uint32_t*)&lo23;
        *(uint2*)(g_ahi + oidx) = hpack;
        *(uint2*)(g_alo + oidx) = lpack;
    }
}

// ---------------- launch ----------------------------------------------------------
extern "C" void kernel_launch(void* const* d_in, const int* in_sizes, int n_in,
                              void* d_out, int out_size)
{
    const float* x     = (const float*)d_in[0];
    const float* mask  = (const float*)d_in[1];
    const float* Wq    = (const float*)d_in[2];
    const float* Wk    = (const float*)d_in[3];
    const float* Wv    = (const float*)d_in[4];
    const float* Woff  = (const float*)d_in[5];
    const float* boff  = (const float*)d_in[6];
    const float* Wproj = (const float*)d_in[7];
    const float* bproj = (const float*)d_in[8];
    const float* suppr = (const float*)d_in[9];
    float* out = (float*)d_out;

    cudaFuncSetAttribute(gemm_merged_kernel,
                         cudaFuncAttributeMaxDynamicSharedMemorySize, MSMEM);
    cudaFuncSetAttribute(gemm_proj_kernel,
                         cudaFuncAttributeMaxDynamicSharedMemorySize, 4 * QTILE);

    conv_x_kernel<<<(MKV_ * C_ / 4 + 255) / 256, 256>>>(x);
    tpose_split_all_kernel<<<dim3(C_ / 32, C_ / 32, 5), dim3(32, 8)>>>(
        Wq, Wk, Wv, Wproj, Woff, boff);

    gemm_merged_kernel<<<QO_BLOCKS + 648, 256, MSMEM>>>();

    attn_kernel<<<BN_, 384>>>(mask, suppr);

    gemm_proj_kernel<<<dim3(C_ / 128, BN_ / 128), 256, 4 * QTILE>>>(bproj, out);
}